// round 1
// baseline (speedup 1.0000x reference)
#include <cuda_runtime.h>
#include <math.h>

#define DIM      1536
#define NHEADS   12
#define HDIM     128
#define S_LEN    1560
#define KV_LEN   9360
#define FT       22
#define FSZ      21
#define WW       52
#define ALPHA_F  0.999f
#define BETA_F   0.001f
#define EPS_F    1e-6f
#define Q_FRAME  5
#define SCALE    0.08838834764831843f   /* 1/sqrt(128) */

// ---------------- scratch (device globals; no allocations allowed) ----------
__device__ float d_qbuf[S_LEN * DIM];
__device__ float d_kbuf[S_LEN * DIM];
__device__ float d_vbuf[S_LEN * DIM];
__device__ float d_kc[KV_LEN * DIM];
__device__ float d_vc[KV_LEN * DIM];
__device__ float d_obuf[S_LEN * DIM];

// ---------------- SGEMM: C[M,DIM] = A[M,DIM] @ B[DIM,DIM] + bias -----------
__global__ __launch_bounds__(256) void sgemm_bias(
    const float* __restrict__ A, const float* __restrict__ B,
    const float* __restrict__ bias, float* __restrict__ C, int M)
{
    const int N = DIM, K = DIM;
    __shared__ float As[16][68];
    __shared__ float Bs[16][68];
    int bm = blockIdx.y * 64, bn = blockIdx.x * 64;
    int tid = threadIdx.x;
    int ty = tid >> 4, tx = tid & 15;

    float acc[4][4] = {};

    int am  = tid >> 2;   // 0..63 row of A tile
    int ak4 = tid & 3;    // 0..3  float4 index along k
    int bk  = tid >> 4;   // 0..15 k row of B tile
    int bn4 = tid & 15;   // 0..15 float4 index along n
    bool avalid = (bm + am) < M;
    const float* Aptr = A + (size_t)(bm + am) * K + ak4 * 4;

    for (int k0 = 0; k0 < K; k0 += 16) {
        float4 av = avalid ? *(const float4*)(Aptr + k0) : make_float4(0.f,0.f,0.f,0.f);
        As[ak4*4+0][am] = av.x;
        As[ak4*4+1][am] = av.y;
        As[ak4*4+2][am] = av.z;
        As[ak4*4+3][am] = av.w;
        float4 bv = *(const float4*)(B + (size_t)(k0 + bk) * N + bn + bn4 * 4);
        *(float4*)&Bs[bk][bn4*4] = bv;
        __syncthreads();
        #pragma unroll
        for (int kk = 0; kk < 16; kk++) {
            float4 a = *(const float4*)&As[kk][ty*4];
            float4 b = *(const float4*)&Bs[kk][tx*4];
            float ar[4] = {a.x, a.y, a.z, a.w};
            float br[4] = {b.x, b.y, b.z, b.w};
            #pragma unroll
            for (int i = 0; i < 4; i++)
                #pragma unroll
                for (int j = 0; j < 4; j++)
                    acc[i][j] = fmaf(ar[i], br[j], acc[i][j]);
        }
        __syncthreads();
    }
    #pragma unroll
    for (int i = 0; i < 4; i++) {
        int gm = bm + ty*4 + i;
        if (gm < M) {
            #pragma unroll
            for (int j = 0; j < 4; j++) {
                int gn = bn + tx*4 + j;
                C[(size_t)gm * N + gn] = acc[i][j] + bias[gn];
            }
        }
    }
}

// ---------------- rmsnorm (+rope for q) ------------------------------------
__device__ __forceinline__ float block_rms_scale(const float* row, float* red)
{
    float ss = 0.f;
    for (int i = threadIdx.x; i < DIM; i += 256) { float v = row[i]; ss += v * v; }
    #pragma unroll
    for (int o = 16; o; o >>= 1) ss += __shfl_xor_sync(0xffffffffu, ss, o);
    if ((threadIdx.x & 31) == 0) red[threadIdx.x >> 5] = ss;
    __syncthreads();
    if (threadIdx.x == 0) {
        float tot = 0.f;
        #pragma unroll
        for (int i = 0; i < 8; i++) tot += red[i];
        red[0] = rsqrtf(tot / (float)DIM + EPS_F);
    }
    __syncthreads();
    return red[0];
}

__global__ __launch_bounds__(256) void rmsnorm_rope_q(
    float* __restrict__ q, const float* __restrict__ g,
    const float* __restrict__ fc, const float* __restrict__ fs)
{
    __shared__ float red[8];
    int t = blockIdx.x;
    float* row = q + (size_t)t * DIM;
    float scale = block_rms_scale(row, red);
    int h = t / WW, w = t % WW;
    for (int p = threadIdx.x; p < DIM / 2; p += 256) {
        int c = p & 63;
        int ridx = (c < FT) ? Q_FRAME : ((c < FT + FSZ) ? h : w);
        float cs = fc[ridx * 64 + c], sn = fs[ridx * 64 + c];
        float a = row[2*p]   * scale * g[2*p];
        float b = row[2*p+1] * scale * g[2*p+1];
        row[2*p]   = a * cs - b * sn;
        row[2*p+1] = a * sn + b * cs;
    }
}

__global__ __launch_bounds__(256) void rmsnorm_plain(
    float* __restrict__ k, const float* __restrict__ g)
{
    __shared__ float red[8];
    int t = blockIdx.x;
    float* row = k + (size_t)t * DIM;
    float scale = block_rms_scale(row, red);
    for (int i = threadIdx.x; i < DIM; i += 256)
        row[i] = row[i] * scale * g[i];
}

// ---------------- build combined KV (gather + sink-blend + rope on K) -------
__global__ __launch_bounds__(256) void build_kv(
    const float* __restrict__ ck, const float* __restrict__ cv,
    const float* __restrict__ kn, const float* __restrict__ vn,
    float* __restrict__ kc, float* __restrict__ vc,
    const float* __restrict__ fc, const float* __restrict__ fs)
{
    int r = blockIdx.x;                 // 0..9359
    const float *sk, *sv, *sk2 = nullptr, *sv2 = nullptr;
    if (r < 1560) {
        sk  = ck + (size_t)r * DIM;        sv  = cv + (size_t)r * DIM;
        sk2 = ck + (size_t)(9360 + r) * DIM; sv2 = cv + (size_t)(9360 + r) * DIM;
    } else if (r < 7800) {
        sk = ck + (size_t)(r + 3120) * DIM; sv = cv + (size_t)(r + 3120) * DIM;
    } else {
        sk = kn + (size_t)(r - 7800) * DIM; sv = vn + (size_t)(r - 7800) * DIM;
    }
    // V: blend/copy
    float* vd = vc + (size_t)r * DIM;
    for (int i = threadIdx.x; i < DIM; i += 256) {
        float v = sv[i];
        if (sv2) v = ALPHA_F * v + BETA_F * sv2[i];
        vd[i] = v;
    }
    // K: blend/copy + rope
    int fr = r / 1560, p = r % 1560, h = p / WW, w = p % WW;
    float* kd = kc + (size_t)r * DIM;
    for (int pp = threadIdx.x; pp < DIM / 2; pp += 256) {
        int c = pp & 63;
        int ridx = (c < FT) ? fr : ((c < FT + FSZ) ? h : w);
        float cs = fc[ridx * 64 + c], sn = fs[ridx * 64 + c];
        float a = sk[2*pp], b = sk[2*pp+1];
        if (sk2) { a = ALPHA_F*a + BETA_F*sk2[2*pp]; b = ALPHA_F*b + BETA_F*sk2[2*pp+1]; }
        kd[2*pp]   = a * cs - b * sn;
        kd[2*pp+1] = a * sn + b * cs;
    }
}

// ---------------- flash attention (fp32), 64q x 64k tiles --------------------
#define ATTN_SMEM_FLOATS (64*128 + 64*129 + 64*128 + 64*68 + 192)

__global__ __launch_bounds__(256) void attn_kernel(
    const float* __restrict__ Q, const float* __restrict__ Kc,
    const float* __restrict__ Vc, float* __restrict__ Oo)
{
    extern __shared__ float sm[];
    float* Qs   = sm;                  // [64][128]
    float* Ks   = Qs + 64*128;         // [64][129]  (pad for conflict-free scalar reads)
    float* Vs   = Ks + 64*129;         // [64][128]
    float* Ss   = Vs + 64*128;         // [64][68]   (pad, float4-aligned rows)
    float* rowm = Ss + 64*68;
    float* rowl = rowm + 64;
    float* rowa = rowl + 64;

    int q0 = blockIdx.x * 64;
    int h  = blockIdx.y;
    int tid = threadIdx.x;
    int ty = tid >> 4, tx = tid & 15;

    // load Q tile (float4, coalesced)
    #pragma unroll
    for (int i = 0; i < 8; i++) {
        int idx = tid + 256*i;
        int r = idx >> 5, d4 = idx & 31;
        int gq = q0 + r;
        float4 v = (gq < S_LEN)
            ? *(const float4*)(Q + (size_t)gq*DIM + h*HDIM + d4*4)
            : make_float4(0.f,0.f,0.f,0.f);
        *(float4*)&Qs[r*128 + d4*4] = v;
    }
    if (tid < 64) { rowm[tid] = -INFINITY; rowl[tid] = 0.f; }

    float acco[4][8] = {};

    const int nkt = (KV_LEN + 63) / 64;   // 147
    for (int kt = 0; kt < nkt; kt++) {
        int kt0 = kt * 64;
        __syncthreads();   // previous PV done before smem overwrite
        // K tile: scalar loads (coalesced) -> padded smem, conflict-free stores
        #pragma unroll
        for (int i = 0; i < 8; i++) {
            int idx = tid + 256*i;
            int r = idx >> 5, lane = idx & 31;
            int gr = kt0 + r;
            bool ok = gr < KV_LEN;
            const float* src = Kc + (size_t)gr*DIM + h*HDIM;
            #pragma unroll
            for (int c = 0; c < 4; c++) {
                int kk = lane + 32*c;
                Ks[r*129 + kk] = ok ? src[kk] : 0.f;
            }
        }
        // V tile: float4
        #pragma unroll
        for (int i = 0; i < 8; i++) {
            int idx = tid + 256*i;
            int r = idx >> 5, d4 = idx & 31;
            int gr = kt0 + r;
            float4 v = (gr < KV_LEN)
                ? *(const float4*)(Vc + (size_t)gr*DIM + h*HDIM + d4*4)
                : make_float4(0.f,0.f,0.f,0.f);
            *(float4*)&Vs[r*128 + d4*4] = v;
        }
        __syncthreads();

        // ---- S = Q K^T (strided 4x4 micro-tiles) ----
        float accs[4][4] = {};
        #pragma unroll 8
        for (int kk4 = 0; kk4 < 32; kk4++) {
            float ar[4][4];
            #pragma unroll
            for (int i = 0; i < 4; i++) {
                float4 a = *(const float4*)&Qs[(ty + 16*i)*128 + kk4*4];
                ar[i][0]=a.x; ar[i][1]=a.y; ar[i][2]=a.z; ar[i][3]=a.w;
            }
            #pragma unroll
            for (int u = 0; u < 4; u++) {
                int kk = kk4*4 + u;
                float b[4];
                #pragma unroll
                for (int j = 0; j < 4; j++) b[j] = Ks[(tx + 16*j)*129 + kk];
                #pragma unroll
                for (int i = 0; i < 4; i++)
                    #pragma unroll
                    for (int j = 0; j < 4; j++)
                        accs[i][j] = fmaf(ar[i][u], b[j], accs[i][j]);
            }
        }
        #pragma unroll
        for (int i = 0; i < 4; i++)
            #pragma unroll
            for (int j = 0; j < 4; j++) {
                int col = tx + 16*j;
                float sv = (kt0 + col < KV_LEN) ? accs[i][j] * SCALE : -1e30f;
                Ss[(ty + 16*i)*68 + col] = sv;
            }
        __syncthreads();

        // ---- online softmax (4 threads / row) ----
        {
            int row = tid >> 2, part = tid & 3;
            float mx = -INFINITY;
            #pragma unroll
            for (int c = part; c < 64; c += 4) mx = fmaxf(mx, Ss[row*68 + c]);
            mx = fmaxf(mx, __shfl_xor_sync(0xffffffffu, mx, 1));
            mx = fmaxf(mx, __shfl_xor_sync(0xffffffffu, mx, 2));
            float m_old = rowm[row];
            float mnew  = fmaxf(m_old, mx);
            float sum = 0.f;
            #pragma unroll
            for (int c = part; c < 64; c += 4) {
                float pv = __expf(Ss[row*68 + c] - mnew);
                Ss[row*68 + c] = pv;
                sum += pv;
            }
            sum += __shfl_xor_sync(0xffffffffu, sum, 1);
            sum += __shfl_xor_sync(0xffffffffu, sum, 2);
            if (part == 0) {
                float alpha = __expf(m_old - mnew);
                rowa[row] = alpha;
                rowl[row] = rowl[row] * alpha + sum;
                rowm[row] = mnew;
            }
        }
        __syncthreads();

        // ---- O = O*alpha + P @ V (strided 4x8 micro-tiles) ----
        #pragma unroll
        for (int i = 0; i < 4; i++) {
            float alpha = rowa[ty + 16*i];
            #pragma unroll
            for (int j = 0; j < 8; j++) acco[i][j] *= alpha;
        }
        #pragma unroll 4
        for (int kk4 = 0; kk4 < 16; kk4++) {
            float ar[4][4];
            #pragma unroll
            for (int i = 0; i < 4; i++) {
                float4 a = *(const float4*)&Ss[(ty + 16*i)*68 + kk4*4];
                ar[i][0]=a.x; ar[i][1]=a.y; ar[i][2]=a.z; ar[i][3]=a.w;
            }
            #pragma unroll
            for (int u = 0; u < 4; u++) {
                int kk = kk4*4 + u;
                float b[8];
                #pragma unroll
                for (int j = 0; j < 8; j++) b[j] = Vs[kk*128 + tx + 16*j];
                #pragma unroll
                for (int i = 0; i < 4; i++)
                    #pragma unroll
                    for (int j = 0; j < 8; j++)
                        acco[i][j] = fmaf(ar[i][u], b[j], acco[i][j]);
            }
        }
    }

    // final: divide by l, write out
    #pragma unroll
    for (int i = 0; i < 4; i++) {
        int r = ty + 16*i;
        int gq = q0 + r;
        if (gq < S_LEN) {
            float inv = 1.f / rowl[r];
            #pragma unroll
            for (int j = 0; j < 8; j++)
                Oo[(size_t)gq*DIM + h*HDIM + tx + 16*j] = acco[i][j] * inv;
        }
    }
}

// ---------------- launch -----------------------------------------------------
extern "C" void kernel_launch(void* const* d_in, const int* in_sizes, int n_in,
                              void* d_out, int out_size)
{
    const float* x  = (const float*)d_in[0];
    const float* Wq = (const float*)d_in[1];
    const float* bq = (const float*)d_in[2];
    const float* Wk = (const float*)d_in[3];
    const float* bk = (const float*)d_in[4];
    const float* Wv = (const float*)d_in[5];
    const float* bv = (const float*)d_in[6];
    const float* Wo = (const float*)d_in[7];
    const float* bo = (const float*)d_in[8];
    const float* gq = (const float*)d_in[9];
    const float* gk = (const float*)d_in[10];
    const float* ck = (const float*)d_in[11];
    const float* cv = (const float*)d_in[12];
    const float* fc = (const float*)d_in[13];
    const float* fs = (const float*)d_in[14];
    float* out = (float*)d_out;

    float *qb, *kb, *vb, *kc, *vc, *ob;
    cudaGetSymbolAddress((void**)&qb, d_qbuf);
    cudaGetSymbolAddress((void**)&kb, d_kbuf);
    cudaGetSymbolAddress((void**)&vb, d_vbuf);
    cudaGetSymbolAddress((void**)&kc, d_kc);
    cudaGetSymbolAddress((void**)&vc, d_vc);
    cudaGetSymbolAddress((void**)&ob, d_obuf);

    dim3 gg(DIM / 64, (S_LEN + 63) / 64);   // 24 x 25

    sgemm_bias<<<gg, 256>>>(x, Wq, bq, qb, S_LEN);
    sgemm_bias<<<gg, 256>>>(x, Wk, bk, kb, S_LEN);
    sgemm_bias<<<gg, 256>>>(x, Wv, bv, vb, S_LEN);

    rmsnorm_rope_q<<<S_LEN, 256>>>(qb, gq, fc, fs);
    rmsnorm_plain<<<S_LEN, 256>>>(kb, gk);

    build_kv<<<KV_LEN, 256>>>(ck, cv, kb, vb, kc, vc, fc, fs);

    int attn_smem = ATTN_SMEM_FLOATS * (int)sizeof(float);
    cudaFuncSetAttribute(attn_kernel, cudaFuncAttributeMaxDynamicSharedMemorySize, attn_smem);
    attn_kernel<<<dim3((S_LEN + 63) / 64, NHEADS), 256, attn_smem>>>(qb, kc, vc, ob);

    sgemm_bias<<<gg, 256>>>(ob, Wo, bo, out, S_LEN);
}

// round 2
// speedup vs baseline: 1.0951x; 1.0951x over previous
#include <cuda_runtime.h>
#include <math.h>
#include <stdint.h>

#define DIM      1536
#define NHEADS   12
#define HDIM     128
#define S_LEN    1560
#define KV_LEN   9360
#define FT       22
#define FSZ      21
#define WW       52
#define ALPHA_F  0.999f
#define BETA_F   0.001f
#define EPS_F    1e-6f
#define Q_FRAME  5
#define SCALE    0.08838834764831843f   /* 1/sqrt(128) */

// ---------------- scratch (device globals; no allocations allowed) ----------
__device__ float d_qbuf[S_LEN * DIM];
__device__ float d_kbuf[S_LEN * DIM];
__device__ float d_vbuf[S_LEN * DIM];
__device__ float d_kc[KV_LEN * DIM];
__device__ float d_vc[KV_LEN * DIM];
__device__ float d_obuf[S_LEN * DIM];

// ---------------- SGEMM: C[M,DIM] = A[M,DIM] @ B[DIM,DIM] + bias -----------
__global__ __launch_bounds__(256) void sgemm_bias(
    const float* __restrict__ A, const float* __restrict__ B,
    const float* __restrict__ bias, float* __restrict__ C, int M)
{
    const int N = DIM, K = DIM;
    __shared__ float As[16][68];
    __shared__ float Bs[16][68];
    int bm = blockIdx.y * 64, bn = blockIdx.x * 64;
    int tid = threadIdx.x;
    int ty = tid >> 4, tx = tid & 15;

    float acc[4][4] = {};

    int am  = tid >> 2;
    int ak4 = tid & 3;
    int bk  = tid >> 4;
    int bn4 = tid & 15;
    bool avalid = (bm + am) < M;
    const float* Aptr = A + (size_t)(bm + am) * K + ak4 * 4;

    for (int k0 = 0; k0 < K; k0 += 16) {
        float4 av = avalid ? *(const float4*)(Aptr + k0) : make_float4(0.f,0.f,0.f,0.f);
        As[ak4*4+0][am] = av.x;
        As[ak4*4+1][am] = av.y;
        As[ak4*4+2][am] = av.z;
        As[ak4*4+3][am] = av.w;
        float4 bv = *(const float4*)(B + (size_t)(k0 + bk) * N + bn + bn4 * 4);
        *(float4*)&Bs[bk][bn4*4] = bv;
        __syncthreads();
        #pragma unroll
        for (int kk = 0; kk < 16; kk++) {
            float4 a = *(const float4*)&As[kk][ty*4];
            float4 b = *(const float4*)&Bs[kk][tx*4];
            float ar[4] = {a.x, a.y, a.z, a.w};
            float br[4] = {b.x, b.y, b.z, b.w};
            #pragma unroll
            for (int i = 0; i < 4; i++)
                #pragma unroll
                for (int j = 0; j < 4; j++)
                    acc[i][j] = fmaf(ar[i], br[j], acc[i][j]);
        }
        __syncthreads();
    }
    #pragma unroll
    for (int i = 0; i < 4; i++) {
        int gm = bm + ty*4 + i;
        if (gm < M) {
            #pragma unroll
            for (int j = 0; j < 4; j++) {
                int gn = bn + tx*4 + j;
                C[(size_t)gm * N + gn] = acc[i][j] + bias[gn];
            }
        }
    }
}

// ---------------- rmsnorm (+rope for q) ------------------------------------
__device__ __forceinline__ float block_rms_scale(const float* row, float* red)
{
    float ss = 0.f;
    for (int i = threadIdx.x; i < DIM; i += 256) { float v = row[i]; ss += v * v; }
    #pragma unroll
    for (int o = 16; o; o >>= 1) ss += __shfl_xor_sync(0xffffffffu, ss, o);
    if ((threadIdx.x & 31) == 0) red[threadIdx.x >> 5] = ss;
    __syncthreads();
    if (threadIdx.x == 0) {
        float tot = 0.f;
        #pragma unroll
        for (int i = 0; i < 8; i++) tot += red[i];
        red[0] = rsqrtf(tot / (float)DIM + EPS_F);
    }
    __syncthreads();
    return red[0];
}

__global__ __launch_bounds__(256) void rmsnorm_rope_q(
    float* __restrict__ q, const float* __restrict__ g,
    const float* __restrict__ fc, const float* __restrict__ fs)
{
    __shared__ float red[8];
    int t = blockIdx.x;
    float* row = q + (size_t)t * DIM;
    float scale = block_rms_scale(row, red);
    int h = t / WW, w = t % WW;
    for (int p = threadIdx.x; p < DIM / 2; p += 256) {
        int c = p & 63;
        int ridx = (c < FT) ? Q_FRAME : ((c < FT + FSZ) ? h : w);
        float cs = fc[ridx * 64 + c], sn = fs[ridx * 64 + c];
        float a = row[2*p]   * scale * g[2*p];
        float b = row[2*p+1] * scale * g[2*p+1];
        row[2*p]   = a * cs - b * sn;
        row[2*p+1] = a * sn + b * cs;
    }
}

__global__ __launch_bounds__(256) void rmsnorm_plain(
    float* __restrict__ k, const float* __restrict__ g)
{
    __shared__ float red[8];
    int t = blockIdx.x;
    float* row = k + (size_t)t * DIM;
    float scale = block_rms_scale(row, red);
    for (int i = threadIdx.x; i < DIM; i += 256)
        row[i] = row[i] * scale * g[i];
}

// ---------------- build combined KV (gather + sink-blend + rope on K) -------
__global__ __launch_bounds__(256) void build_kv(
    const float* __restrict__ ck, const float* __restrict__ cv,
    const float* __restrict__ kn, const float* __restrict__ vn,
    float* __restrict__ kc, float* __restrict__ vc,
    const float* __restrict__ fc, const float* __restrict__ fs)
{
    int r = blockIdx.x;
    const float *sk, *sv, *sk2 = nullptr, *sv2 = nullptr;
    if (r < 1560) {
        sk  = ck + (size_t)r * DIM;          sv  = cv + (size_t)r * DIM;
        sk2 = ck + (size_t)(9360 + r) * DIM; sv2 = cv + (size_t)(9360 + r) * DIM;
    } else if (r < 7800) {
        sk = ck + (size_t)(r + 3120) * DIM;  sv = cv + (size_t)(r + 3120) * DIM;
    } else {
        sk = kn + (size_t)(r - 7800) * DIM;  sv = vn + (size_t)(r - 7800) * DIM;
    }
    float* vd = vc + (size_t)r * DIM;
    for (int i = threadIdx.x; i < DIM; i += 256) {
        float v = sv[i];
        if (sv2) v = ALPHA_F * v + BETA_F * sv2[i];
        vd[i] = v;
    }
    int fr = r / 1560, p = r % 1560, h = p / WW, w = p % WW;
    float* kd = kc + (size_t)r * DIM;
    for (int pp = threadIdx.x; pp < DIM / 2; pp += 256) {
        int c = pp & 63;
        int ridx = (c < FT) ? fr : ((c < FT + FSZ) ? h : w);
        float cs = fc[ridx * 64 + c], sn = fs[ridx * 64 + c];
        float a = sk[2*pp], b = sk[2*pp+1];
        if (sk2) { a = ALPHA_F*a + BETA_F*sk2[2*pp]; b = ALPHA_F*b + BETA_F*sk2[2*pp+1]; }
        kd[2*pp]   = a * cs - b * sn;
        kd[2*pp+1] = a * sn + b * cs;
    }
}

// ================== tf32 tensor-core flash attention =========================
// smem layout (uint32 units):
//   QA  [16ks][4mi][32lane][4reg]   : 8192   (Q A-fragments, tf32 bits)
//   KB  [16ks][8nt][32lane][2reg]   : 8192   (K B-fragments)  -- aliased with:
//   PA  [8ks][4mi][32lane][4reg]    : 4096   (P A-fragments, overlays KB)
//   VB  [8ks][16nt][32lane][2reg]   : 8192   (V B-fragments)
//   xmax[2][64], xsum[2][64]        : 256
#define ATTN_SMEM_U32 (8192 + 8192 + 8192 + 256)

__device__ __forceinline__ uint32_t f2tf32(float f) {
    uint32_t r;
    asm("cvt.rna.tf32.f32 %0, %1;" : "=r"(r) : "f"(f));
    return r;
}

__device__ __forceinline__ void mma_tf32(
    float& c0, float& c1, float& c2, float& c3,
    uint32_t a0, uint32_t a1, uint32_t a2, uint32_t a3,
    uint32_t b0, uint32_t b1)
{
    asm volatile(
        "mma.sync.aligned.m16n8k8.row.col.f32.tf32.tf32.f32 "
        "{%0,%1,%2,%3},{%4,%5,%6,%7},{%8,%9},{%0,%1,%2,%3};"
        : "+f"(c0), "+f"(c1), "+f"(c2), "+f"(c3)
        : "r"(a0), "r"(a1), "r"(a2), "r"(a3), "r"(b0), "r"(b1));
}

__global__ __launch_bounds__(256, 2) void attn_tc(
    const float* __restrict__ Q, const float* __restrict__ Kc,
    const float* __restrict__ Vc, float* __restrict__ Oo)
{
    extern __shared__ uint32_t sm[];
    uint32_t* QA = sm;                 // 8192
    uint32_t* KB = sm + 8192;          // 8192 (QK phase)
    uint32_t* PA = sm + 8192;          // 4096 (PV phase, overlays KB)
    uint32_t* VB = sm + 16384;         // 8192
    float* xmax  = (float*)(sm + 24576);  // [2][64]
    float* xsum  = (float*)(sm + 24704);  // [2][64]

    const int q0   = blockIdx.x * 64;
    const int head = blockIdx.y;
    const int tid  = threadIdx.x;
    const int lane = tid & 31;
    const int wrp  = tid >> 5;
    const int mi   = wrp & 3;       // M group: rows 16*mi..16*mi+15
    const int ni   = wrp >> 2;      // N group: cols 32*ni..32*ni+31
    const int g    = lane >> 2;     // groupID
    const int t4   = lane & 3;      // threadID in group

    // ---- Q -> QA fragments (once) ----
    for (int idx = tid; idx < 64 * 32; idx += 256) {
        int r = idx >> 5, d4 = idx & 31;
        int k = d4 * 4;
        int gq = q0 + r;
        float4 v = (gq < S_LEN)
            ? *(const float4*)(Q + (size_t)gq * DIM + head * HDIM + k)
            : make_float4(0.f, 0.f, 0.f, 0.f);
        int ks = k >> 3;
        int khi = (k & 4) ? 2 : 0;
        int rl = r & 15;
        int reg = ((rl >= 8) ? 1 : 0) + khi;
        int ln = (rl & 7) * 4;
        uint32_t* base = QA + (size_t)((ks * 4 + (r >> 4)) * 32) * 4;
        base[(ln + 0) * 4 + reg] = f2tf32(v.x);
        base[(ln + 1) * 4 + reg] = f2tf32(v.y);
        base[(ln + 2) * 4 + reg] = f2tf32(v.z);
        base[(ln + 3) * 4 + reg] = f2tf32(v.w);
    }

    float m0 = -INFINITY, m1 = -INFINITY;
    float l0 = 0.f, l1 = 0.f;
    float O[8][4];
    #pragma unroll
    for (int i = 0; i < 8; i++)
        #pragma unroll
        for (int j = 0; j < 4; j++) O[i][j] = 0.f;

    const int nkt = (KV_LEN + 63) / 64;   // 147
    for (int kt = 0; kt < nkt; kt++) {
        int kt0 = kt * 64;
        __syncthreads();   // prev PV (reads PA/VB) done before overwrite

        // ---- K tile -> KB fragments ----
        for (int idx = tid; idx < 64 * 32; idx += 256) {
            int row = idx >> 5, d4 = idx & 31;
            int k = d4 * 4;
            int gr = kt0 + row;
            float4 v = (gr < KV_LEN)
                ? *(const float4*)(Kc + (size_t)gr * DIM + head * HDIM + k)
                : make_float4(0.f, 0.f, 0.f, 0.f);
            int ks = k >> 3;
            int reg = (k & 4) ? 1 : 0;
            int nt = row >> 3;
            int ln = (row & 7) * 4;
            uint32_t* base = KB + (size_t)((ks * 8 + nt) * 32) * 2;
            base[(ln + 0) * 2 + reg] = f2tf32(v.x);
            base[(ln + 1) * 2 + reg] = f2tf32(v.y);
            base[(ln + 2) * 2 + reg] = f2tf32(v.z);
            base[(ln + 3) * 2 + reg] = f2tf32(v.w);
        }
        // ---- V tile -> VB fragments ----
        for (int idx = tid; idx < 64 * 32; idx += 256) {
            int row = idx >> 5, d4 = idx & 31;
            int d = d4 * 4;
            int gr = kt0 + row;
            float4 v = (gr < KV_LEN)
                ? *(const float4*)(Vc + (size_t)gr * DIM + head * HDIM + d)
                : make_float4(0.f, 0.f, 0.f, 0.f);
            int ks = row >> 3;
            int reg = (row & 4) ? 1 : 0;
            int nt = d >> 3;
            int t0 = row & 3;
            uint32_t* base = VB + (size_t)((ks * 16 + nt) * 32) * 2;
            base[(((d & 7) + 0) * 4 + t0) * 2 + reg] = f2tf32(v.x);
            base[(((d & 7) + 1) * 4 + t0) * 2 + reg] = f2tf32(v.y);
            base[(((d & 7) + 2) * 4 + t0) * 2 + reg] = f2tf32(v.z);
            base[(((d & 7) + 3) * 4 + t0) * 2 + reg] = f2tf32(v.w);
        }
        __syncthreads();

        // ---- S = Q K^T ----
        float Sc[4][4];
        #pragma unroll
        for (int i = 0; i < 4; i++)
            #pragma unroll
            for (int j = 0; j < 4; j++) Sc[i][j] = 0.f;

        #pragma unroll
        for (int ks = 0; ks < 16; ks++) {
            uint4 a = *(const uint4*)(QA + (size_t)((ks * 4 + mi) * 32 + lane) * 4);
            #pragma unroll
            for (int ntl = 0; ntl < 4; ntl++) {
                int nt = ni * 4 + ntl;
                uint2 b = *(const uint2*)(KB + (size_t)((ks * 8 + nt) * 32 + lane) * 2);
                mma_tf32(Sc[ntl][0], Sc[ntl][1], Sc[ntl][2], Sc[ntl][3],
                         a.x, a.y, a.z, a.w, b.x, b.y);
            }
        }

        // scale + mask
        float pm0 = -INFINITY, pm1 = -INFINITY;
        #pragma unroll
        for (int ntl = 0; ntl < 4; ntl++) {
            int cbase = ni * 32 + ntl * 8 + 2 * t4;
            #pragma unroll
            for (int j = 0; j < 4; j++) {
                int c = cbase + (j & 1);
                bool valid = (kt0 + c) < KV_LEN;
                Sc[ntl][j] = valid ? Sc[ntl][j] * SCALE : -1e30f;
            }
            pm0 = fmaxf(pm0, fmaxf(Sc[ntl][0], Sc[ntl][1]));
            pm1 = fmaxf(pm1, fmaxf(Sc[ntl][2], Sc[ntl][3]));
        }
        pm0 = fmaxf(pm0, __shfl_xor_sync(0xffffffffu, pm0, 1));
        pm0 = fmaxf(pm0, __shfl_xor_sync(0xffffffffu, pm0, 2));
        pm1 = fmaxf(pm1, __shfl_xor_sync(0xffffffffu, pm1, 1));
        pm1 = fmaxf(pm1, __shfl_xor_sync(0xffffffffu, pm1, 2));
        if (t4 == 0) {
            xmax[ni * 64 + 16 * mi + g]     = pm0;
            xmax[ni * 64 + 16 * mi + g + 8] = pm1;
        }
        __syncthreads();   // xmax visible; KB reads done -> PA writes safe

        int r0 = 16 * mi + g, r1 = r0 + 8;
        float m0n = fmaxf(m0, fmaxf(xmax[r0], xmax[64 + r0]));
        float m1n = fmaxf(m1, fmaxf(xmax[r1], xmax[64 + r1]));

        float s0 = 0.f, s1 = 0.f;
        #pragma unroll
        for (int ntl = 0; ntl < 4; ntl++) {
            int ks = ni * 4 + ntl;
            uint32_t* base = PA + (size_t)((ks * 4 + mi) * 32) * 4;
            #pragma unroll
            for (int j = 0; j < 4; j++) {
                float e = __expf(Sc[ntl][j] - ((j < 2) ? m0n : m1n));
                if (j < 2) s0 += e; else s1 += e;
                int c = 2 * t4 + (j & 1);               // col within 8-block
                int rl = (j < 2) ? g : (g + 8);
                int reg = ((rl >= 8) ? 1 : 0) + ((c >= 4) ? 2 : 0);
                base[((rl & 7) * 4 + (c & 3)) * 4 + reg] = f2tf32(e);
            }
        }
        s0 += __shfl_xor_sync(0xffffffffu, s0, 1);
        s0 += __shfl_xor_sync(0xffffffffu, s0, 2);
        s1 += __shfl_xor_sync(0xffffffffu, s1, 1);
        s1 += __shfl_xor_sync(0xffffffffu, s1, 2);
        if (t4 == 0) {
            xsum[ni * 64 + r0] = s0;
            xsum[ni * 64 + r1] = s1;
        }
        __syncthreads();

        float alpha0 = __expf(m0 - m0n);
        float alpha1 = __expf(m1 - m1n);
        l0 = l0 * alpha0 + xsum[r0] + xsum[64 + r0];
        l1 = l1 * alpha1 + xsum[r1] + xsum[64 + r1];
        m0 = m0n; m1 = m1n;

        #pragma unroll
        for (int ntl = 0; ntl < 8; ntl++) {
            O[ntl][0] *= alpha0; O[ntl][1] *= alpha0;
            O[ntl][2] *= alpha1; O[ntl][3] *= alpha1;
        }

        // ---- O += P V ----
        #pragma unroll
        for (int ks = 0; ks < 8; ks++) {
            uint4 a = *(const uint4*)(PA + (size_t)((ks * 4 + mi) * 32 + lane) * 4);
            #pragma unroll
            for (int ntl = 0; ntl < 8; ntl++) {
                int nt = ni * 8 + ntl;
                uint2 b = *(const uint2*)(VB + (size_t)((ks * 16 + nt) * 32 + lane) * 2);
                mma_tf32(O[ntl][0], O[ntl][1], O[ntl][2], O[ntl][3],
                         a.x, a.y, a.z, a.w, b.x, b.y);
            }
        }
    }

    // ---- finalize ----
    float inv0 = 1.f / l0, inv1 = 1.f / l1;
    int gr0 = q0 + 16 * mi + g;
    int gr1 = gr0 + 8;
    #pragma unroll
    for (int ntl = 0; ntl < 8; ntl++) {
        int c = ni * 64 + ntl * 8 + 2 * t4;
        if (gr0 < S_LEN) {
            float2 o0 = make_float2(O[ntl][0] * inv0, O[ntl][1] * inv0);
            *(float2*)(Oo + (size_t)gr0 * DIM + head * HDIM + c) = o0;
        }
        if (gr1 < S_LEN) {
            float2 o1 = make_float2(O[ntl][2] * inv1, O[ntl][3] * inv1);
            *(float2*)(Oo + (size_t)gr1 * DIM + head * HDIM + c) = o1;
        }
    }
}

// ---------------- launch -----------------------------------------------------
extern "C" void kernel_launch(void* const* d_in, const int* in_sizes, int n_in,
                              void* d_out, int out_size)
{
    const float* x  = (const float*)d_in[0];
    const float* Wq = (const float*)d_in[1];
    const float* bq = (const float*)d_in[2];
    const float* Wk = (const float*)d_in[3];
    const float* bk = (const float*)d_in[4];
    const float* Wv = (const float*)d_in[5];
    const float* bv = (const float*)d_in[6];
    const float* Wo = (const float*)d_in[7];
    const float* bo = (const float*)d_in[8];
    const float* gq = (const float*)d_in[9];
    const float* gk = (const float*)d_in[10];
    const float* ck = (const float*)d_in[11];
    const float* cv = (const float*)d_in[12];
    const float* fc = (const float*)d_in[13];
    const float* fs = (const float*)d_in[14];
    float* out = (float*)d_out;

    float *qb, *kb, *vb, *kc, *vc, *ob;
    cudaGetSymbolAddress((void**)&qb, d_qbuf);
    cudaGetSymbolAddress((void**)&kb, d_kbuf);
    cudaGetSymbolAddress((void**)&vb, d_vbuf);
    cudaGetSymbolAddress((void**)&kc, d_kc);
    cudaGetSymbolAddress((void**)&vc, d_vc);
    cudaGetSymbolAddress((void**)&ob, d_obuf);

    dim3 gg(DIM / 64, (S_LEN + 63) / 64);   // 24 x 25

    sgemm_bias<<<gg, 256>>>(x, Wq, bq, qb, S_LEN);
    sgemm_bias<<<gg, 256>>>(x, Wk, bk, kb, S_LEN);
    sgemm_bias<<<gg, 256>>>(x, Wv, bv, vb, S_LEN);

    rmsnorm_rope_q<<<S_LEN, 256>>>(qb, gq, fc, fs);
    rmsnorm_plain<<<S_LEN, 256>>>(kb, gk);

    build_kv<<<KV_LEN, 256>>>(ck, cv, kb, vb, kc, vc, fc, fs);

    int attn_smem = ATTN_SMEM_U32 * (int)sizeof(uint32_t);
    cudaFuncSetAttribute(attn_tc, cudaFuncAttributeMaxDynamicSharedMemorySize, attn_smem);
    attn_tc<<<dim3((S_LEN + 63) / 64, NHEADS), 256, attn_smem>>>(qb, kc, vc, ob);

    sgemm_bias<<<gg, 256>>>(ob, Wo, bo, out, S_LEN);
}

// round 3
// speedup vs baseline: 2.1213x; 1.9370x over previous
#include <cuda_runtime.h>
#include <math.h>
#include <stdint.h>

#define DIM      1536
#define NHEADS   12
#define HDIM     128
#define S_LEN    1560
#define KV_LEN   9360
#define FT       22
#define FSZ      21
#define WW       52
#define ALPHA_F  0.999f
#define BETA_F   0.001f
#define EPS_F    1e-6f
#define Q_FRAME  5
#define SCALE    0.08838834764831843f   /* 1/sqrt(128) */

// ---------------- scratch (device globals; no allocations allowed) ----------
__device__ float d_qbuf[S_LEN * DIM];
__device__ float d_kbuf[S_LEN * DIM];
__device__ float d_vbuf[S_LEN * DIM];
__device__ float d_kc[KV_LEN * DIM];
__device__ float d_vc[KV_LEN * DIM];
__device__ float d_obuf[S_LEN * DIM];

// ---------------- SGEMM: C[M,DIM] = A[M,DIM] @ B[DIM,DIM] + bias -----------
__global__ __launch_bounds__(256) void sgemm_bias(
    const float* __restrict__ A, const float* __restrict__ B,
    const float* __restrict__ bias, float* __restrict__ C, int M)
{
    const int N = DIM, K = DIM;
    __shared__ float As[16][68];
    __shared__ float Bs[16][68];
    int bm = blockIdx.y * 64, bn = blockIdx.x * 64;
    int tid = threadIdx.x;
    int ty = tid >> 4, tx = tid & 15;

    float acc[4][4] = {};

    int am  = tid >> 2;
    int ak4 = tid & 3;
    int bk  = tid >> 4;
    int bn4 = tid & 15;
    bool avalid = (bm + am) < M;
    const float* Aptr = A + (size_t)(bm + am) * K + ak4 * 4;

    for (int k0 = 0; k0 < K; k0 += 16) {
        float4 av = avalid ? *(const float4*)(Aptr + k0) : make_float4(0.f,0.f,0.f,0.f);
        As[ak4*4+0][am] = av.x;
        As[ak4*4+1][am] = av.y;
        As[ak4*4+2][am] = av.z;
        As[ak4*4+3][am] = av.w;
        float4 bv = *(const float4*)(B + (size_t)(k0 + bk) * N + bn + bn4 * 4);
        *(float4*)&Bs[bk][bn4*4] = bv;
        __syncthreads();
        #pragma unroll
        for (int kk = 0; kk < 16; kk++) {
            float4 a = *(const float4*)&As[kk][ty*4];
            float4 b = *(const float4*)&Bs[kk][tx*4];
            float ar[4] = {a.x, a.y, a.z, a.w};
            float br[4] = {b.x, b.y, b.z, b.w};
            #pragma unroll
            for (int i = 0; i < 4; i++)
                #pragma unroll
                for (int j = 0; j < 4; j++)
                    acc[i][j] = fmaf(ar[i], br[j], acc[i][j]);
        }
        __syncthreads();
    }
    #pragma unroll
    for (int i = 0; i < 4; i++) {
        int gm = bm + ty*4 + i;
        if (gm < M) {
            #pragma unroll
            for (int j = 0; j < 4; j++) {
                int gn = bn + tx*4 + j;
                C[(size_t)gm * N + gn] = acc[i][j] + bias[gn];
            }
        }
    }
}

// ---------------- rmsnorm (+rope for q) ------------------------------------
__device__ __forceinline__ float block_rms_scale(const float* row, float* red)
{
    float ss = 0.f;
    for (int i = threadIdx.x; i < DIM; i += 256) { float v = row[i]; ss += v * v; }
    #pragma unroll
    for (int o = 16; o; o >>= 1) ss += __shfl_xor_sync(0xffffffffu, ss, o);
    if ((threadIdx.x & 31) == 0) red[threadIdx.x >> 5] = ss;
    __syncthreads();
    if (threadIdx.x == 0) {
        float tot = 0.f;
        #pragma unroll
        for (int i = 0; i < 8; i++) tot += red[i];
        red[0] = rsqrtf(tot / (float)DIM + EPS_F);
    }
    __syncthreads();
    return red[0];
}

__global__ __launch_bounds__(256) void rmsnorm_rope_q(
    float* __restrict__ q, const float* __restrict__ g,
    const float* __restrict__ fc, const float* __restrict__ fs)
{
    __shared__ float red[8];
    int t = blockIdx.x;
    float* row = q + (size_t)t * DIM;
    float scale = block_rms_scale(row, red);
    int h = t / WW, w = t % WW;
    for (int p = threadIdx.x; p < DIM / 2; p += 256) {
        int c = p & 63;
        int ridx = (c < FT) ? Q_FRAME : ((c < FT + FSZ) ? h : w);
        float cs = fc[ridx * 64 + c], sn = fs[ridx * 64 + c];
        float a = row[2*p]   * scale * g[2*p];
        float b = row[2*p+1] * scale * g[2*p+1];
        row[2*p]   = a * cs - b * sn;
        row[2*p+1] = a * sn + b * cs;
    }
}

__global__ __launch_bounds__(256) void rmsnorm_plain(
    float* __restrict__ k, const float* __restrict__ g)
{
    __shared__ float red[8];
    int t = blockIdx.x;
    float* row = k + (size_t)t * DIM;
    float scale = block_rms_scale(row, red);
    for (int i = threadIdx.x; i < DIM; i += 256)
        row[i] = row[i] * scale * g[i];
}

// ---------------- build combined KV (gather + sink-blend + rope on K) -------
__global__ __launch_bounds__(256) void build_kv(
    const float* __restrict__ ck, const float* __restrict__ cv,
    const float* __restrict__ kn, const float* __restrict__ vn,
    float* __restrict__ kc, float* __restrict__ vc,
    const float* __restrict__ fc, const float* __restrict__ fs)
{
    int r = blockIdx.x;
    const float *sk, *sv, *sk2 = nullptr, *sv2 = nullptr;
    if (r < 1560) {
        sk  = ck + (size_t)r * DIM;          sv  = cv + (size_t)r * DIM;
        sk2 = ck + (size_t)(9360 + r) * DIM; sv2 = cv + (size_t)(9360 + r) * DIM;
    } else if (r < 7800) {
        sk = ck + (size_t)(r + 3120) * DIM;  sv = cv + (size_t)(r + 3120) * DIM;
    } else {
        sk = kn + (size_t)(r - 7800) * DIM;  sv = vn + (size_t)(r - 7800) * DIM;
    }
    float* vd = vc + (size_t)r * DIM;
    for (int i = threadIdx.x; i < DIM; i += 256) {
        float v = sv[i];
        if (sv2) v = ALPHA_F * v + BETA_F * sv2[i];
        vd[i] = v;
    }
    int fr = r / 1560, p = r % 1560, h = p / WW, w = p % WW;
    float* kd = kc + (size_t)r * DIM;
    for (int pp = threadIdx.x; pp < DIM / 2; pp += 256) {
        int c = pp & 63;
        int ridx = (c < FT) ? fr : ((c < FT + FSZ) ? h : w);
        float cs = fc[ridx * 64 + c], sn = fs[ridx * 64 + c];
        float a = sk[2*pp], b = sk[2*pp+1];
        if (sk2) { a = ALPHA_F*a + BETA_F*sk2[2*pp]; b = ALPHA_F*b + BETA_F*sk2[2*pp+1]; }
        kd[2*pp]   = a * cs - b * sn;
        kd[2*pp+1] = a * sn + b * cs;
    }
}

// ================== tf32 tensor-core flash attention =========================
// Padded strides kill the store-side bank conflicts:
//   QA: per-ks stride 516 words (4*128 + 4)  -> store 2-way, uint4 loads aligned+clean
//   KB: per-ks stride 514 words (8*64 + 2)   -> store banks = lane (conflict-free)
//   VB: per-nt stride 66 words  (64 + 2)     -> store 2-way, uint2 loads clean
//   PA: per-ks stride 516 words              -> overlays KB region
#define QA_KS 516
#define KB_KS 514
#define PA_KS 516
#define VB_NT 66
#define VB_KS (16 * VB_NT)     /* 1056 */

#define QA_OFF 0
#define KB_OFF (16 * QA_KS)                 /* 8256  */
#define PA_OFF KB_OFF
#define VB_OFF (KB_OFF + 16 * KB_KS)        /* 16480 */
#define XM_OFF (VB_OFF + 8 * VB_KS)         /* 24928 */
#define XS_OFF (XM_OFF + 128)
#define ATTN_SMEM_U32 (XS_OFF + 128)        /* 25184 words = 100736 B */

__device__ __forceinline__ uint32_t f2tf32(float f) {
    uint32_t r;
    asm("cvt.rna.tf32.f32 %0, %1;" : "=r"(r) : "f"(f));
    return r;
}

__device__ __forceinline__ void mma_tf32(
    float& c0, float& c1, float& c2, float& c3,
    uint32_t a0, uint32_t a1, uint32_t a2, uint32_t a3,
    uint32_t b0, uint32_t b1)
{
    asm volatile(
        "mma.sync.aligned.m16n8k8.row.col.f32.tf32.tf32.f32 "
        "{%0,%1,%2,%3},{%4,%5,%6,%7},{%8,%9},{%0,%1,%2,%3};"
        : "+f"(c0), "+f"(c1), "+f"(c2), "+f"(c3)
        : "r"(a0), "r"(a1), "r"(a2), "r"(a3), "r"(b0), "r"(b1));
}

__global__ __launch_bounds__(256, 2) void attn_tc(
    const float* __restrict__ Q, const float* __restrict__ Kc,
    const float* __restrict__ Vc, float* __restrict__ Oo)
{
    extern __shared__ uint32_t sm[];
    uint32_t* QA = sm + QA_OFF;
    uint32_t* KB = sm + KB_OFF;
    uint32_t* PA = sm + PA_OFF;
    uint32_t* VB = sm + VB_OFF;
    float* xmax  = (float*)(sm + XM_OFF);   // [2][64]
    float* xsum  = (float*)(sm + XS_OFF);   // [2][64]

    const int q0   = blockIdx.x * 64;
    const int head = blockIdx.y;
    const int tid  = threadIdx.x;
    const int lane = tid & 31;
    const int wrp  = tid >> 5;
    const int mi   = wrp & 3;       // M group: rows 16*mi..16*mi+15
    const int ni   = wrp >> 2;      // N group: cols 32*ni..32*ni+31
    const int g    = lane >> 2;     // groupID
    const int t4   = lane & 3;      // threadID in group

    // ---- Q -> QA fragments (once) ----
    for (int idx = tid; idx < 64 * 32; idx += 256) {
        int r = idx >> 5, d4 = idx & 31;
        int k = d4 * 4;
        int gq = q0 + r;
        float4 v = (gq < S_LEN)
            ? *(const float4*)(Q + (size_t)gq * DIM + head * HDIM + k)
            : make_float4(0.f, 0.f, 0.f, 0.f);
        int ks = k >> 3;
        int khi = (k & 4) ? 2 : 0;
        int rl = r & 15;
        int reg = ((rl >= 8) ? 1 : 0) + khi;
        int ln = (rl & 7) * 4;
        uint32_t* base = QA + ks * QA_KS + (r >> 4) * 128;
        base[(ln + 0) * 4 + reg] = f2tf32(v.x);
        base[(ln + 1) * 4 + reg] = f2tf32(v.y);
        base[(ln + 2) * 4 + reg] = f2tf32(v.z);
        base[(ln + 3) * 4 + reg] = f2tf32(v.w);
    }

    float m0 = -INFINITY, m1 = -INFINITY;
    float l0 = 0.f, l1 = 0.f;
    float O[8][4];
    #pragma unroll
    for (int i = 0; i < 8; i++)
        #pragma unroll
        for (int j = 0; j < 4; j++) O[i][j] = 0.f;

    const int nkt = (KV_LEN + 63) / 64;   // 147
    for (int kt = 0; kt < nkt; kt++) {
        int kt0 = kt * 64;
        __syncthreads();   // prev PV (reads PA/VB) done before overwrite

        // ---- K tile -> KB fragments (store banks = lane: conflict-free) ----
        for (int idx = tid; idx < 64 * 32; idx += 256) {
            int row = idx >> 5, d4 = idx & 31;
            int k = d4 * 4;
            int gr = kt0 + row;
            float4 v = (gr < KV_LEN)
                ? *(const float4*)(Kc + (size_t)gr * DIM + head * HDIM + k)
                : make_float4(0.f, 0.f, 0.f, 0.f);
            int ks = k >> 3;
            int reg = (k & 4) ? 1 : 0;
            int nt = row >> 3;
            int ln = (row & 7) * 4;
            uint32_t* base = KB + ks * KB_KS + nt * 64;
            base[(ln + 0) * 2 + reg] = f2tf32(v.x);
            base[(ln + 1) * 2 + reg] = f2tf32(v.y);
            base[(ln + 2) * 2 + reg] = f2tf32(v.z);
            base[(ln + 3) * 2 + reg] = f2tf32(v.w);
        }
        // ---- V tile -> VB fragments (2-way max) ----
        for (int idx = tid; idx < 64 * 32; idx += 256) {
            int row = idx >> 5, d4 = idx & 31;
            int d = d4 * 4;
            int gr = kt0 + row;
            float4 v = (gr < KV_LEN)
                ? *(const float4*)(Vc + (size_t)gr * DIM + head * HDIM + d)
                : make_float4(0.f, 0.f, 0.f, 0.f);
            int ks = row >> 3;
            int reg = (row & 4) ? 1 : 0;
            int nt = d >> 3;
            int t0 = row & 3;
            uint32_t* base = VB + ks * VB_KS + nt * VB_NT;
            base[(((d & 7) + 0) * 4 + t0) * 2 + reg] = f2tf32(v.x);
            base[(((d & 7) + 1) * 4 + t0) * 2 + reg] = f2tf32(v.y);
            base[(((d & 7) + 2) * 4 + t0) * 2 + reg] = f2tf32(v.z);
            base[(((d & 7) + 3) * 4 + t0) * 2 + reg] = f2tf32(v.w);
        }
        __syncthreads();

        // ---- S = Q K^T ----
        float Sc[4][4];
        #pragma unroll
        for (int i = 0; i < 4; i++)
            #pragma unroll
            for (int j = 0; j < 4; j++) Sc[i][j] = 0.f;

        #pragma unroll
        for (int ks = 0; ks < 16; ks++) {
            uint4 a = *(const uint4*)(QA + ks * QA_KS + mi * 128 + lane * 4);
            #pragma unroll
            for (int ntl = 0; ntl < 4; ntl++) {
                int nt = ni * 4 + ntl;
                uint2 b = *(const uint2*)(KB + ks * KB_KS + nt * 64 + lane * 2);
                mma_tf32(Sc[ntl][0], Sc[ntl][1], Sc[ntl][2], Sc[ntl][3],
                         a.x, a.y, a.z, a.w, b.x, b.y);
            }
        }

        // scale + mask
        float pm0 = -INFINITY, pm1 = -INFINITY;
        #pragma unroll
        for (int ntl = 0; ntl < 4; ntl++) {
            int cbase = ni * 32 + ntl * 8 + 2 * t4;
            #pragma unroll
            for (int j = 0; j < 4; j++) {
                int c = cbase + (j & 1);
                bool valid = (kt0 + c) < KV_LEN;
                Sc[ntl][j] = valid ? Sc[ntl][j] * SCALE : -1e30f;
            }
            pm0 = fmaxf(pm0, fmaxf(Sc[ntl][0], Sc[ntl][1]));
            pm1 = fmaxf(pm1, fmaxf(Sc[ntl][2], Sc[ntl][3]));
        }
        pm0 = fmaxf(pm0, __shfl_xor_sync(0xffffffffu, pm0, 1));
        pm0 = fmaxf(pm0, __shfl_xor_sync(0xffffffffu, pm0, 2));
        pm1 = fmaxf(pm1, __shfl_xor_sync(0xffffffffu, pm1, 1));
        pm1 = fmaxf(pm1, __shfl_xor_sync(0xffffffffu, pm1, 2));
        if (t4 == 0) {
            xmax[ni * 64 + 16 * mi + g]     = pm0;
            xmax[ni * 64 + 16 * mi + g + 8] = pm1;
        }
        __syncthreads();   // xmax visible; KB reads done -> PA writes safe

        int r0 = 16 * mi + g, r1 = r0 + 8;
        float m0n = fmaxf(m0, fmaxf(xmax[r0], xmax[64 + r0]));
        float m1n = fmaxf(m1, fmaxf(xmax[r1], xmax[64 + r1]));

        float s0 = 0.f, s1 = 0.f;
        #pragma unroll
        for (int ntl = 0; ntl < 4; ntl++) {
            int ks = ni * 4 + ntl;
            uint32_t* base = PA + ks * PA_KS + mi * 128;
            #pragma unroll
            for (int j = 0; j < 4; j++) {
                float e = __expf(Sc[ntl][j] - ((j < 2) ? m0n : m1n));
                if (j < 2) s0 += e; else s1 += e;
                int c = 2 * t4 + (j & 1);               // col within 8-block
                int rl = (j < 2) ? g : (g + 8);
                int reg = ((rl >= 8) ? 1 : 0) + ((c >= 4) ? 2 : 0);
                base[((rl & 7) * 4 + (c & 3)) * 4 + reg] = f2tf32(e);
            }
        }
        s0 += __shfl_xor_sync(0xffffffffu, s0, 1);
        s0 += __shfl_xor_sync(0xffffffffu, s0, 2);
        s1 += __shfl_xor_sync(0xffffffffu, s1, 1);
        s1 += __shfl_xor_sync(0xffffffffu, s1, 2);
        if (t4 == 0) {
            xsum[ni * 64 + r0] = s0;
            xsum[ni * 64 + r1] = s1;
        }
        __syncthreads();

        float alpha0 = __expf(m0 - m0n);
        float alpha1 = __expf(m1 - m1n);
        l0 = l0 * alpha0 + xsum[r0] + xsum[64 + r0];
        l1 = l1 * alpha1 + xsum[r1] + xsum[64 + r1];
        m0 = m0n; m1 = m1n;

        #pragma unroll
        for (int ntl = 0; ntl < 8; ntl++) {
            O[ntl][0] *= alpha0; O[ntl][1] *= alpha0;
            O[ntl][2] *= alpha1; O[ntl][3] *= alpha1;
        }

        // ---- O += P V ----
        #pragma unroll
        for (int ks = 0; ks < 8; ks++) {
            uint4 a = *(const uint4*)(PA + ks * PA_KS + mi * 128 + lane * 4);
            #pragma unroll
            for (int ntl = 0; ntl < 8; ntl++) {
                int nt = ni * 8 + ntl;
                uint2 b = *(const uint2*)(VB + ks * VB_KS + nt * VB_NT + lane * 2);
                mma_tf32(O[ntl][0], O[ntl][1], O[ntl][2], O[ntl][3],
                         a.x, a.y, a.z, a.w, b.x, b.y);
            }
        }
    }

    // ---- finalize ----
    float inv0 = 1.f / l0, inv1 = 1.f / l1;
    int gr0 = q0 + 16 * mi + g;
    int gr1 = gr0 + 8;
    #pragma unroll
    for (int ntl = 0; ntl < 8; ntl++) {
        int c = ni * 64 + ntl * 8 + 2 * t4;
        if (gr0 < S_LEN) {
            float2 o0 = make_float2(O[ntl][0] * inv0, O[ntl][1] * inv0);
            *(float2*)(Oo + (size_t)gr0 * DIM + head * HDIM + c) = o0;
        }
        if (gr1 < S_LEN) {
            float2 o1 = make_float2(O[ntl][2] * inv1, O[ntl][3] * inv1);
            *(float2*)(Oo + (size_t)gr1 * DIM + head * HDIM + c) = o1;
        }
    }
}

// ---------------- launch -----------------------------------------------------
extern "C" void kernel_launch(void* const* d_in, const int* in_sizes, int n_in,
                              void* d_out, int out_size)
{
    const float* x  = (const float*)d_in[0];
    const float* Wq = (const float*)d_in[1];
    const float* bq = (const float*)d_in[2];
    const float* Wk = (const float*)d_in[3];
    const float* bk = (const float*)d_in[4];
    const float* Wv = (const float*)d_in[5];
    const float* bv = (const float*)d_in[6];
    const float* Wo = (const float*)d_in[7];
    const float* bo = (const float*)d_in[8];
    const float* gq = (const float*)d_in[9];
    const float* gk = (const float*)d_in[10];
    const float* ck = (const float*)d_in[11];
    const float* cv = (const float*)d_in[12];
    const float* fc = (const float*)d_in[13];
    const float* fs = (const float*)d_in[14];
    float* out = (float*)d_out;

    float *qb, *kb, *vb, *kc, *vc, *ob;
    cudaGetSymbolAddress((void**)&qb, d_qbuf);
    cudaGetSymbolAddress((void**)&kb, d_kbuf);
    cudaGetSymbolAddress((void**)&vb, d_vbuf);
    cudaGetSymbolAddress((void**)&kc, d_kc);
    cudaGetSymbolAddress((void**)&vc, d_vc);
    cudaGetSymbolAddress((void**)&ob, d_obuf);

    dim3 gg(DIM / 64, (S_LEN + 63) / 64);   // 24 x 25

    sgemm_bias<<<gg, 256>>>(x, Wq, bq, qb, S_LEN);
    sgemm_bias<<<gg, 256>>>(x, Wk, bk, kb, S_LEN);
    sgemm_bias<<<gg, 256>>>(x, Wv, bv, vb, S_LEN);

    rmsnorm_rope_q<<<S_LEN, 256>>>(qb, gq, fc, fs);
    rmsnorm_plain<<<S_LEN, 256>>>(kb, gk);

    build_kv<<<KV_LEN, 256>>>(ck, cv, kb, vb, kc, vc, fc, fs);

    int attn_smem = ATTN_SMEM_U32 * (int)sizeof(uint32_t);
    cudaFuncSetAttribute(attn_tc, cudaFuncAttributeMaxDynamicSharedMemorySize, attn_smem);
    attn_tc<<<dim3((S_LEN + 63) / 64, NHEADS), 256, attn_smem>>>(qb, kc, vc, ob);

    sgemm_bias<<<gg, 256>>>(ob, Wo, bo, out, S_LEN);
}

// round 4
// speedup vs baseline: 2.2820x; 1.0757x over previous
#include <cuda_runtime.h>
#include <math.h>
#include <stdint.h>

#define DIM      1536
#define NHEADS   12
#define HDIM     128
#define S_LEN    1560
#define KV_LEN   9360
#define FT       22
#define FSZ      21
#define WW       52
#define ALPHA_F  0.999f
#define BETA_F   0.001f
#define EPS_F    1e-6f
#define Q_FRAME  5
#define SCALE    0.08838834764831843f   /* 1/sqrt(128) */

// ---------------- scratch (device globals; no allocations allowed) ----------
__device__ float d_qbuf[S_LEN * DIM];
__device__ float d_kbuf[S_LEN * DIM];
__device__ float d_vbuf[S_LEN * DIM];
__device__ float d_kc[KV_LEN * DIM];
__device__ float d_vc[KV_LEN * DIM];
__device__ float d_obuf[S_LEN * DIM];

__device__ __forceinline__ uint32_t f2tf32(float f) {
    uint32_t r;
    asm("cvt.rna.tf32.f32 %0, %1;" : "=r"(r) : "f"(f));
    return r;
}
__device__ __forceinline__ float tf32r(float f) {
    uint32_t r = f2tf32(f);
    return __uint_as_float(r);
}

__device__ __forceinline__ void mma_tf32(
    float& c0, float& c1, float& c2, float& c3,
    uint32_t a0, uint32_t a1, uint32_t a2, uint32_t a3,
    uint32_t b0, uint32_t b1)
{
    asm volatile(
        "mma.sync.aligned.m16n8k8.row.col.f32.tf32.tf32.f32 "
        "{%0,%1,%2,%3},{%4,%5,%6,%7},{%8,%9},{%0,%1,%2,%3};"
        : "+f"(c0), "+f"(c1), "+f"(c2), "+f"(c3)
        : "r"(a0), "r"(a1), "r"(a2), "r"(a3), "r"(b0), "r"(b1));
}

// ============ tf32 3x-split GEMM: C[M,1536] = A @ B + bias (fp32-accurate) ===
// CTA tile 128x64, k-slice 16. 8 warps: wm = wrp&3 (32-row strip), wn = wrp>>2
// (32-col strip). Warp tile 32x32 -> mfrag 2 x nfrag 4.
// smem: Ah/Al [128][20] (pad->conflict-free frag loads), Bh/Bl [16][72].
__global__ __launch_bounds__(256, 2) void gemm_tf32_bias(
    const float* __restrict__ A, const float* __restrict__ B,
    const float* __restrict__ bias, float* __restrict__ C, int M)
{
    __shared__ float Ah[128 * 20], Al[128 * 20];
    __shared__ float Bh[16 * 72],  Bl[16 * 72];

    const int tid  = threadIdx.x;
    const int lane = tid & 31, wrp = tid >> 5;
    const int wm = wrp & 3, wn = wrp >> 2;
    const int g = lane >> 2, t4 = lane & 3;
    const int bm = blockIdx.y * 128, bn = blockIdx.x * 64;

    float acc[2][4][4];
    #pragma unroll
    for (int i = 0; i < 2; i++)
        #pragma unroll
        for (int j = 0; j < 4; j++)
            #pragma unroll
            for (int r = 0; r < 4; r++) acc[i][j][r] = 0.f;

    const int ar  = tid >> 2;        // 0..63 base row idx (2 iters -> 128)
    const int ak4 = tid & 3;         // float4 along k
    const int bkr = tid >> 4;        // 0..15 k row of B tile
    const int bc4 = tid & 15;        // float4 along n

    for (int k0 = 0; k0 < DIM; k0 += 16) {
        __syncthreads();
        // ---- A tile 128x16 -> hi/lo ----
        #pragma unroll
        for (int it = 0; it < 2; it++) {
            int r = ar + it * 64;
            int gr = bm + r;
            float4 v = (gr < M)
                ? *(const float4*)(A + (size_t)gr * DIM + k0 + ak4 * 4)
                : make_float4(0.f, 0.f, 0.f, 0.f);
            float4 h, l;
            h.x = tf32r(v.x); l.x = tf32r(v.x - h.x);
            h.y = tf32r(v.y); l.y = tf32r(v.y - h.y);
            h.z = tf32r(v.z); l.z = tf32r(v.z - h.z);
            h.w = tf32r(v.w); l.w = tf32r(v.w - h.w);
            *(float4*)&Ah[r * 20 + ak4 * 4] = h;
            *(float4*)&Al[r * 20 + ak4 * 4] = l;
        }
        // ---- B tile 16x64 -> hi/lo ----
        {
            float4 v = *(const float4*)(B + (size_t)(k0 + bkr) * DIM + bn + bc4 * 4);
            float4 h, l;
            h.x = tf32r(v.x); l.x = tf32r(v.x - h.x);
            h.y = tf32r(v.y); l.y = tf32r(v.y - h.y);
            h.z = tf32r(v.z); l.z = tf32r(v.z - h.z);
            h.w = tf32r(v.w); l.w = tf32r(v.w - h.w);
            *(float4*)&Bh[bkr * 72 + bc4 * 4] = h;
            *(float4*)&Bl[bkr * 72 + bc4 * 4] = l;
        }
        __syncthreads();

        #pragma unroll
        for (int ks = 0; ks < 2; ks++) {
            uint32_t ah[2][4], al[2][4];
            #pragma unroll
            for (int mf = 0; mf < 2; mf++) {
                int r0 = wm * 32 + mf * 16 + g;
                int cb = ks * 8 + t4;
                ah[mf][0] = __float_as_uint(Ah[r0 * 20 + cb]);
                ah[mf][1] = __float_as_uint(Ah[(r0 + 8) * 20 + cb]);
                ah[mf][2] = __float_as_uint(Ah[r0 * 20 + cb + 4]);
                ah[mf][3] = __float_as_uint(Ah[(r0 + 8) * 20 + cb + 4]);
                al[mf][0] = __float_as_uint(Al[r0 * 20 + cb]);
                al[mf][1] = __float_as_uint(Al[(r0 + 8) * 20 + cb]);
                al[mf][2] = __float_as_uint(Al[r0 * 20 + cb + 4]);
                al[mf][3] = __float_as_uint(Al[(r0 + 8) * 20 + cb + 4]);
            }
            uint32_t bh[4][2], bl[4][2];
            #pragma unroll
            for (int nf = 0; nf < 4; nf++) {
                int cb = wn * 32 + nf * 8 + g;
                bh[nf][0] = __float_as_uint(Bh[(ks * 8 + t4) * 72 + cb]);
                bh[nf][1] = __float_as_uint(Bh[(ks * 8 + t4 + 4) * 72 + cb]);
                bl[nf][0] = __float_as_uint(Bl[(ks * 8 + t4) * 72 + cb]);
                bl[nf][1] = __float_as_uint(Bl[(ks * 8 + t4 + 4) * 72 + cb]);
            }
            #pragma unroll
            for (int mf = 0; mf < 2; mf++)
                #pragma unroll
                for (int nf = 0; nf < 4; nf++) {
                    mma_tf32(acc[mf][nf][0], acc[mf][nf][1], acc[mf][nf][2], acc[mf][nf][3],
                             ah[mf][0], ah[mf][1], ah[mf][2], ah[mf][3],
                             bh[nf][0], bh[nf][1]);
                    mma_tf32(acc[mf][nf][0], acc[mf][nf][1], acc[mf][nf][2], acc[mf][nf][3],
                             al[mf][0], al[mf][1], al[mf][2], al[mf][3],
                             bh[nf][0], bh[nf][1]);
                    mma_tf32(acc[mf][nf][0], acc[mf][nf][1], acc[mf][nf][2], acc[mf][nf][3],
                             ah[mf][0], ah[mf][1], ah[mf][2], ah[mf][3],
                             bl[nf][0], bl[nf][1]);
                }
        }
    }

    // ---- epilogue ----
    #pragma unroll
    for (int nf = 0; nf < 4; nf++) {
        int col = bn + wn * 32 + nf * 8 + 2 * t4;
        float2 bv = *(const float2*)(bias + col);
        #pragma unroll
        for (int mf = 0; mf < 2; mf++) {
            int r0 = bm + wm * 32 + mf * 16 + g;
            if (r0 < M) {
                float2 o = make_float2(acc[mf][nf][0] + bv.x, acc[mf][nf][1] + bv.y);
                *(float2*)(C + (size_t)r0 * DIM + col) = o;
            }
            if (r0 + 8 < M) {
                float2 o = make_float2(acc[mf][nf][2] + bv.x, acc[mf][nf][3] + bv.y);
                *(float2*)(C + (size_t)(r0 + 8) * DIM + col) = o;
            }
        }
    }
}

// ---------------- rmsnorm (+rope for q) ------------------------------------
__device__ __forceinline__ float block_rms_scale(const float* row, float* red)
{
    float ss = 0.f;
    for (int i = threadIdx.x; i < DIM; i += 256) { float v = row[i]; ss += v * v; }
    #pragma unroll
    for (int o = 16; o; o >>= 1) ss += __shfl_xor_sync(0xffffffffu, ss, o);
    if ((threadIdx.x & 31) == 0) red[threadIdx.x >> 5] = ss;
    __syncthreads();
    if (threadIdx.x == 0) {
        float tot = 0.f;
        #pragma unroll
        for (int i = 0; i < 8; i++) tot += red[i];
        red[0] = rsqrtf(tot / (float)DIM + EPS_F);
    }
    __syncthreads();
    return red[0];
}

// q output is stored pre-rounded to tf32 (consumed only by tensor-core attn)
__global__ __launch_bounds__(256) void rmsnorm_rope_q(
    float* __restrict__ q, const float* __restrict__ g,
    const float* __restrict__ fc, const float* __restrict__ fs)
{
    __shared__ float red[8];
    int t = blockIdx.x;
    float* row = q + (size_t)t * DIM;
    float scale = block_rms_scale(row, red);
    int h = t / WW, w = t % WW;
    for (int p = threadIdx.x; p < DIM / 2; p += 256) {
        int c = p & 63;
        int ridx = (c < FT) ? Q_FRAME : ((c < FT + FSZ) ? h : w);
        float cs = fc[ridx * 64 + c], sn = fs[ridx * 64 + c];
        float a = row[2*p]   * scale * g[2*p];
        float b = row[2*p+1] * scale * g[2*p+1];
        row[2*p]   = tf32r(a * cs - b * sn);
        row[2*p+1] = tf32r(a * sn + b * cs);
    }
}

__global__ __launch_bounds__(256) void rmsnorm_plain(
    float* __restrict__ k, const float* __restrict__ g)
{
    __shared__ float red[8];
    int t = blockIdx.x;
    float* row = k + (size_t)t * DIM;
    float scale = block_rms_scale(row, red);
    for (int i = threadIdx.x; i < DIM; i += 256)
        row[i] = row[i] * scale * g[i];
}

// ---------------- build combined KV (gather + blend + rope; tf32-rounded) ---
__global__ __launch_bounds__(256) void build_kv(
    const float* __restrict__ ck, const float* __restrict__ cv,
    const float* __restrict__ kn, const float* __restrict__ vn,
    float* __restrict__ kc, float* __restrict__ vc,
    const float* __restrict__ fc, const float* __restrict__ fs)
{
    int r = blockIdx.x;
    const float *sk, *sv, *sk2 = nullptr, *sv2 = nullptr;
    if (r < 1560) {
        sk  = ck + (size_t)r * DIM;          sv  = cv + (size_t)r * DIM;
        sk2 = ck + (size_t)(9360 + r) * DIM; sv2 = cv + (size_t)(9360 + r) * DIM;
    } else if (r < 7800) {
        sk = ck + (size_t)(r + 3120) * DIM;  sv = cv + (size_t)(r + 3120) * DIM;
    } else {
        sk = kn + (size_t)(r - 7800) * DIM;  sv = vn + (size_t)(r - 7800) * DIM;
    }
    float* vd = vc + (size_t)r * DIM;
    for (int i = threadIdx.x; i < DIM; i += 256) {
        float v = sv[i];
        if (sv2) v = ALPHA_F * v + BETA_F * sv2[i];
        vd[i] = tf32r(v);
    }
    int fr = r / 1560, p = r % 1560, h = p / WW, w = p % WW;
    float* kd = kc + (size_t)r * DIM;
    for (int pp = threadIdx.x; pp < DIM / 2; pp += 256) {
        int c = pp & 63;
        int ridx = (c < FT) ? fr : ((c < FT + FSZ) ? h : w);
        float cs = fc[ridx * 64 + c], sn = fs[ridx * 64 + c];
        float a = sk[2*pp], b = sk[2*pp+1];
        if (sk2) { a = ALPHA_F*a + BETA_F*sk2[2*pp]; b = ALPHA_F*b + BETA_F*sk2[2*pp+1]; }
        kd[2*pp]   = tf32r(a * cs - b * sn);
        kd[2*pp+1] = tf32r(a * sn + b * cs);
    }
}

// ================== tf32 tensor-core flash attention =========================
// Inputs (Q, Kc, Vc) arrive pre-rounded to tf32 -> loads copy raw bits.
#define QA_KS 516
#define KB_KS 514
#define PA_KS 516
#define VB_NT 66
#define VB_KS (16 * VB_NT)

#define QA_OFF 0
#define KB_OFF (16 * QA_KS)
#define PA_OFF KB_OFF
#define VB_OFF (KB_OFF + 16 * KB_KS)
#define XM_OFF (VB_OFF + 8 * VB_KS)
#define XS_OFF (XM_OFF + 128)
#define ATTN_SMEM_U32 (XS_OFF + 128)

__global__ __launch_bounds__(256, 2) void attn_tc(
    const float* __restrict__ Q, const float* __restrict__ Kc,
    const float* __restrict__ Vc, float* __restrict__ Oo)
{
    extern __shared__ uint32_t sm[];
    uint32_t* QA = sm + QA_OFF;
    uint32_t* KB = sm + KB_OFF;
    uint32_t* PA = sm + PA_OFF;
    uint32_t* VB = sm + VB_OFF;
    float* xmax  = (float*)(sm + XM_OFF);
    float* xsum  = (float*)(sm + XS_OFF);

    const int q0   = blockIdx.x * 64;
    const int head = blockIdx.y;
    const int tid  = threadIdx.x;
    const int lane = tid & 31;
    const int wrp  = tid >> 5;
    const int mi   = wrp & 3;
    const int ni   = wrp >> 2;
    const int g    = lane >> 2;
    const int t4   = lane & 3;

    for (int idx = tid; idx < 64 * 32; idx += 256) {
        int r = idx >> 5, d4 = idx & 31;
        int k = d4 * 4;
        int gq = q0 + r;
        float4 v = (gq < S_LEN)
            ? *(const float4*)(Q + (size_t)gq * DIM + head * HDIM + k)
            : make_float4(0.f, 0.f, 0.f, 0.f);
        int ks = k >> 3;
        int khi = (k & 4) ? 2 : 0;
        int rl = r & 15;
        int reg = ((rl >= 8) ? 1 : 0) + khi;
        int ln = (rl & 7) * 4;
        uint32_t* base = QA + ks * QA_KS + (r >> 4) * 128;
        base[(ln + 0) * 4 + reg] = __float_as_uint(v.x);
        base[(ln + 1) * 4 + reg] = __float_as_uint(v.y);
        base[(ln + 2) * 4 + reg] = __float_as_uint(v.z);
        base[(ln + 3) * 4 + reg] = __float_as_uint(v.w);
    }

    float m0 = -INFINITY, m1 = -INFINITY;
    float l0 = 0.f, l1 = 0.f;
    float O[8][4];
    #pragma unroll
    for (int i = 0; i < 8; i++)
        #pragma unroll
        for (int j = 0; j < 4; j++) O[i][j] = 0.f;

    const int nkt = (KV_LEN + 63) / 64;
    for (int kt = 0; kt < nkt; kt++) {
        int kt0 = kt * 64;
        __syncthreads();

        for (int idx = tid; idx < 64 * 32; idx += 256) {
            int row = idx >> 5, d4 = idx & 31;
            int k = d4 * 4;
            int gr = kt0 + row;
            float4 v = (gr < KV_LEN)
                ? *(const float4*)(Kc + (size_t)gr * DIM + head * HDIM + k)
                : make_float4(0.f, 0.f, 0.f, 0.f);
            int ks = k >> 3;
            int reg = (k & 4) ? 1 : 0;
            int nt = row >> 3;
            int ln = (row & 7) * 4;
            uint32_t* base = KB + ks * KB_KS + nt * 64;
            base[(ln + 0) * 2 + reg] = __float_as_uint(v.x);
            base[(ln + 1) * 2 + reg] = __float_as_uint(v.y);
            base[(ln + 2) * 2 + reg] = __float_as_uint(v.z);
            base[(ln + 3) * 2 + reg] = __float_as_uint(v.w);
        }
        for (int idx = tid; idx < 64 * 32; idx += 256) {
            int row = idx >> 5, d4 = idx & 31;
            int d = d4 * 4;
            int gr = kt0 + row;
            float4 v = (gr < KV_LEN)
                ? *(const float4*)(Vc + (size_t)gr * DIM + head * HDIM + d)
                : make_float4(0.f, 0.f, 0.f, 0.f);
            int ks = row >> 3;
            int reg = (row & 4) ? 1 : 0;
            int nt = d >> 3;
            int t0 = row & 3;
            uint32_t* base = VB + ks * VB_KS + nt * VB_NT;
            base[(((d & 7) + 0) * 4 + t0) * 2 + reg] = __float_as_uint(v.x);
            base[(((d & 7) + 1) * 4 + t0) * 2 + reg] = __float_as_uint(v.y);
            base[(((d & 7) + 2) * 4 + t0) * 2 + reg] = __float_as_uint(v.z);
            base[(((d & 7) + 3) * 4 + t0) * 2 + reg] = __float_as_uint(v.w);
        }
        __syncthreads();

        float Sc[4][4];
        #pragma unroll
        for (int i = 0; i < 4; i++)
            #pragma unroll
            for (int j = 0; j < 4; j++) Sc[i][j] = 0.f;

        #pragma unroll
        for (int ks = 0; ks < 16; ks++) {
            uint4 a = *(const uint4*)(QA + ks * QA_KS + mi * 128 + lane * 4);
            #pragma unroll
            for (int ntl = 0; ntl < 4; ntl++) {
                int nt = ni * 4 + ntl;
                uint2 b = *(const uint2*)(KB + ks * KB_KS + nt * 64 + lane * 2);
                mma_tf32(Sc[ntl][0], Sc[ntl][1], Sc[ntl][2], Sc[ntl][3],
                         a.x, a.y, a.z, a.w, b.x, b.y);
            }
        }

        float pm0 = -INFINITY, pm1 = -INFINITY;
        #pragma unroll
        for (int ntl = 0; ntl < 4; ntl++) {
            int cbase = ni * 32 + ntl * 8 + 2 * t4;
            #pragma unroll
            for (int j = 0; j < 4; j++) {
                int c = cbase + (j & 1);
                bool valid = (kt0 + c) < KV_LEN;
                Sc[ntl][j] = valid ? Sc[ntl][j] * SCALE : -1e30f;
            }
            pm0 = fmaxf(pm0, fmaxf(Sc[ntl][0], Sc[ntl][1]));
            pm1 = fmaxf(pm1, fmaxf(Sc[ntl][2], Sc[ntl][3]));
        }
        pm0 = fmaxf(pm0, __shfl_xor_sync(0xffffffffu, pm0, 1));
        pm0 = fmaxf(pm0, __shfl_xor_sync(0xffffffffu, pm0, 2));
        pm1 = fmaxf(pm1, __shfl_xor_sync(0xffffffffu, pm1, 1));
        pm1 = fmaxf(pm1, __shfl_xor_sync(0xffffffffu, pm1, 2));
        if (t4 == 0) {
            xmax[ni * 64 + 16 * mi + g]     = pm0;
            xmax[ni * 64 + 16 * mi + g + 8] = pm1;
        }
        __syncthreads();

        int r0 = 16 * mi + g, r1 = r0 + 8;
        float m0n = fmaxf(m0, fmaxf(xmax[r0], xmax[64 + r0]));
        float m1n = fmaxf(m1, fmaxf(xmax[r1], xmax[64 + r1]));

        float s0 = 0.f, s1 = 0.f;
        #pragma unroll
        for (int ntl = 0; ntl < 4; ntl++) {
            int ks = ni * 4 + ntl;
            uint32_t* base = PA + ks * PA_KS + mi * 128;
            #pragma unroll
            for (int j = 0; j < 4; j++) {
                float e = __expf(Sc[ntl][j] - ((j < 2) ? m0n : m1n));
                if (j < 2) s0 += e; else s1 += e;
                int c = 2 * t4 + (j & 1);
                int rl = (j < 2) ? g : (g + 8);
                int reg = ((rl >= 8) ? 1 : 0) + ((c >= 4) ? 2 : 0);
                base[((rl & 7) * 4 + (c & 3)) * 4 + reg] = f2tf32(e);
            }
        }
        s0 += __shfl_xor_sync(0xffffffffu, s0, 1);
        s0 += __shfl_xor_sync(0xffffffffu, s0, 2);
        s1 += __shfl_xor_sync(0xffffffffu, s1, 1);
        s1 += __shfl_xor_sync(0xffffffffu, s1, 2);
        if (t4 == 0) {
            xsum[ni * 64 + r0] = s0;
            xsum[ni * 64 + r1] = s1;
        }
        __syncthreads();

        float alpha0 = __expf(m0 - m0n);
        float alpha1 = __expf(m1 - m1n);
        l0 = l0 * alpha0 + xsum[r0] + xsum[64 + r0];
        l1 = l1 * alpha1 + xsum[r1] + xsum[64 + r1];
        m0 = m0n; m1 = m1n;

        #pragma unroll
        for (int ntl = 0; ntl < 8; ntl++) {
            O[ntl][0] *= alpha0; O[ntl][1] *= alpha0;
            O[ntl][2] *= alpha1; O[ntl][3] *= alpha1;
        }

        #pragma unroll
        for (int ks = 0; ks < 8; ks++) {
            uint4 a = *(const uint4*)(PA + ks * PA_KS + mi * 128 + lane * 4);
            #pragma unroll
            for (int ntl = 0; ntl < 8; ntl++) {
                int nt = ni * 8 + ntl;
                uint2 b = *(const uint2*)(VB + ks * VB_KS + nt * VB_NT + lane * 2);
                mma_tf32(O[ntl][0], O[ntl][1], O[ntl][2], O[ntl][3],
                         a.x, a.y, a.z, a.w, b.x, b.y);
            }
        }
    }

    float inv0 = 1.f / l0, inv1 = 1.f / l1;
    int gr0 = q0 + 16 * mi + g;
    int gr1 = gr0 + 8;
    #pragma unroll
    for (int ntl = 0; ntl < 8; ntl++) {
        int c = ni * 64 + ntl * 8 + 2 * t4;
        if (gr0 < S_LEN) {
            float2 o0 = make_float2(O[ntl][0] * inv0, O[ntl][1] * inv0);
            *(float2*)(Oo + (size_t)gr0 * DIM + head * HDIM + c) = o0;
        }
        if (gr1 < S_LEN) {
            float2 o1 = make_float2(O[ntl][2] * inv1, O[ntl][3] * inv1);
            *(float2*)(Oo + (size_t)gr1 * DIM + head * HDIM + c) = o1;
        }
    }
}

// ---------------- launch -----------------------------------------------------
extern "C" void kernel_launch(void* const* d_in, const int* in_sizes, int n_in,
                              void* d_out, int out_size)
{
    const float* x  = (const float*)d_in[0];
    const float* Wq = (const float*)d_in[1];
    const float* bq = (const float*)d_in[2];
    const float* Wk = (const float*)d_in[3];
    const float* bk = (const float*)d_in[4];
    const float* Wv = (const float*)d_in[5];
    const float* bv = (const float*)d_in[6];
    const float* Wo = (const float*)d_in[7];
    const float* bo = (const float*)d_in[8];
    const float* gq = (const float*)d_in[9];
    const float* gk = (const float*)d_in[10];
    const float* ck = (const float*)d_in[11];
    const float* cv = (const float*)d_in[12];
    const float* fc = (const float*)d_in[13];
    const float* fs = (const float*)d_in[14];
    float* out = (float*)d_out;

    float *qb, *kb, *vb, *kc, *vc, *ob;
    cudaGetSymbolAddress((void**)&qb, d_qbuf);
    cudaGetSymbolAddress((void**)&kb, d_kbuf);
    cudaGetSymbolAddress((void**)&vb, d_vbuf);
    cudaGetSymbolAddress((void**)&kc, d_kc);
    cudaGetSymbolAddress((void**)&vc, d_vc);
    cudaGetSymbolAddress((void**)&ob, d_obuf);

    dim3 gg(DIM / 64, (S_LEN + 127) / 128);   // 24 x 13

    gemm_tf32_bias<<<gg, 256>>>(x, Wq, bq, qb, S_LEN);
    gemm_tf32_bias<<<gg, 256>>>(x, Wk, bk, kb, S_LEN);
    gemm_tf32_bias<<<gg, 256>>>(x, Wv, bv, vb, S_LEN);

    rmsnorm_rope_q<<<S_LEN, 256>>>(qb, gq, fc, fs);
    rmsnorm_plain<<<S_LEN, 256>>>(kb, gk);

    build_kv<<<KV_LEN, 256>>>(ck, cv, kb, vb, kc, vc, fc, fs);

    int attn_smem = ATTN_SMEM_U32 * (int)sizeof(uint32_t);
    cudaFuncSetAttribute(attn_tc, cudaFuncAttributeMaxDynamicSharedMemorySize, attn_smem);
    attn_tc<<<dim3((S_LEN + 63) / 64, NHEADS), 256, attn_smem>>>(qb, kc, vc, ob);

    gemm_tf32_bias<<<gg, 256>>>(ob, Wo, bo, out, S_LEN);
}

// round 5
// speedup vs baseline: 2.8531x; 1.2503x over previous
#include <cuda_runtime.h>
#include <cuda_bf16.h>
#include <math.h>
#include <stdint.h>

#define DIM      1536
#define NHEADS   12
#define HDIM     128
#define S_LEN    1560
#define KV_LEN   9360
#define FT       22
#define FSZ      21
#define WW       52
#define ALPHA_F  0.999f
#define BETA_F   0.001f
#define EPS_F    1e-6f
#define Q_FRAME  5
#define SCALE    0.08838834764831843f   /* 1/sqrt(128) */

// ---------------- scratch (device globals; no allocations allowed) ----------
__device__ float d_qbuf[S_LEN * DIM];
__device__ float d_kbuf[S_LEN * DIM];
__device__ float d_vbuf[S_LEN * DIM];
__device__ float d_kc[KV_LEN * DIM];
__device__ float d_vc[KV_LEN * DIM];
__device__ float d_obuf[S_LEN * DIM];

__device__ __forceinline__ uint32_t f2tf32(float f) {
    uint32_t r;
    asm("cvt.rna.tf32.f32 %0, %1;" : "=r"(r) : "f"(f));
    return r;
}
__device__ __forceinline__ float tf32r(float f) {
    uint32_t r = f2tf32(f);
    return __uint_as_float(r);
}
__device__ __forceinline__ float bfr(float v) {
    return __bfloat162float(__float2bfloat16_rn(v));
}
__device__ __forceinline__ uint32_t pkbf2(float lo, float hi) {
    __nv_bfloat162 t = __floats2bfloat162_rn(lo, hi);
    return *reinterpret_cast<uint32_t*>(&t);
}

__device__ __forceinline__ void mma_tf32(
    float& c0, float& c1, float& c2, float& c3,
    uint32_t a0, uint32_t a1, uint32_t a2, uint32_t a3,
    uint32_t b0, uint32_t b1)
{
    asm volatile(
        "mma.sync.aligned.m16n8k8.row.col.f32.tf32.tf32.f32 "
        "{%0,%1,%2,%3},{%4,%5,%6,%7},{%8,%9},{%0,%1,%2,%3};"
        : "+f"(c0), "+f"(c1), "+f"(c2), "+f"(c3)
        : "r"(a0), "r"(a1), "r"(a2), "r"(a3), "r"(b0), "r"(b1));
}

__device__ __forceinline__ void mma_bf16(
    float* c, const uint4& a, const uint2& b)
{
    asm volatile(
        "mma.sync.aligned.m16n8k16.row.col.f32.bf16.bf16.f32 "
        "{%0,%1,%2,%3},{%4,%5,%6,%7},{%8,%9},{%0,%1,%2,%3};"
        : "+f"(c[0]), "+f"(c[1]), "+f"(c[2]), "+f"(c[3])
        : "r"(a.x), "r"(a.y), "r"(a.z), "r"(a.w), "r"(b.x), "r"(b.y));
}

// ============ bf16 3-term GEMM: C[M,1536] = A @ B + bias (fp32-accurate) ====
// CTA 128x128, BK=64, 256 thr (8 warps: wm=wrp&3 32-row strip, wn=wrp>>2
// 64-col strip). Fragment-order smem; vectorized frag loads (conflict-free).
// blockIdx.x selects among up to 3 (W,bias,C) triples (12 n-tiles each).
#define G_AH 0
#define G_AL 4096
#define G_BH 8192
#define G_BL 12416
#define G_SMEM_U32 16640   /* 66560 B */

__global__ __launch_bounds__(256, 2) void gemm3_bf16(
    const float* __restrict__ A,
    const float* __restrict__ W0, const float* __restrict__ W1, const float* __restrict__ W2,
    const float* __restrict__ b0, const float* __restrict__ b1, const float* __restrict__ b2,
    float* __restrict__ C0, float* __restrict__ C1, float* __restrict__ C2,
    int M)
{
    extern __shared__ uint32_t gsm[];
    uint32_t* AH = gsm + G_AH;
    uint32_t* AL = gsm + G_AL;
    uint32_t* BH = gsm + G_BH;
    uint32_t* BL = gsm + G_BL;

    const int sel = blockIdx.x / 12;
    const float* B    = (sel == 0) ? W0 : (sel == 1) ? W1 : W2;
    const float* bias = (sel == 0) ? b0 : (sel == 1) ? b1 : b2;
    float*       C    = (sel == 0) ? C0 : (sel == 1) ? C1 : C2;
    const int bn = (blockIdx.x - sel * 12) * 128;
    const int bm = blockIdx.y * 128;

    const int tid  = threadIdx.x;
    const int lane = tid & 31, wrp = tid >> 5;
    const int wm = wrp & 3, wn = wrp >> 2;
    const int g = lane >> 2, t4 = lane & 3;

    float acc[2][8][4];
    #pragma unroll
    for (int i = 0; i < 2; i++)
        #pragma unroll
        for (int j = 0; j < 8; j++)
            #pragma unroll
            for (int r = 0; r < 4; r++) acc[i][j][r] = 0.f;

    for (int k0 = 0; k0 < DIM; k0 += 64) {
        __syncthreads();   // previous compute done before smem overwrite
        // ---- A tile 128x64 -> hi/lo fragment-order ----
        #pragma unroll
        for (int it = 0; it < 8; it++) {
            int idx = tid + it * 256;
            int r = idx >> 4, c4 = idx & 15;
            int gr = bm + r;
            float4 v = (gr < M)
                ? *(const float4*)(A + (size_t)gr * DIM + k0 + c4 * 4)
                : make_float4(0.f, 0.f, 0.f, 0.f);
            int rl = r & 15, mtile = r >> 4;
            int ks = c4 >> 2, k8 = (c4 >> 1) & 1, t4a = (c4 & 1) * 2;
            int reg = (rl >> 3) + 2 * k8;
            int base = ks * 1024 + mtile * 128;
            int lane0 = (rl & 7) * 4 + t4a;
            float hx = bfr(v.x), hy = bfr(v.y), hz = bfr(v.z), hw = bfr(v.w);
            AH[base + lane0 * 4 + reg]       = pkbf2(hx, hy);
            AH[base + (lane0 + 1) * 4 + reg] = pkbf2(hz, hw);
            AL[base + lane0 * 4 + reg]       = pkbf2(v.x - hx, v.y - hy);
            AL[base + (lane0 + 1) * 4 + reg] = pkbf2(v.z - hz, v.w - hw);
        }
        // ---- B tile 64x128 -> hi/lo fragment-order ----
        #pragma unroll
        for (int it = 0; it < 4; it++) {
            int idx = tid + it * 256;
            int kp = idx >> 5, n4 = idx & 31;
            const float* bp = B + (size_t)(k0 + 2 * kp) * DIM + bn + n4 * 4;
            float4 u = *(const float4*)bp;
            float4 w = *(const float4*)(bp + DIM);
            int ks = kp >> 3, tb = kp & 3, reg = (kp >> 2) & 1;
            int base = ks * 1056;
            float uu[4] = {u.x, u.y, u.z, u.w};
            float ww[4] = {w.x, w.y, w.z, w.w};
            #pragma unroll
            for (int j = 0; j < 4; j++) {
                int n = n4 * 4 + j;
                int nt = n >> 3;
                int lb = (n & 7) * 4 + tb;
                float hu = bfr(uu[j]), hw2 = bfr(ww[j]);
                BH[base + nt * 66 + lb * 2 + reg] = pkbf2(hu, hw2);
                BL[base + nt * 66 + lb * 2 + reg] = pkbf2(uu[j] - hu, ww[j] - hw2);
            }
        }
        __syncthreads();

        #pragma unroll
        for (int ks = 0; ks < 4; ks++) {
            uint4 ah0 = *(const uint4*)&AH[ks * 1024 + (wm * 2 + 0) * 128 + lane * 4];
            uint4 ah1 = *(const uint4*)&AH[ks * 1024 + (wm * 2 + 1) * 128 + lane * 4];
            uint4 al0 = *(const uint4*)&AL[ks * 1024 + (wm * 2 + 0) * 128 + lane * 4];
            uint4 al1 = *(const uint4*)&AL[ks * 1024 + (wm * 2 + 1) * 128 + lane * 4];
            #pragma unroll
            for (int nf = 0; nf < 8; nf++) {
                int nt = wn * 8 + nf;
                uint2 bh = *(const uint2*)&BH[ks * 1056 + nt * 66 + lane * 2];
                uint2 bl = *(const uint2*)&BL[ks * 1056 + nt * 66 + lane * 2];
                mma_bf16(acc[0][nf], ah0, bh);
                mma_bf16(acc[1][nf], ah1, bh);
                mma_bf16(acc[0][nf], al0, bh);
                mma_bf16(acc[1][nf], al1, bh);
                mma_bf16(acc[0][nf], ah0, bl);
                mma_bf16(acc[1][nf], ah1, bl);
            }
        }
    }

    // ---- epilogue ----
    #pragma unroll
    for (int nf = 0; nf < 8; nf++) {
        int cn = bn + wn * 64 + nf * 8 + 2 * t4;
        float2 bv = *(const float2*)(bias + cn);
        #pragma unroll
        for (int mf = 0; mf < 2; mf++) {
            int r0 = bm + wm * 32 + mf * 16 + g;
            if (r0 < M) {
                float2 o = make_float2(acc[mf][nf][0] + bv.x, acc[mf][nf][1] + bv.y);
                *(float2*)(C + (size_t)r0 * DIM + cn) = o;
            }
            if (r0 + 8 < M) {
                float2 o = make_float2(acc[mf][nf][2] + bv.x, acc[mf][nf][3] + bv.y);
                *(float2*)(C + (size_t)(r0 + 8) * DIM + cn) = o;
            }
        }
    }
}

// ---------------- rmsnorm (+rope for q) ------------------------------------
__device__ __forceinline__ float block_rms_scale(const float* row, float* red)
{
    float ss = 0.f;
    for (int i = threadIdx.x; i < DIM; i += 256) { float v = row[i]; ss += v * v; }
    #pragma unroll
    for (int o = 16; o; o >>= 1) ss += __shfl_xor_sync(0xffffffffu, ss, o);
    if ((threadIdx.x & 31) == 0) red[threadIdx.x >> 5] = ss;
    __syncthreads();
    if (threadIdx.x == 0) {
        float tot = 0.f;
        #pragma unroll
        for (int i = 0; i < 8; i++) tot += red[i];
        red[0] = rsqrtf(tot / (float)DIM + EPS_F);
    }
    __syncthreads();
    return red[0];
}

__global__ __launch_bounds__(256) void rmsnorm_rope_q(
    float* __restrict__ q, const float* __restrict__ g,
    const float* __restrict__ fc, const float* __restrict__ fs)
{
    __shared__ float red[8];
    int t = blockIdx.x;
    float* row = q + (size_t)t * DIM;
    float scale = block_rms_scale(row, red);
    int h = t / WW, w = t % WW;
    for (int p = threadIdx.x; p < DIM / 2; p += 256) {
        int c = p & 63;
        int ridx = (c < FT) ? Q_FRAME : ((c < FT + FSZ) ? h : w);
        float cs = fc[ridx * 64 + c], sn = fs[ridx * 64 + c];
        float a = row[2*p]   * scale * g[2*p];
        float b = row[2*p+1] * scale * g[2*p+1];
        row[2*p]   = tf32r(a * cs - b * sn);
        row[2*p+1] = tf32r(a * sn + b * cs);
    }
}

__global__ __launch_bounds__(256) void rmsnorm_plain(
    float* __restrict__ k, const float* __restrict__ g)
{
    __shared__ float red[8];
    int t = blockIdx.x;
    float* row = k + (size_t)t * DIM;
    float scale = block_rms_scale(row, red);
    for (int i = threadIdx.x; i < DIM; i += 256)
        row[i] = row[i] * scale * g[i];
}

// ---------------- build combined KV (gather + blend + rope; tf32-rounded) ---
__global__ __launch_bounds__(256) void build_kv(
    const float* __restrict__ ck, const float* __restrict__ cv,
    const float* __restrict__ kn, const float* __restrict__ vn,
    float* __restrict__ kc, float* __restrict__ vc,
    const float* __restrict__ fc, const float* __restrict__ fs)
{
    int r = blockIdx.x;
    const float *sk, *sv, *sk2 = nullptr, *sv2 = nullptr;
    if (r < 1560) {
        sk  = ck + (size_t)r * DIM;          sv  = cv + (size_t)r * DIM;
        sk2 = ck + (size_t)(9360 + r) * DIM; sv2 = cv + (size_t)(9360 + r) * DIM;
    } else if (r < 7800) {
        sk = ck + (size_t)(r + 3120) * DIM;  sv = cv + (size_t)(r + 3120) * DIM;
    } else {
        sk = kn + (size_t)(r - 7800) * DIM;  sv = vn + (size_t)(r - 7800) * DIM;
    }
    float* vd = vc + (size_t)r * DIM;
    for (int i = threadIdx.x; i < DIM; i += 256) {
        float v = sv[i];
        if (sv2) v = ALPHA_F * v + BETA_F * sv2[i];
        vd[i] = tf32r(v);
    }
    int fr = r / 1560, p = r % 1560, h = p / WW, w = p % WW;
    float* kd = kc + (size_t)r * DIM;
    for (int pp = threadIdx.x; pp < DIM / 2; pp += 256) {
        int c = pp & 63;
        int ridx = (c < FT) ? fr : ((c < FT + FSZ) ? h : w);
        float cs = fc[ridx * 64 + c], sn = fs[ridx * 64 + c];
        float a = sk[2*pp], b = sk[2*pp+1];
        if (sk2) { a = ALPHA_F*a + BETA_F*sk2[2*pp]; b = ALPHA_F*b + BETA_F*sk2[2*pp+1]; }
        kd[2*pp]   = tf32r(a * cs - b * sn);
        kd[2*pp+1] = tf32r(a * sn + b * cs);
    }
}

// ================== tf32 tensor-core flash attention =========================
#define QA_KS 516
#define KB_KS 514
#define PA_KS 516
#define VB_NT 66
#define VB_KS (16 * VB_NT)

#define QA_OFF 0
#define KB_OFF (16 * QA_KS)
#define PA_OFF KB_OFF
#define VB_OFF (KB_OFF + 16 * KB_KS)
#define XM_OFF (VB_OFF + 8 * VB_KS)
#define XS_OFF (XM_OFF + 128)
#define ATTN_SMEM_U32 (XS_OFF + 128)

__global__ __launch_bounds__(256, 2) void attn_tc(
    const float* __restrict__ Q, const float* __restrict__ Kc,
    const float* __restrict__ Vc, float* __restrict__ Oo)
{
    extern __shared__ uint32_t sm[];
    uint32_t* QA = sm + QA_OFF;
    uint32_t* KB = sm + KB_OFF;
    uint32_t* PA = sm + PA_OFF;
    uint32_t* VB = sm + VB_OFF;
    float* xmax  = (float*)(sm + XM_OFF);
    float* xsum  = (float*)(sm + XS_OFF);

    const int q0   = blockIdx.x * 64;
    const int head = blockIdx.y;
    const int tid  = threadIdx.x;
    const int lane = tid & 31;
    const int wrp  = tid >> 5;
    const int mi   = wrp & 3;
    const int ni   = wrp >> 2;
    const int g    = lane >> 2;
    const int t4   = lane & 3;

    for (int idx = tid; idx < 64 * 32; idx += 256) {
        int r = idx >> 5, d4 = idx & 31;
        int k = d4 * 4;
        int gq = q0 + r;
        float4 v = (gq < S_LEN)
            ? *(const float4*)(Q + (size_t)gq * DIM + head * HDIM + k)
            : make_float4(0.f, 0.f, 0.f, 0.f);
        int ks = k >> 3;
        int khi = (k & 4) ? 2 : 0;
        int rl = r & 15;
        int reg = ((rl >= 8) ? 1 : 0) + khi;
        int ln = (rl & 7) * 4;
        uint32_t* base = QA + ks * QA_KS + (r >> 4) * 128;
        base[(ln + 0) * 4 + reg] = __float_as_uint(v.x);
        base[(ln + 1) * 4 + reg] = __float_as_uint(v.y);
        base[(ln + 2) * 4 + reg] = __float_as_uint(v.z);
        base[(ln + 3) * 4 + reg] = __float_as_uint(v.w);
    }

    float m0 = -INFINITY, m1 = -INFINITY;
    float l0 = 0.f, l1 = 0.f;
    float O[8][4];
    #pragma unroll
    for (int i = 0; i < 8; i++)
        #pragma unroll
        for (int j = 0; j < 4; j++) O[i][j] = 0.f;

    const int nkt = (KV_LEN + 63) / 64;
    for (int kt = 0; kt < nkt; kt++) {
        int kt0 = kt * 64;
        __syncthreads();

        for (int idx = tid; idx < 64 * 32; idx += 256) {
            int row = idx >> 5, d4 = idx & 31;
            int k = d4 * 4;
            int gr = kt0 + row;
            float4 v = (gr < KV_LEN)
                ? *(const float4*)(Kc + (size_t)gr * DIM + head * HDIM + k)
                : make_float4(0.f, 0.f, 0.f, 0.f);
            int ks = k >> 3;
            int reg = (k & 4) ? 1 : 0;
            int nt = row >> 3;
            int ln = (row & 7) * 4;
            uint32_t* base = KB + ks * KB_KS + nt * 64;
            base[(ln + 0) * 2 + reg] = __float_as_uint(v.x);
            base[(ln + 1) * 2 + reg] = __float_as_uint(v.y);
            base[(ln + 2) * 2 + reg] = __float_as_uint(v.z);
            base[(ln + 3) * 2 + reg] = __float_as_uint(v.w);
        }
        for (int idx = tid; idx < 64 * 32; idx += 256) {
            int row = idx >> 5, d4 = idx & 31;
            int d = d4 * 4;
            int gr = kt0 + row;
            float4 v = (gr < KV_LEN)
                ? *(const float4*)(Vc + (size_t)gr * DIM + head * HDIM + d)
                : make_float4(0.f, 0.f, 0.f, 0.f);
            int ks = row >> 3;
            int reg = (row & 4) ? 1 : 0;
            int nt = d >> 3;
            int t0 = row & 3;
            uint32_t* base = VB + ks * VB_KS + nt * VB_NT;
            base[(((d & 7) + 0) * 4 + t0) * 2 + reg] = __float_as_uint(v.x);
            base[(((d & 7) + 1) * 4 + t0) * 2 + reg] = __float_as_uint(v.y);
            base[(((d & 7) + 2) * 4 + t0) * 2 + reg] = __float_as_uint(v.z);
            base[(((d & 7) + 3) * 4 + t0) * 2 + reg] = __float_as_uint(v.w);
        }
        __syncthreads();

        float Sc[4][4];
        #pragma unroll
        for (int i = 0; i < 4; i++)
            #pragma unroll
            for (int j = 0; j < 4; j++) Sc[i][j] = 0.f;

        #pragma unroll
        for (int ks = 0; ks < 16; ks++) {
            uint4 a = *(const uint4*)(QA + ks * QA_KS + mi * 128 + lane * 4);
            #pragma unroll
            for (int ntl = 0; ntl < 4; ntl++) {
                int nt = ni * 4 + ntl;
                uint2 b = *(const uint2*)(KB + ks * KB_KS + nt * 64 + lane * 2);
                mma_tf32(Sc[ntl][0], Sc[ntl][1], Sc[ntl][2], Sc[ntl][3],
                         a.x, a.y, a.z, a.w, b.x, b.y);
            }
        }

        float pm0 = -INFINITY, pm1 = -INFINITY;
        #pragma unroll
        for (int ntl = 0; ntl < 4; ntl++) {
            int cbase = ni * 32 + ntl * 8 + 2 * t4;
            #pragma unroll
            for (int j = 0; j < 4; j++) {
                int c = cbase + (j & 1);
                bool valid = (kt0 + c) < KV_LEN;
                Sc[ntl][j] = valid ? Sc[ntl][j] * SCALE : -1e30f;
            }
            pm0 = fmaxf(pm0, fmaxf(Sc[ntl][0], Sc[ntl][1]));
            pm1 = fmaxf(pm1, fmaxf(Sc[ntl][2], Sc[ntl][3]));
        }
        pm0 = fmaxf(pm0, __shfl_xor_sync(0xffffffffu, pm0, 1));
        pm0 = fmaxf(pm0, __shfl_xor_sync(0xffffffffu, pm0, 2));
        pm1 = fmaxf(pm1, __shfl_xor_sync(0xffffffffu, pm1, 1));
        pm1 = fmaxf(pm1, __shfl_xor_sync(0xffffffffu, pm1, 2));
        if (t4 == 0) {
            xmax[ni * 64 + 16 * mi + g]     = pm0;
            xmax[ni * 64 + 16 * mi + g + 8] = pm1;
        }
        __syncthreads();

        int r0 = 16 * mi + g, r1 = r0 + 8;
        float m0n = fmaxf(m0, fmaxf(xmax[r0], xmax[64 + r0]));
        float m1n = fmaxf(m1, fmaxf(xmax[r1], xmax[64 + r1]));

        float s0 = 0.f, s1 = 0.f;
        #pragma unroll
        for (int ntl = 0; ntl < 4; ntl++) {
            int ks = ni * 4 + ntl;
            uint32_t* base = PA + ks * PA_KS + mi * 128;
            #pragma unroll
            for (int j = 0; j < 4; j++) {
                float e = __expf(Sc[ntl][j] - ((j < 2) ? m0n : m1n));
                if (j < 2) s0 += e; else s1 += e;
                int c = 2 * t4 + (j & 1);
                int rl = (j < 2) ? g : (g + 8);
                int reg = ((rl >= 8) ? 1 : 0) + ((c >= 4) ? 2 : 0);
                base[((rl & 7) * 4 + (c & 3)) * 4 + reg] = f2tf32(e);
            }
        }
        s0 += __shfl_xor_sync(0xffffffffu, s0, 1);
        s0 += __shfl_xor_sync(0xffffffffu, s0, 2);
        s1 += __shfl_xor_sync(0xffffffffu, s1, 1);
        s1 += __shfl_xor_sync(0xffffffffu, s1, 2);
        if (t4 == 0) {
            xsum[ni * 64 + r0] = s0;
            xsum[ni * 64 + r1] = s1;
        }
        __syncthreads();

        float alpha0 = __expf(m0 - m0n);
        float alpha1 = __expf(m1 - m1n);
        l0 = l0 * alpha0 + xsum[r0] + xsum[64 + r0];
        l1 = l1 * alpha1 + xsum[r1] + xsum[64 + r1];
        m0 = m0n; m1 = m1n;

        #pragma unroll
        for (int ntl = 0; ntl < 8; ntl++) {
            O[ntl][0] *= alpha0; O[ntl][1] *= alpha0;
            O[ntl][2] *= alpha1; O[ntl][3] *= alpha1;
        }

        #pragma unroll
        for (int ks = 0; ks < 8; ks++) {
            uint4 a = *(const uint4*)(PA + ks * PA_KS + mi * 128 + lane * 4);
            #pragma unroll
            for (int ntl = 0; ntl < 8; ntl++) {
                int nt = ni * 8 + ntl;
                uint2 b = *(const uint2*)(VB + ks * VB_KS + nt * VB_NT + lane * 2);
                mma_tf32(O[ntl][0], O[ntl][1], O[ntl][2], O[ntl][3],
                         a.x, a.y, a.z, a.w, b.x, b.y);
            }
        }
    }

    float inv0 = 1.f / l0, inv1 = 1.f / l1;
    int gr0 = q0 + 16 * mi + g;
    int gr1 = gr0 + 8;
    #pragma unroll
    for (int ntl = 0; ntl < 8; ntl++) {
        int c = ni * 64 + ntl * 8 + 2 * t4;
        if (gr0 < S_LEN) {
            float2 o0 = make_float2(O[ntl][0] * inv0, O[ntl][1] * inv0);
            *(float2*)(Oo + (size_t)gr0 * DIM + head * HDIM + c) = o0;
        }
        if (gr1 < S_LEN) {
            float2 o1 = make_float2(O[ntl][2] * inv1, O[ntl][3] * inv1);
            *(float2*)(Oo + (size_t)gr1 * DIM + head * HDIM + c) = o1;
        }
    }
}

// ---------------- launch -----------------------------------------------------
extern "C" void kernel_launch(void* const* d_in, const int* in_sizes, int n_in,
                              void* d_out, int out_size)
{
    const float* x  = (const float*)d_in[0];
    const float* Wq = (const float*)d_in[1];
    const float* bq = (const float*)d_in[2];
    const float* Wk = (const float*)d_in[3];
    const float* bk = (const float*)d_in[4];
    const float* Wv = (const float*)d_in[5];
    const float* bv = (const float*)d_in[6];
    const float* Wo = (const float*)d_in[7];
    const float* bo = (const float*)d_in[8];
    const float* gq = (const float*)d_in[9];
    const float* gk = (const float*)d_in[10];
    const float* ck = (const float*)d_in[11];
    const float* cv = (const float*)d_in[12];
    const float* fc = (const float*)d_in[13];
    const float* fs = (const float*)d_in[14];
    float* out = (float*)d_out;

    float *qb, *kb, *vb, *kc, *vc, *ob;
    cudaGetSymbolAddress((void**)&qb, d_qbuf);
    cudaGetSymbolAddress((void**)&kb, d_kbuf);
    cudaGetSymbolAddress((void**)&vb, d_vbuf);
    cudaGetSymbolAddress((void**)&kc, d_kc);
    cudaGetSymbolAddress((void**)&vc, d_vc);
    cudaGetSymbolAddress((void**)&ob, d_obuf);

    int gemm_smem = G_SMEM_U32 * (int)sizeof(uint32_t);
    cudaFuncSetAttribute(gemm3_bf16, cudaFuncAttributeMaxDynamicSharedMemorySize, gemm_smem);

    // fused QKV projection (one launch, 36 x 13 CTAs)
    gemm3_bf16<<<dim3(36, 13), 256, gemm_smem>>>(
        x, Wq, Wk, Wv, bq, bk, bv, qb, kb, vb, S_LEN);

    rmsnorm_rope_q<<<S_LEN, 256>>>(qb, gq, fc, fs);
    rmsnorm_plain<<<S_LEN, 256>>>(kb, gk);

    build_kv<<<KV_LEN, 256>>>(ck, cv, kb, vb, kc, vc, fc, fs);

    int attn_smem = ATTN_SMEM_U32 * (int)sizeof(uint32_t);
    cudaFuncSetAttribute(attn_tc, cudaFuncAttributeMaxDynamicSharedMemorySize, attn_smem);
    attn_tc<<<dim3((S_LEN + 63) / 64, NHEADS), 256, attn_smem>>>(qb, kc, vc, ob);

    // output projection
    gemm3_bf16<<<dim3(12, 13), 256, gemm_smem>>>(
        ob, Wo, Wo, Wo, bo, bo, bo, out, out, out, S_LEN);
}

// round 7
// speedup vs baseline: 3.2365x; 1.1344x over previous
#include <cuda_runtime.h>
#include <cuda_bf16.h>
#include <math.h>
#include <stdint.h>

#define DIM      1536
#define NHEADS   12
#define HDIM     128
#define S_LEN    1560
#define KV_LEN   9360
#define NKT      147            /* 64-row kv tiles */
#define FT       22
#define FSZ      21
#define WW       52
#define ALPHA_F  0.999f
#define BETA_F   0.001f
#define EPS_F    1e-6f
#define Q_FRAME  5
#define SCALE    0.08838834764831843f   /* 1/sqrt(128) */

// ---------------- scratch (device globals; no allocations allowed) ----------
__device__ float d_qbuf[S_LEN * DIM];
__device__ float d_kbuf[S_LEN * DIM];
__device__ float d_vbuf[S_LEN * DIM];
__device__ float d_kfrag[(size_t)NHEADS * NKT * 8192];
__device__ float d_vfrag[(size_t)NHEADS * NKT * 8192];
__device__ float d_obuf[S_LEN * DIM];

__device__ __forceinline__ uint32_t f2tf32(float f) {
    uint32_t r;
    asm("cvt.rna.tf32.f32 %0, %1;" : "=r"(r) : "f"(f));
    return r;
}
__device__ __forceinline__ float tf32r(float f) {
    uint32_t r = f2tf32(f);
    return __uint_as_float(r);
}
__device__ __forceinline__ float bfr(float v) {
    return __bfloat162float(__float2bfloat16_rn(v));
}
__device__ __forceinline__ uint32_t pkbf2(float lo, float hi) {
    __nv_bfloat162 t = __floats2bfloat162_rn(lo, hi);
    return *reinterpret_cast<uint32_t*>(&t);
}
__device__ __forceinline__ void cpa16(void* dst, const void* src) {
    uint32_t d = (uint32_t)__cvta_generic_to_shared(dst);
    asm volatile("cp.async.ca.shared.global [%0], [%1], 16;" :: "r"(d), "l"(src));
}

__device__ __forceinline__ void mma_tf32(
    float& c0, float& c1, float& c2, float& c3,
    uint32_t a0, uint32_t a1, uint32_t a2, uint32_t a3,
    uint32_t b0, uint32_t b1)
{
    asm volatile(
        "mma.sync.aligned.m16n8k8.row.col.f32.tf32.tf32.f32 "
        "{%0,%1,%2,%3},{%4,%5,%6,%7},{%8,%9},{%0,%1,%2,%3};"
        : "+f"(c0), "+f"(c1), "+f"(c2), "+f"(c3)
        : "r"(a0), "r"(a1), "r"(a2), "r"(a3), "r"(b0), "r"(b1));
}

__device__ __forceinline__ void mma_bf16(
    float* c, const uint4& a, const uint2& b)
{
    asm volatile(
        "mma.sync.aligned.m16n8k16.row.col.f32.bf16.bf16.f32 "
        "{%0,%1,%2,%3},{%4,%5,%6,%7},{%8,%9},{%0,%1,%2,%3};"
        : "+f"(c[0]), "+f"(c[1]), "+f"(c[2]), "+f"(c[3])
        : "r"(a.x), "r"(a.y), "r"(a.z), "r"(a.w), "r"(b.x), "r"(b.y));
}

// ============ bf16 3-term GEMM (unchanged) ==================================
#define G_AH 0
#define G_AL 4096
#define G_BH 8192
#define G_BL 12416
#define G_SMEM_U32 16640

__global__ __launch_bounds__(256, 2) void gemm3_bf16(
    const float* __restrict__ A,
    const float* __restrict__ W0, const float* __restrict__ W1, const float* __restrict__ W2,
    const float* __restrict__ b0, const float* __restrict__ b1, const float* __restrict__ b2,
    float* __restrict__ C0, float* __restrict__ C1, float* __restrict__ C2,
    int M)
{
    extern __shared__ uint32_t gsm[];
    uint32_t* AH = gsm + G_AH;
    uint32_t* AL = gsm + G_AL;
    uint32_t* BH = gsm + G_BH;
    uint32_t* BL = gsm + G_BL;

    const int sel = blockIdx.x / 12;
    const float* B    = (sel == 0) ? W0 : (sel == 1) ? W1 : W2;
    const float* bias = (sel == 0) ? b0 : (sel == 1) ? b1 : b2;
    float*       C    = (sel == 0) ? C0 : (sel == 1) ? C1 : C2;
    const int bn = (blockIdx.x - sel * 12) * 128;
    const int bm = blockIdx.y * 128;

    const int tid  = threadIdx.x;
    const int lane = tid & 31, wrp = tid >> 5;
    const int wm = wrp & 3, wn = wrp >> 2;
    const int g = lane >> 2, t4 = lane & 3;

    float acc[2][8][4];
    #pragma unroll
    for (int i = 0; i < 2; i++)
        #pragma unroll
        for (int j = 0; j < 8; j++)
            #pragma unroll
            for (int r = 0; r < 4; r++) acc[i][j][r] = 0.f;

    for (int k0 = 0; k0 < DIM; k0 += 64) {
        __syncthreads();
        #pragma unroll
        for (int it = 0; it < 8; it++) {
            int idx = tid + it * 256;
            int r = idx >> 4, c4 = idx & 15;
            int gr = bm + r;
            float4 v = (gr < M)
                ? *(const float4*)(A + (size_t)gr * DIM + k0 + c4 * 4)
                : make_float4(0.f, 0.f, 0.f, 0.f);
            int rl = r & 15, mtile = r >> 4;
            int ks = c4 >> 2, k8 = (c4 >> 1) & 1, t4a = (c4 & 1) * 2;
            int reg = (rl >> 3) + 2 * k8;
            int base = ks * 1024 + mtile * 128;
            int lane0 = (rl & 7) * 4 + t4a;
            float hx = bfr(v.x), hy = bfr(v.y), hz = bfr(v.z), hw = bfr(v.w);
            AH[base + lane0 * 4 + reg]       = pkbf2(hx, hy);
            AH[base + (lane0 + 1) * 4 + reg] = pkbf2(hz, hw);
            AL[base + lane0 * 4 + reg]       = pkbf2(v.x - hx, v.y - hy);
            AL[base + (lane0 + 1) * 4 + reg] = pkbf2(v.z - hz, v.w - hw);
        }
        #pragma unroll
        for (int it = 0; it < 4; it++) {
            int idx = tid + it * 256;
            int kp = idx >> 5, n4 = idx & 31;
            const float* bp = B + (size_t)(k0 + 2 * kp) * DIM + bn + n4 * 4;
            float4 u = *(const float4*)bp;
            float4 w = *(const float4*)(bp + DIM);
            int ks = kp >> 3, tb = kp & 3, reg = (kp >> 2) & 1;
            int base = ks * 1056;
            float uu[4] = {u.x, u.y, u.z, u.w};
            float ww[4] = {w.x, w.y, w.z, w.w};
            #pragma unroll
            for (int j = 0; j < 4; j++) {
                int n = n4 * 4 + j;
                int nt = n >> 3;
                int lb = (n & 7) * 4 + tb;
                float hu = bfr(uu[j]), hw2 = bfr(ww[j]);
                BH[base + nt * 66 + lb * 2 + reg] = pkbf2(hu, hw2);
                BL[base + nt * 66 + lb * 2 + reg] = pkbf2(uu[j] - hu, ww[j] - hw2);
            }
        }
        __syncthreads();

        #pragma unroll
        for (int ks = 0; ks < 4; ks++) {
            uint4 ah0 = *(const uint4*)&AH[ks * 1024 + (wm * 2 + 0) * 128 + lane * 4];
            uint4 ah1 = *(const uint4*)&AH[ks * 1024 + (wm * 2 + 1) * 128 + lane * 4];
            uint4 al0 = *(const uint4*)&AL[ks * 1024 + (wm * 2 + 0) * 128 + lane * 4];
            uint4 al1 = *(const uint4*)&AL[ks * 1024 + (wm * 2 + 1) * 128 + lane * 4];
            #pragma unroll
            for (int nf = 0; nf < 8; nf++) {
                int nt = wn * 8 + nf;
                uint2 bh = *(const uint2*)&BH[ks * 1056 + nt * 66 + lane * 2];
                uint2 bl = *(const uint2*)&BL[ks * 1056 + nt * 66 + lane * 2];
                mma_bf16(acc[0][nf], ah0, bh);
                mma_bf16(acc[1][nf], ah1, bh);
                mma_bf16(acc[0][nf], al0, bh);
                mma_bf16(acc[1][nf], al1, bh);
                mma_bf16(acc[0][nf], ah0, bl);
                mma_bf16(acc[1][nf], ah1, bl);
            }
        }
    }

    #pragma unroll
    for (int nf = 0; nf < 8; nf++) {
        int cn = bn + wn * 64 + nf * 8 + 2 * t4;
        float2 bv = *(const float2*)(bias + cn);
        #pragma unroll
        for (int mf = 0; mf < 2; mf++) {
            int r0 = bm + wm * 32 + mf * 16 + g;
            if (r0 < M) {
                float2 o = make_float2(acc[mf][nf][0] + bv.x, acc[mf][nf][1] + bv.y);
                *(float2*)(C + (size_t)r0 * DIM + cn) = o;
            }
            if (r0 + 8 < M) {
                float2 o = make_float2(acc[mf][nf][2] + bv.x, acc[mf][nf][3] + bv.y);
                *(float2*)(C + (size_t)(r0 + 8) * DIM + cn) = o;
            }
        }
    }
}

// ---------------- rmsnorm (+rope for q) ------------------------------------
__device__ __forceinline__ float block_rms_scale(const float* row, float* red)
{
    float ss = 0.f;
    for (int i = threadIdx.x; i < DIM; i += 256) { float v = row[i]; ss += v * v; }
    #pragma unroll
    for (int o = 16; o; o >>= 1) ss += __shfl_xor_sync(0xffffffffu, ss, o);
    if ((threadIdx.x & 31) == 0) red[threadIdx.x >> 5] = ss;
    __syncthreads();
    if (threadIdx.x == 0) {
        float tot = 0.f;
        #pragma unroll
        for (int i = 0; i < 8; i++) tot += red[i];
        red[0] = rsqrtf(tot / (float)DIM + EPS_F);
    }
    __syncthreads();
    return red[0];
}

__global__ __launch_bounds__(256) void rmsnorm_rope_q(
    float* __restrict__ q, const float* __restrict__ g,
    const float* __restrict__ fc, const float* __restrict__ fs)
{
    __shared__ float red[8];
    int t = blockIdx.x;
    float* row = q + (size_t)t * DIM;
    float scale = block_rms_scale(row, red);
    int h = t / WW, w = t % WW;
    for (int p = threadIdx.x; p < DIM / 2; p += 256) {
        int c = p & 63;
        int ridx = (c < FT) ? Q_FRAME : ((c < FT + FSZ) ? h : w);
        float cs = fc[ridx * 64 + c], sn = fs[ridx * 64 + c];
        float a = row[2*p]   * scale * g[2*p];
        float b = row[2*p+1] * scale * g[2*p+1];
        row[2*p]   = tf32r(a * cs - b * sn);
        row[2*p+1] = tf32r(a * sn + b * cs);
    }
}

__global__ __launch_bounds__(256) void rmsnorm_plain(
    float* __restrict__ k, const float* __restrict__ g)
{
    __shared__ float red[8];
    int t = blockIdx.x;
    float* row = k + (size_t)t * DIM;
    float scale = block_rms_scale(row, red);
    for (int i = threadIdx.x; i < DIM; i += 256)
        row[i] = row[i] * scale * g[i];
}

// ------ build combined KV directly in mma-fragment order (per head,tile) ----
// K block word = ks*512 + (row&7... nt)*64 + (row&7)*8 + 2*(kl&3) + (kl>>2)
//   -> per task (rowT, ks): contiguous 8-word group, k order {0,4,1,5,2,6,3,7}
// V block word = ks*1024 + nt*64 + (d&7)*8 + 2*(row&3) + ((row>>2)&1)
__device__ __forceinline__ const float* kv_src(
    int R, const float* __restrict__ cc, const float* __restrict__ nn,
    const float** s2)
{
    *s2 = nullptr;
    if (R < 1560) { *s2 = cc + (size_t)(9360 + R) * DIM; return cc + (size_t)R * DIM; }
    if (R < 7800) return cc + (size_t)(R + 3120) * DIM;
    return nn + (size_t)(R - 7800) * DIM;
}

__global__ __launch_bounds__(256) void build_kv_frag(
    const float* __restrict__ ck, const float* __restrict__ cv,
    const float* __restrict__ kn, const float* __restrict__ vn,
    float* __restrict__ kf, float* __restrict__ vf,
    const float* __restrict__ fc, const float* __restrict__ fs)
{
    const int tile = blockIdx.x, head = blockIdx.y;
    const int tid = threadIdx.x;
    float* dst = (blockIdx.z ? vf : kf) + ((size_t)head * NKT + tile) * 8192;

    if (blockIdx.z == 0) {
        // ---- K: task t -> (rowT, ks); 8 contiguous k, permuted store ----
        #pragma unroll
        for (int it = 0; it < 4; it++) {
            int t = tid + it * 256;               // 0..1023
            int ks = t >> 6;                      // 0..15
            int rowT = ((t >> 3) & 7) * 8 + (t & 7);
            int k0 = ks * 8;
            int R = tile * 64 + rowT;
            float pr[8] = {0.f,0.f,0.f,0.f,0.f,0.f,0.f,0.f};
            if (R < KV_LEN) {
                const float* s2;
                const float* s1 = kv_src(R, ck, kn, &s2);
                float4 a = *(const float4*)(s1 + head * HDIM + k0);
                float4 b4 = *(const float4*)(s1 + head * HDIM + k0 + 4);
                if (s2) {
                    float4 a2 = *(const float4*)(s2 + head * HDIM + k0);
                    float4 b2 = *(const float4*)(s2 + head * HDIM + k0 + 4);
                    a.x = ALPHA_F*a.x + BETA_F*a2.x; a.y = ALPHA_F*a.y + BETA_F*a2.y;
                    a.z = ALPHA_F*a.z + BETA_F*a2.z; a.w = ALPHA_F*a.w + BETA_F*a2.w;
                    b4.x = ALPHA_F*b4.x + BETA_F*b2.x; b4.y = ALPHA_F*b4.y + BETA_F*b2.y;
                    b4.z = ALPHA_F*b4.z + BETA_F*b2.z; b4.w = ALPHA_F*b4.w + BETA_F*b2.w;
                }
                float raw[8] = {a.x, a.y, a.z, a.w, b4.x, b4.y, b4.z, b4.w};
                int fr = R / 1560, pp = R % 1560, hh = pp / WW, wc = pp % WW;
                #pragma unroll
                for (int j = 0; j < 4; j++) {
                    int c = ks * 4 + j;           // rope pair index 0..63
                    int ridx = (c < FT) ? fr : ((c < FT + FSZ) ? hh : wc);
                    float cs = fc[ridx * 64 + c], sn = fs[ridx * 64 + c];
                    float x = raw[2*j], y = raw[2*j + 1];
                    pr[2*j]     = tf32r(x * cs - y * sn);
                    pr[2*j + 1] = tf32r(x * sn + y * cs);
                }
            }
            // fragment order within 8-word group: kl {0,4,1,5 | 2,6,3,7}
            *(float4*)(dst + t * 8)     = make_float4(pr[0], pr[4], pr[1], pr[5]);
            *(float4*)(dst + t * 8 + 4) = make_float4(pr[2], pr[6], pr[3], pr[7]);
        }
    } else {
        // ---- V (unchanged; verified correct inversion) ----
        #pragma unroll
        for (int it = 0; it < 8; it++) {
            int idx = (tid + it * 256) * 4;
            int ks = idx >> 10, rem = idx & 1023;
            int nt = rem >> 6, w = rem & 63;
            int dd = w >> 3, w2b = w & 7;   // 0 or 4
            int d = nt * 8 + dd;
            float out[4];
            #pragma unroll
            for (int j = 0; j < 4; j++) {
                int w2 = w2b + j;
                int r7 = (w2 >> 1) + ((w2 & 1) << 2);
                int R = tile * 64 + ks * 8 + r7;
                float v = 0.f;
                if (R < KV_LEN) {
                    const float* s2;
                    const float* s1 = kv_src(R, cv, vn, &s2);
                    v = s1[head * HDIM + d];
                    if (s2) v = ALPHA_F * v + BETA_F * s2[head * HDIM + d];
                }
                out[j] = tf32r(v);
            }
            *(float4*)(dst + idx) = make_float4(out[0], out[1], out[2], out[3]);
        }
    }
}

// ================== tf32 tensor-core flash attention =========================
#define QA_KS 516
#define PA_KS 516
#define QA_OFF 0
#define KB_OFF (16 * QA_KS)          /* 8256 */
#define PA_OFF KB_OFF                /* PA (4128 w) overlays KB (8192 w) */
#define VB_OFF (KB_OFF + 8192)       /* 16448 */
#define XM_OFF (VB_OFF + 8192)       /* 24640 */
#define XS_OFF (XM_OFF + 128)
#define ATTN_SMEM_U32 (XS_OFF + 128) /* 24896 words = 99584 B */

__global__ __launch_bounds__(256, 2) void attn_tc(
    const float* __restrict__ Q, const float* __restrict__ Kf,
    const float* __restrict__ Vf, float* __restrict__ Oo)
{
    extern __shared__ uint32_t sm[];
    uint32_t* QA = sm + QA_OFF;
    uint32_t* KB = sm + KB_OFF;
    uint32_t* PA = sm + PA_OFF;
    uint32_t* VB = sm + VB_OFF;
    float* xmax  = (float*)(sm + XM_OFF);
    float* xsum  = (float*)(sm + XS_OFF);

    const int q0   = blockIdx.x * 64;
    const int head = blockIdx.y;
    const int tid  = threadIdx.x;
    const int lane = tid & 31;
    const int wrp  = tid >> 5;
    const int mi   = wrp & 3;
    const int ni   = wrp >> 2;
    const int g    = lane >> 2;
    const int t4   = lane & 3;

    for (int idx = tid; idx < 64 * 32; idx += 256) {
        int r = idx >> 5, d4 = idx & 31;
        int k = d4 * 4;
        int gq = q0 + r;
        float4 v = (gq < S_LEN)
            ? *(const float4*)(Q + (size_t)gq * DIM + head * HDIM + k)
            : make_float4(0.f, 0.f, 0.f, 0.f);
        int ks = k >> 3;
        int khi = (k & 4) ? 2 : 0;
        int rl = r & 15;
        int reg = ((rl >= 8) ? 1 : 0) + khi;
        int ln = (rl & 7) * 4;
        uint32_t* base = QA + ks * QA_KS + (r >> 4) * 128;
        base[(ln + 0) * 4 + reg] = __float_as_uint(v.x);
        base[(ln + 1) * 4 + reg] = __float_as_uint(v.y);
        base[(ln + 2) * 4 + reg] = __float_as_uint(v.z);
        base[(ln + 3) * 4 + reg] = __float_as_uint(v.w);
    }

    float m0 = -INFINITY, m1 = -INFINITY;
    float l0 = 0.f, l1 = 0.f;
    float O[8][4];
    #pragma unroll
    for (int i = 0; i < 8; i++)
        #pragma unroll
        for (int j = 0; j < 4; j++) O[i][j] = 0.f;

    for (int kt = 0; kt < NKT; kt++) {
        int kt0 = kt * 64;
        __syncthreads();   // prev PV (reads PA/VB) done before overwrite

        const float* kfp = Kf + ((size_t)head * NKT + kt) * 8192;
        const float* vfp = Vf + ((size_t)head * NKT + kt) * 8192;
        #pragma unroll
        for (int it = 0; it < 8; it++) {
            int idx = (tid + it * 256) * 4;
            cpa16(KB + idx, kfp + idx);
        }
        asm volatile("cp.async.commit_group;");
        #pragma unroll
        for (int it = 0; it < 8; it++) {
            int idx = (tid + it * 256) * 4;
            cpa16(VB + idx, vfp + idx);
        }
        asm volatile("cp.async.commit_group;");
        asm volatile("cp.async.wait_group 1;");   // K done; V in flight
        __syncthreads();

        // ---- S = Q K^T ----
        float Sc[4][4];
        #pragma unroll
        for (int i = 0; i < 4; i++)
            #pragma unroll
            for (int j = 0; j < 4; j++) Sc[i][j] = 0.f;

        #pragma unroll
        for (int ks = 0; ks < 16; ks++) {
            uint4 a = *(const uint4*)(QA + ks * QA_KS + mi * 128 + lane * 4);
            #pragma unroll
            for (int ntl = 0; ntl < 4; ntl++) {
                int nt = ni * 4 + ntl;
                uint2 b = *(const uint2*)(KB + ks * 512 + nt * 64 + lane * 2);
                mma_tf32(Sc[ntl][0], Sc[ntl][1], Sc[ntl][2], Sc[ntl][3],
                         a.x, a.y, a.z, a.w, b.x, b.y);
            }
        }

        float pm0 = -INFINITY, pm1 = -INFINITY;
        #pragma unroll
        for (int ntl = 0; ntl < 4; ntl++) {
            int cbase = ni * 32 + ntl * 8 + 2 * t4;
            #pragma unroll
            for (int j = 0; j < 4; j++) {
                int c = cbase + (j & 1);
                bool valid = (kt0 + c) < KV_LEN;
                Sc[ntl][j] = valid ? Sc[ntl][j] * SCALE : -1e30f;
            }
            pm0 = fmaxf(pm0, fmaxf(Sc[ntl][0], Sc[ntl][1]));
            pm1 = fmaxf(pm1, fmaxf(Sc[ntl][2], Sc[ntl][3]));
        }
        pm0 = fmaxf(pm0, __shfl_xor_sync(0xffffffffu, pm0, 1));
        pm0 = fmaxf(pm0, __shfl_xor_sync(0xffffffffu, pm0, 2));
        pm1 = fmaxf(pm1, __shfl_xor_sync(0xffffffffu, pm1, 1));
        pm1 = fmaxf(pm1, __shfl_xor_sync(0xffffffffu, pm1, 2));
        if (t4 == 0) {
            xmax[ni * 64 + 16 * mi + g]     = pm0;
            xmax[ni * 64 + 16 * mi + g + 8] = pm1;
        }
        __syncthreads();   // xmax visible; KB reads done -> PA writes safe

        int r0 = 16 * mi + g, r1 = r0 + 8;
        float m0n = fmaxf(m0, fmaxf(xmax[r0], xmax[64 + r0]));
        float m1n = fmaxf(m1, fmaxf(xmax[r1], xmax[64 + r1]));

        float s0 = 0.f, s1 = 0.f;
        #pragma unroll
        for (int ntl = 0; ntl < 4; ntl++) {
            int ks = ni * 4 + ntl;
            uint32_t* base = PA + ks * PA_KS + mi * 128;
            #pragma unroll
            for (int j = 0; j < 4; j++) {
                float e = __expf(Sc[ntl][j] - ((j < 2) ? m0n : m1n));
                if (j < 2) s0 += e; else s1 += e;
                int c = 2 * t4 + (j & 1);
                int rl = (j < 2) ? g : (g + 8);
                int reg = ((rl >= 8) ? 1 : 0) + ((c >= 4) ? 2 : 0);
                base[((rl & 7) * 4 + (c & 3)) * 4 + reg] = f2tf32(e);
            }
        }
        s0 += __shfl_xor_sync(0xffffffffu, s0, 1);
        s0 += __shfl_xor_sync(0xffffffffu, s0, 2);
        s1 += __shfl_xor_sync(0xffffffffu, s1, 1);
        s1 += __shfl_xor_sync(0xffffffffu, s1, 2);
        if (t4 == 0) {
            xsum[ni * 64 + r0] = s0;
            xsum[ni * 64 + r1] = s1;
        }
        asm volatile("cp.async.wait_group 0;");   // V arrived
        __syncthreads();

        float alpha0 = __expf(m0 - m0n);
        float alpha1 = __expf(m1 - m1n);
        l0 = l0 * alpha0 + xsum[r0] + xsum[64 + r0];
        l1 = l1 * alpha1 + xsum[r1] + xsum[64 + r1];
        m0 = m0n; m1 = m1n;

        #pragma unroll
        for (int ntl = 0; ntl < 8; ntl++) {
            O[ntl][0] *= alpha0; O[ntl][1] *= alpha0;
            O[ntl][2] *= alpha1; O[ntl][3] *= alpha1;
        }

        #pragma unroll
        for (int ks = 0; ks < 8; ks++) {
            uint4 a = *(const uint4*)(PA + ks * PA_KS + mi * 128 + lane * 4);
            #pragma unroll
            for (int ntl = 0; ntl < 8; ntl++) {
                int nt = ni * 8 + ntl;
                uint2 b = *(const uint2*)(VB + ks * 1024 + nt * 64 + lane * 2);
                mma_tf32(O[ntl][0], O[ntl][1], O[ntl][2], O[ntl][3],
                         a.x, a.y, a.z, a.w, b.x, b.y);
            }
        }
    }

    float inv0 = 1.f / l0, inv1 = 1.f / l1;
    int gr0 = q0 + 16 * mi + g;
    int gr1 = gr0 + 8;
    #pragma unroll
    for (int ntl = 0; ntl < 8; ntl++) {
        int c = ni * 64 + ntl * 8 + 2 * t4;
        if (gr0 < S_LEN) {
            float2 o0 = make_float2(O[ntl][0] * inv0, O[ntl][1] * inv0);
            *(float2*)(Oo + (size_t)gr0 * DIM + head * HDIM + c) = o0;
        }
        if (gr1 < S_LEN) {
            float2 o1 = make_float2(O[ntl][2] * inv1, O[ntl][3] * inv1);
            *(float2*)(Oo + (size_t)gr1 * DIM + head * HDIM + c) = o1;
        }
    }
}

// ---------------- launch -----------------------------------------------------
extern "C" void kernel_launch(void* const* d_in, const int* in_sizes, int n_in,
                              void* d_out, int out_size)
{
    const float* x  = (const float*)d_in[0];
    const float* Wq = (const float*)d_in[1];
    const float* bq = (const float*)d_in[2];
    const float* Wk = (const float*)d_in[3];
    const float* bk = (const float*)d_in[4];
    const float* Wv = (const float*)d_in[5];
    const float* bv = (const float*)d_in[6];
    const float* Wo = (const float*)d_in[7];
    const float* bo = (const float*)d_in[8];
    const float* gq = (const float*)d_in[9];
    const float* gk = (const float*)d_in[10];
    const float* ck = (const float*)d_in[11];
    const float* cv = (const float*)d_in[12];
    const float* fc = (const float*)d_in[13];
    const float* fs = (const float*)d_in[14];
    float* out = (float*)d_out;

    float *qb, *kb, *vb, *kf, *vf, *ob;
    cudaGetSymbolAddress((void**)&qb, d_qbuf);
    cudaGetSymbolAddress((void**)&kb, d_kbuf);
    cudaGetSymbolAddress((void**)&vb, d_vbuf);
    cudaGetSymbolAddress((void**)&kf, d_kfrag);
    cudaGetSymbolAddress((void**)&vf, d_vfrag);
    cudaGetSymbolAddress((void**)&ob, d_obuf);

    int gemm_smem = G_SMEM_U32 * (int)sizeof(uint32_t);
    cudaFuncSetAttribute(gemm3_bf16, cudaFuncAttributeMaxDynamicSharedMemorySize, gemm_smem);

    gemm3_bf16<<<dim3(36, 13), 256, gemm_smem>>>(
        x, Wq, Wk, Wv, bq, bk, bv, qb, kb, vb, S_LEN);

    rmsnorm_rope_q<<<S_LEN, 256>>>(qb, gq, fc, fs);
    rmsnorm_plain<<<S_LEN, 256>>>(kb, gk);

    build_kv_frag<<<dim3(NKT, NHEADS, 2), 256>>>(ck, cv, kb, vb, kf, vf, fc, fs);

    int attn_smem = ATTN_SMEM_U32 * (int)sizeof(uint32_t);
    cudaFuncSetAttribute(attn_tc, cudaFuncAttributeMaxDynamicSharedMemorySize, attn_smem);
    attn_tc<<<dim3((S_LEN + 63) / 64, NHEADS), 256, attn_smem>>>(qb, kf, vf, ob);

    gemm3_bf16<<<dim3(12, 13), 256, gemm_smem>>>(
        ob, Wo, Wo, Wo, bo, bo, bo, out, out, out, S_LEN);
}

// round 10
// speedup vs baseline: 3.5312x; 1.0910x over previous
#include <cuda_runtime.h>
#include <cuda_bf16.h>
#include <math.h>
#include <stdint.h>

#define DIM      1536
#define NHEADS   12
#define HDIM     128
#define S_LEN    1560
#define KV_LEN   9360
#define NKT      147            /* 64-row kv tiles */
#define FT       22
#define FSZ      21
#define WW       52
#define ALPHA_F  0.999f
#define BETA_F   0.001f
#define EPS_F    1e-6f
#define Q_FRAME  5
#define SCALE    0.08838834764831843f   /* 1/sqrt(128) */

// ---------------- scratch (device globals; no allocations allowed) ----------
__device__ float d_qbuf[S_LEN * DIM];
__device__ float d_kbuf[S_LEN * DIM];
__device__ float d_vbuf[S_LEN * DIM];
__device__ float d_kfrag[(size_t)NHEADS * NKT * 8192];
__device__ float d_vfrag[(size_t)NHEADS * NKT * 8192];
__device__ float d_obuf[S_LEN * DIM];

__device__ __forceinline__ uint32_t f2tf32(float f) {
    uint32_t r;
    asm("cvt.rna.tf32.f32 %0, %1;" : "=r"(r) : "f"(f));
    return r;
}
__device__ __forceinline__ float tf32r(float f) {
    uint32_t r = f2tf32(f);
    return __uint_as_float(r);
}
__device__ __forceinline__ float bfr(float v) {
    return __bfloat162float(__float2bfloat16_rn(v));
}
__device__ __forceinline__ uint32_t pkbf2(float lo, float hi) {
    __nv_bfloat162 t = __floats2bfloat162_rn(lo, hi);
    return *reinterpret_cast<uint32_t*>(&t);
}
__device__ __forceinline__ void cpa16(void* dst, const void* src) {
    uint32_t d = (uint32_t)__cvta_generic_to_shared(dst);
    asm volatile("cp.async.ca.shared.global [%0], [%1], 16;" :: "r"(d), "l"(src));
}

__device__ __forceinline__ void mma_tf32(
    float& c0, float& c1, float& c2, float& c3,
    uint32_t a0, uint32_t a1, uint32_t a2, uint32_t a3,
    uint32_t b0, uint32_t b1)
{
    asm volatile(
        "mma.sync.aligned.m16n8k8.row.col.f32.tf32.tf32.f32 "
        "{%0,%1,%2,%3},{%4,%5,%6,%7},{%8,%9},{%0,%1,%2,%3};"
        : "+f"(c0), "+f"(c1), "+f"(c2), "+f"(c3)
        : "r"(a0), "r"(a1), "r"(a2), "r"(a3), "r"(b0), "r"(b1));
}

__device__ __forceinline__ void mma_bf16(
    float* c, const uint4& a, const uint2& b)
{
    asm volatile(
        "mma.sync.aligned.m16n8k16.row.col.f32.bf16.bf16.f32 "
        "{%0,%1,%2,%3},{%4,%5,%6,%7},{%8,%9},{%0,%1,%2,%3};"
        : "+f"(c[0]), "+f"(c[1]), "+f"(c[2]), "+f"(c[3])
        : "r"(a.x), "r"(a.y), "r"(a.z), "r"(a.w), "r"(b.x), "r"(b.y));
}

// ============ bf16 3-term GEMM (unchanged) ==================================
#define G_AH 0
#define G_AL 4096
#define G_BH 8192
#define G_BL 12416
#define G_SMEM_U32 16640

__global__ __launch_bounds__(256, 2) void gemm3_bf16(
    const float* __restrict__ A,
    const float* __restrict__ W0, const float* __restrict__ W1, const float* __restrict__ W2,
    const float* __restrict__ b0, const float* __restrict__ b1, const float* __restrict__ b2,
    float* __restrict__ C0, float* __restrict__ C1, float* __restrict__ C2,
    int M)
{
    extern __shared__ uint32_t gsm[];
    uint32_t* AH = gsm + G_AH;
    uint32_t* AL = gsm + G_AL;
    uint32_t* BH = gsm + G_BH;
    uint32_t* BL = gsm + G_BL;

    const int sel = blockIdx.x / 12;
    const float* B    = (sel == 0) ? W0 : (sel == 1) ? W1 : W2;
    const float* bias = (sel == 0) ? b0 : (sel == 1) ? b1 : b2;
    float*       C    = (sel == 0) ? C0 : (sel == 1) ? C1 : C2;
    const int bn = (blockIdx.x - sel * 12) * 128;
    const int bm = blockIdx.y * 128;

    const int tid  = threadIdx.x;
    const int lane = tid & 31, wrp = tid >> 5;
    const int wm = wrp & 3, wn = wrp >> 2;
    const int g = lane >> 2, t4 = lane & 3;

    float acc[2][8][4];
    #pragma unroll
    for (int i = 0; i < 2; i++)
        #pragma unroll
        for (int j = 0; j < 8; j++)
            #pragma unroll
            for (int r = 0; r < 4; r++) acc[i][j][r] = 0.f;

    for (int k0 = 0; k0 < DIM; k0 += 64) {
        __syncthreads();
        #pragma unroll
        for (int it = 0; it < 8; it++) {
            int idx = tid + it * 256;
            int r = idx >> 4, c4 = idx & 15;
            int gr = bm + r;
            float4 v = (gr < M)
                ? *(const float4*)(A + (size_t)gr * DIM + k0 + c4 * 4)
                : make_float4(0.f, 0.f, 0.f, 0.f);
            int rl = r & 15, mtile = r >> 4;
            int ks = c4 >> 2, k8 = (c4 >> 1) & 1, t4a = (c4 & 1) * 2;
            int reg = (rl >> 3) + 2 * k8;
            int base = ks * 1024 + mtile * 128;
            int lane0 = (rl & 7) * 4 + t4a;
            float hx = bfr(v.x), hy = bfr(v.y), hz = bfr(v.z), hw = bfr(v.w);
            AH[base + lane0 * 4 + reg]       = pkbf2(hx, hy);
            AH[base + (lane0 + 1) * 4 + reg] = pkbf2(hz, hw);
            AL[base + lane0 * 4 + reg]       = pkbf2(v.x - hx, v.y - hy);
            AL[base + (lane0 + 1) * 4 + reg] = pkbf2(v.z - hz, v.w - hw);
        }
        #pragma unroll
        for (int it = 0; it < 4; it++) {
            int idx = tid + it * 256;
            int kp = idx >> 5, n4 = idx & 31;
            const float* bp = B + (size_t)(k0 + 2 * kp) * DIM + bn + n4 * 4;
            float4 u = *(const float4*)bp;
            float4 w = *(const float4*)(bp + DIM);
            int ks = kp >> 3, tb = kp & 3, reg = (kp >> 2) & 1;
            int base = ks * 1056;
            float uu[4] = {u.x, u.y, u.z, u.w};
            float ww[4] = {w.x, w.y, w.z, w.w};
            #pragma unroll
            for (int j = 0; j < 4; j++) {
                int n = n4 * 4 + j;
                int nt = n >> 3;
                int lb = (n & 7) * 4 + tb;
                float hu = bfr(uu[j]), hw2 = bfr(ww[j]);
                BH[base + nt * 66 + lb * 2 + reg] = pkbf2(hu, hw2);
                BL[base + nt * 66 + lb * 2 + reg] = pkbf2(uu[j] - hu, ww[j] - hw2);
            }
        }
        __syncthreads();

        #pragma unroll
        for (int ks = 0; ks < 4; ks++) {
            uint4 ah0 = *(const uint4*)&AH[ks * 1024 + (wm * 2 + 0) * 128 + lane * 4];
            uint4 ah1 = *(const uint4*)&AH[ks * 1024 + (wm * 2 + 1) * 128 + lane * 4];
            uint4 al0 = *(const uint4*)&AL[ks * 1024 + (wm * 2 + 0) * 128 + lane * 4];
            uint4 al1 = *(const uint4*)&AL[ks * 1024 + (wm * 2 + 1) * 128 + lane * 4];
            #pragma unroll
            for (int nf = 0; nf < 8; nf++) {
                int nt = wn * 8 + nf;
                uint2 bh = *(const uint2*)&BH[ks * 1056 + nt * 66 + lane * 2];
                uint2 bl = *(const uint2*)&BL[ks * 1056 + nt * 66 + lane * 2];
                mma_bf16(acc[0][nf], ah0, bh);
                mma_bf16(acc[1][nf], ah1, bh);
                mma_bf16(acc[0][nf], al0, bh);
                mma_bf16(acc[1][nf], al1, bh);
                mma_bf16(acc[0][nf], ah0, bl);
                mma_bf16(acc[1][nf], ah1, bl);
            }
        }
    }

    #pragma unroll
    for (int nf = 0; nf < 8; nf++) {
        int cn = bn + wn * 64 + nf * 8 + 2 * t4;
        float2 bv = *(const float2*)(bias + cn);
        #pragma unroll
        for (int mf = 0; mf < 2; mf++) {
            int r0 = bm + wm * 32 + mf * 16 + g;
            if (r0 < M) {
                float2 o = make_float2(acc[mf][nf][0] + bv.x, acc[mf][nf][1] + bv.y);
                *(float2*)(C + (size_t)r0 * DIM + cn) = o;
            }
            if (r0 + 8 < M) {
                float2 o = make_float2(acc[mf][nf][2] + bv.x, acc[mf][nf][3] + bv.y);
                *(float2*)(C + (size_t)(r0 + 8) * DIM + cn) = o;
            }
        }
    }
}

// ---------------- rmsnorm (+rope for q) ------------------------------------
__device__ __forceinline__ float block_rms_scale(const float* row, float* red)
{
    float ss = 0.f;
    for (int i = threadIdx.x; i < DIM; i += 256) { float v = row[i]; ss += v * v; }
    #pragma unroll
    for (int o = 16; o; o >>= 1) ss += __shfl_xor_sync(0xffffffffu, ss, o);
    if ((threadIdx.x & 31) == 0) red[threadIdx.x >> 5] = ss;
    __syncthreads();
    if (threadIdx.x == 0) {
        float tot = 0.f;
        #pragma unroll
        for (int i = 0; i < 8; i++) tot += red[i];
        red[0] = rsqrtf(tot / (float)DIM + EPS_F);
    }
    __syncthreads();
    return red[0];
}

__global__ __launch_bounds__(256) void rmsnorm_rope_q(
    float* __restrict__ q, const float* __restrict__ g,
    const float* __restrict__ fc, const float* __restrict__ fs)
{
    __shared__ float red[8];
    int t = blockIdx.x;
    float* row = q + (size_t)t * DIM;
    float scale = block_rms_scale(row, red);
    int h = t / WW, w = t % WW;
    for (int p = threadIdx.x; p < DIM / 2; p += 256) {
        int c = p & 63;
        int ridx = (c < FT) ? Q_FRAME : ((c < FT + FSZ) ? h : w);
        float cs = fc[ridx * 64 + c], sn = fs[ridx * 64 + c];
        float a = row[2*p]   * scale * g[2*p];
        float b = row[2*p+1] * scale * g[2*p+1];
        row[2*p]   = tf32r(a * cs - b * sn);
        row[2*p+1] = tf32r(a * sn + b * cs);
    }
}

__global__ __launch_bounds__(256) void rmsnorm_plain(
    float* __restrict__ k, const float* __restrict__ g)
{
    __shared__ float red[8];
    int t = blockIdx.x;
    float* row = k + (size_t)t * DIM;
    float scale = block_rms_scale(row, red);
    for (int i = threadIdx.x; i < DIM; i += 256)
        row[i] = row[i] * scale * g[i];
}

// ------ build combined KV directly in mma-fragment order (unchanged) -------
__device__ __forceinline__ const float* kv_src(
    int R, const float* __restrict__ cc, const float* __restrict__ nn,
    const float** s2)
{
    *s2 = nullptr;
    if (R < 1560) { *s2 = cc + (size_t)(9360 + R) * DIM; return cc + (size_t)R * DIM; }
    if (R < 7800) return cc + (size_t)(R + 3120) * DIM;
    return nn + (size_t)(R - 7800) * DIM;
}

__global__ __launch_bounds__(256) void build_kv_frag(
    const float* __restrict__ ck, const float* __restrict__ cv,
    const float* __restrict__ kn, const float* __restrict__ vn,
    float* __restrict__ kf, float* __restrict__ vf,
    const float* __restrict__ fc, const float* __restrict__ fs)
{
    const int tile = blockIdx.x, head = blockIdx.y;
    const int tid = threadIdx.x;
    float* dst = (blockIdx.z ? vf : kf) + ((size_t)head * NKT + tile) * 8192;

    if (blockIdx.z == 0) {
        #pragma unroll
        for (int it = 0; it < 4; it++) {
            int t = tid + it * 256;
            int ks = t >> 6;
            int rowT = ((t >> 3) & 7) * 8 + (t & 7);
            int k0 = ks * 8;
            int R = tile * 64 + rowT;
            float pr[8] = {0.f,0.f,0.f,0.f,0.f,0.f,0.f,0.f};
            if (R < KV_LEN) {
                const float* s2;
                const float* s1 = kv_src(R, ck, kn, &s2);
                float4 a = *(const float4*)(s1 + head * HDIM + k0);
                float4 b4 = *(const float4*)(s1 + head * HDIM + k0 + 4);
                if (s2) {
                    float4 a2 = *(const float4*)(s2 + head * HDIM + k0);
                    float4 b2 = *(const float4*)(s2 + head * HDIM + k0 + 4);
                    a.x = ALPHA_F*a.x + BETA_F*a2.x; a.y = ALPHA_F*a.y + BETA_F*a2.y;
                    a.z = ALPHA_F*a.z + BETA_F*a2.z; a.w = ALPHA_F*a.w + BETA_F*a2.w;
                    b4.x = ALPHA_F*b4.x + BETA_F*b2.x; b4.y = ALPHA_F*b4.y + BETA_F*b2.y;
                    b4.z = ALPHA_F*b4.z + BETA_F*b2.z; b4.w = ALPHA_F*b4.w + BETA_F*b2.w;
                }
                float raw[8] = {a.x, a.y, a.z, a.w, b4.x, b4.y, b4.z, b4.w};
                int fr = R / 1560, pp = R % 1560, hh = pp / WW, wc = pp % WW;
                #pragma unroll
                for (int j = 0; j < 4; j++) {
                    int c = ks * 4 + j;
                    int ridx = (c < FT) ? fr : ((c < FT + FSZ) ? hh : wc);
                    float cs = fc[ridx * 64 + c], sn = fs[ridx * 64 + c];
                    float x = raw[2*j], y = raw[2*j + 1];
                    pr[2*j]     = tf32r(x * cs - y * sn);
                    pr[2*j + 1] = tf32r(x * sn + y * cs);
                }
            }
            *(float4*)(dst + t * 8)     = make_float4(pr[0], pr[4], pr[1], pr[5]);
            *(float4*)(dst + t * 8 + 4) = make_float4(pr[2], pr[6], pr[3], pr[7]);
        }
    } else {
        #pragma unroll
        for (int it = 0; it < 8; it++) {
            int idx = (tid + it * 256) * 4;
            int ks = idx >> 10, rem = idx & 1023;
            int nt = rem >> 6, w = rem & 63;
            int dd = w >> 3, w2b = w & 7;
            int d = nt * 8 + dd;
            float out[4];
            #pragma unroll
            for (int j = 0; j < 4; j++) {
                int w2 = w2b + j;
                int r7 = (w2 >> 1) + ((w2 & 1) << 2);
                int R = tile * 64 + ks * 8 + r7;
                float v = 0.f;
                if (R < KV_LEN) {
                    const float* s2;
                    const float* s1 = kv_src(R, cv, vn, &s2);
                    v = s1[head * HDIM + d];
                    if (s2) v = ALPHA_F * v + BETA_F * s2[head * HDIM + d];
                }
                out[j] = tf32r(v);
            }
            *(float4*)(dst + idx) = make_float4(out[0], out[1], out[2], out[3]);
        }
    }
}

// ===== tf32 flash attention: 64-q CTA / 128 thr, warp-local softmax ========
// 4 warps; warp mt owns rows 16*mt..16*mt+15 x ALL 64 cols -> softmax is
// register+shfl only. PA is a separate warp-private region (no aliasing
// barrier). 2 CTAs/SM hide the K/V load latency; grid 25x12=300 balanced.
#define QA_ST 516
#define PA_ST 516
#define QA_OFF 0                          /* 16*516 = 8256 */
#define KB_OFF 8256                       /* 8192 */
#define VB_OFF (KB_OFF + 8192)            /* 8192 */
#define PA_OFF (VB_OFF + 8192)            /* 8*516 = 4128 */
#define ATTN_SMEM_U32 (PA_OFF + 4128)     /* 28768 w = 115072 B */

__global__ __launch_bounds__(128, 2) void attn_tc(
    const float* __restrict__ Q, const float* __restrict__ Kf,
    const float* __restrict__ Vf, float* __restrict__ Oo)
{
    extern __shared__ uint32_t sm[];
    uint32_t* QA = sm + QA_OFF;
    uint32_t* KB = sm + KB_OFF;
    uint32_t* VB = sm + VB_OFF;
    uint32_t* PA = sm + PA_OFF;

    const int q0   = blockIdx.x * 64;
    const int head = blockIdx.y;
    const int tid  = threadIdx.x;
    const int lane = tid & 31;
    const int mt   = tid >> 5;        // warp owns rows 16*mt..16*mt+15
    const int g    = lane >> 2;
    const int t4   = lane & 3;

    // ---- Q (64 rows) -> QA fragments (once) ----
    for (int idx = tid; idx < 64 * 32; idx += 128) {
        int r = idx >> 5, d4 = idx & 31;
        int k = d4 * 4;
        int gq = q0 + r;
        float4 v = (gq < S_LEN)
            ? *(const float4*)(Q + (size_t)gq * DIM + head * HDIM + k)
            : make_float4(0.f, 0.f, 0.f, 0.f);
        int ks = d4 >> 1;
        int khi = (d4 & 1) * 2;
        int rl = r & 15;
        int reg = ((rl >= 8) ? 1 : 0) + khi;
        int ln = (rl & 7) * 4;
        uint32_t* base = QA + ks * QA_ST + (r >> 4) * 128;
        base[(ln + 0) * 4 + reg] = __float_as_uint(v.x);
        base[(ln + 1) * 4 + reg] = __float_as_uint(v.y);
        base[(ln + 2) * 4 + reg] = __float_as_uint(v.z);
        base[(ln + 3) * 4 + reg] = __float_as_uint(v.w);
    }

    float m0 = -INFINITY, m1 = -INFINITY;
    float l0 = 0.f, l1 = 0.f;
    float O[16][4];
    #pragma unroll
    for (int i = 0; i < 16; i++)
        #pragma unroll
        for (int j = 0; j < 4; j++) O[i][j] = 0.f;

    for (int kt = 0; kt < NKT; kt++) {
        const int kt0 = kt * 64;

        // ---- load K then V (V wait deferred past QK + softmax) ----
        const float* kfp = Kf + ((size_t)head * NKT + kt) * 8192;
        const float* vfp = Vf + ((size_t)head * NKT + kt) * 8192;
        #pragma unroll
        for (int it = 0; it < 16; it++) {
            int idx = (tid + it * 128) * 4;
            cpa16(KB + idx, kfp + idx);
        }
        asm volatile("cp.async.commit_group;");
        #pragma unroll
        for (int it = 0; it < 16; it++) {
            int idx = (tid + it * 128) * 4;
            cpa16(VB + idx, vfp + idx);
        }
        asm volatile("cp.async.commit_group;");
        asm volatile("cp.async.wait_group 1;");   // K resident
        __syncthreads();                          // K visible (covers Q store on kt=0)

        // ---- S = Q K^T  (warp tile 16 x 64) ----
        float Sc[8][4];
        #pragma unroll
        for (int i = 0; i < 8; i++)
            #pragma unroll
            for (int j = 0; j < 4; j++) Sc[i][j] = 0.f;

        #pragma unroll
        for (int ks = 0; ks < 16; ks++) {
            uint4 a = *(const uint4*)(QA + ks * QA_ST + mt * 128 + lane * 4);
            #pragma unroll
            for (int nt = 0; nt < 8; nt++) {
                uint2 b = *(const uint2*)(KB + ks * 512 + nt * 64 + lane * 2);
                mma_tf32(Sc[nt][0], Sc[nt][1], Sc[nt][2], Sc[nt][3],
                         a.x, a.y, a.z, a.w, b.x, b.y);
            }
        }

        // ---- scale + mask + warp-local row max ----
        float pm0 = -INFINITY, pm1 = -INFINITY;
        #pragma unroll
        for (int nt = 0; nt < 8; nt++) {
            int cbase = nt * 8 + 2 * t4;
            #pragma unroll
            for (int j = 0; j < 4; j++) {
                int c = cbase + (j & 1);
                bool valid = (kt0 + c) < KV_LEN;
                Sc[nt][j] = valid ? Sc[nt][j] * SCALE : -1e30f;
            }
            pm0 = fmaxf(pm0, fmaxf(Sc[nt][0], Sc[nt][1]));
            pm1 = fmaxf(pm1, fmaxf(Sc[nt][2], Sc[nt][3]));
        }
        pm0 = fmaxf(pm0, __shfl_xor_sync(0xffffffffu, pm0, 1));
        pm0 = fmaxf(pm0, __shfl_xor_sync(0xffffffffu, pm0, 2));
        pm1 = fmaxf(pm1, __shfl_xor_sync(0xffffffffu, pm1, 1));
        pm1 = fmaxf(pm1, __shfl_xor_sync(0xffffffffu, pm1, 2));

        float m0n = fmaxf(m0, pm0);
        float m1n = fmaxf(m1, pm1);

        // ---- exp + PA store (warp-private, no barrier) + row sums ----
        float s0 = 0.f, s1 = 0.f;
        #pragma unroll
        for (int nt = 0; nt < 8; nt++) {
            uint32_t* base = PA + nt * PA_ST + mt * 128;
            #pragma unroll
            for (int j = 0; j < 4; j++) {
                float e = __expf(Sc[nt][j] - ((j < 2) ? m0n : m1n));
                if (j < 2) s0 += e; else s1 += e;
                int c = 2 * t4 + (j & 1);
                int rl = (j < 2) ? g : (g + 8);
                int reg = ((rl >= 8) ? 1 : 0) + ((c >= 4) ? 2 : 0);
                base[((rl & 7) * 4 + (c & 3)) * 4 + reg] = f2tf32(e);
            }
        }
        s0 += __shfl_xor_sync(0xffffffffu, s0, 1);
        s0 += __shfl_xor_sync(0xffffffffu, s0, 2);
        s1 += __shfl_xor_sync(0xffffffffu, s1, 1);
        s1 += __shfl_xor_sync(0xffffffffu, s1, 2);

        float alpha0 = __expf(m0 - m0n);
        float alpha1 = __expf(m1 - m1n);
        l0 = l0 * alpha0 + s0;
        l1 = l1 * alpha1 + s1;
        m0 = m0n; m1 = m1n;

        #pragma unroll
        for (int nt = 0; nt < 16; nt++) {
            O[nt][0] *= alpha0; O[nt][1] *= alpha0;
            O[nt][2] *= alpha1; O[nt][3] *= alpha1;
        }

        asm volatile("cp.async.wait_group 0;");   // V resident
        __syncthreads();                          // V visible

        // ---- O += P V  (warp tile 16 x 128; PA warp-local) ----
        #pragma unroll
        for (int ks = 0; ks < 8; ks++) {
            uint4 a = *(const uint4*)(PA + ks * PA_ST + mt * 128 + lane * 4);
            #pragma unroll
            for (int nt = 0; nt < 16; nt++) {
                uint2 b = *(const uint2*)(VB + ks * 1024 + nt * 64 + lane * 2);
                mma_tf32(O[nt][0], O[nt][1], O[nt][2], O[nt][3],
                         a.x, a.y, a.z, a.w, b.x, b.y);
            }
        }
        __syncthreads();   // all KB/VB reads done before next tile overwrites
    }

    // ---- finalize ----
    float inv0 = 1.f / l0, inv1 = 1.f / l1;
    int gr0 = q0 + 16 * mt + g;
    int gr1 = gr0 + 8;
    #pragma unroll
    for (int nt = 0; nt < 16; nt++) {
        int c = nt * 8 + 2 * t4;
        if (gr0 < S_LEN) {
            float2 o0 = make_float2(O[nt][0] * inv0, O[nt][1] * inv0);
            *(float2*)(Oo + (size_t)gr0 * DIM + head * HDIM + c) = o0;
        }
        if (gr1 < S_LEN) {
            float2 o1 = make_float2(O[nt][2] * inv1, O[nt][3] * inv1);
            *(float2*)(Oo + (size_t)gr1 * DIM + head * HDIM + c) = o1;
        }
    }
}

// ---------------- launch -----------------------------------------------------
extern "C" void kernel_launch(void* const* d_in, const int* in_sizes, int n_in,
                              void* d_out, int out_size)
{
    const float* x  = (const float*)d_in[0];
    const float* Wq = (const float*)d_in[1];
    const float* bq = (const float*)d_in[2];
    const float* Wk = (const float*)d_in[3];
    const float* bk = (const float*)d_in[4];
    const float* Wv = (const float*)d_in[5];
    const float* bv = (const float*)d_in[6];
    const float* Wo = (const float*)d_in[7];
    const float* bo = (const float*)d_in[8];
    const float* gq = (const float*)d_in[9];
    const float* gk = (const float*)d_in[10];
    const float* ck = (const float*)d_in[11];
    const float* cv = (const float*)d_in[12];
    const float* fc = (const float*)d_in[13];
    const float* fs = (const float*)d_in[14];
    float* out = (float*)d_out;

    float *qb, *kb, *vb, *kf, *vf, *ob;
    cudaGetSymbolAddress((void**)&qb, d_qbuf);
    cudaGetSymbolAddress((void**)&kb, d_kbuf);
    cudaGetSymbolAddress((void**)&vb, d_vbuf);
    cudaGetSymbolAddress((void**)&kf, d_kfrag);
    cudaGetSymbolAddress((void**)&vf, d_vfrag);
    cudaGetSymbolAddress((void**)&ob, d_obuf);

    int gemm_smem = G_SMEM_U32 * (int)sizeof(uint32_t);
    cudaFuncSetAttribute(gemm3_bf16, cudaFuncAttributeMaxDynamicSharedMemorySize, gemm_smem);

    gemm3_bf16<<<dim3(36, 13), 256, gemm_smem>>>(
        x, Wq, Wk, Wv, bq, bk, bv, qb, kb, vb, S_LEN);

    rmsnorm_rope_q<<<S_LEN, 256>>>(qb, gq, fc, fs);
    rmsnorm_plain<<<S_LEN, 256>>>(kb, gk);

    build_kv_frag<<<dim3(NKT, NHEADS, 2), 256>>>(ck, cv, kb, vb, kf, vf, fc, fs);

    int attn_smem = ATTN_SMEM_U32 * (int)sizeof(uint32_t);
    cudaFuncSetAttribute(attn_tc, cudaFuncAttributeMaxDynamicSharedMemorySize, attn_smem);
    attn_tc<<<dim3((S_LEN + 63) / 64, NHEADS), 128, attn_smem>>>(qb, kf, vf, ob);

    gemm3_bf16<<<dim3(12, 13), 256, gemm_smem>>>(
        ob, Wo, Wo, Wo, bo, bo, bo, out, out, out, S_LEN);
}

// round 12
// speedup vs baseline: 3.5855x; 1.0154x over previous
#include <cuda_runtime.h>
#include <cuda_bf16.h>
#include <math.h>
#include <stdint.h>

#define DIM      1536
#define NHEADS   12
#define HDIM     128
#define S_LEN    1560
#define KV_LEN   9360
#define NKT      147            /* 64-row kv tiles */
#define FT       22
#define FSZ      21
#define WW       52
#define ALPHA_F  0.999f
#define BETA_F   0.001f
#define EPS_F    1e-6f
#define Q_FRAME  5
#define SCALE    0.08838834764831843f      /* 1/sqrt(128) */
#define SCALE2   0.12752476815166922f      /* SCALE * log2(e) */

// ---------------- scratch (device globals; no allocations allowed) ----------
__device__ float d_qbuf[S_LEN * DIM];
__device__ float d_kbuf[S_LEN * DIM];
__device__ float d_vbuf[S_LEN * DIM];
__device__ float d_kfrag[(size_t)NHEADS * NKT * 8192];
__device__ float d_vfrag[(size_t)NHEADS * NKT * 8192];
__device__ float d_obuf[S_LEN * DIM];

__device__ __forceinline__ uint32_t f2tf32(float f) {
    uint32_t r;
    asm("cvt.rna.tf32.f32 %0, %1;" : "=r"(r) : "f"(f));
    return r;
}
__device__ __forceinline__ float tf32r(float f) {
    uint32_t r = f2tf32(f);
    return __uint_as_float(r);
}
__device__ __forceinline__ float bfr(float v) {
    return __bfloat162float(__float2bfloat16_rn(v));
}
__device__ __forceinline__ uint32_t pkbf2(float lo, float hi) {
    __nv_bfloat162 t = __floats2bfloat162_rn(lo, hi);
    return *reinterpret_cast<uint32_t*>(&t);
}
__device__ __forceinline__ void cpa16(void* dst, const void* src) {
    uint32_t d = (uint32_t)__cvta_generic_to_shared(dst);
    asm volatile("cp.async.ca.shared.global [%0], [%1], 16;" :: "r"(d), "l"(src));
}

__device__ __forceinline__ void mma_tf32(
    float& c0, float& c1, float& c2, float& c3,
    uint32_t a0, uint32_t a1, uint32_t a2, uint32_t a3,
    uint32_t b0, uint32_t b1)
{
    asm volatile(
        "mma.sync.aligned.m16n8k8.row.col.f32.tf32.tf32.f32 "
        "{%0,%1,%2,%3},{%4,%5,%6,%7},{%8,%9},{%0,%1,%2,%3};"
        : "+f"(c0), "+f"(c1), "+f"(c2), "+f"(c3)
        : "r"(a0), "r"(a1), "r"(a2), "r"(a3), "r"(b0), "r"(b1));
}

__device__ __forceinline__ void mma_bf16(
    float* c, const uint4& a, const uint2& b)
{
    asm volatile(
        "mma.sync.aligned.m16n8k16.row.col.f32.bf16.bf16.f32 "
        "{%0,%1,%2,%3},{%4,%5,%6,%7},{%8,%9},{%0,%1,%2,%3};"
        : "+f"(c[0]), "+f"(c[1]), "+f"(c[2]), "+f"(c[3])
        : "r"(a.x), "r"(a.y), "r"(a.z), "r"(a.w), "r"(b.x), "r"(b.y));
}

// ============ bf16 3-term GEMM (unchanged) ==================================
#define G_AH 0
#define G_AL 4096
#define G_BH 8192
#define G_BL 12416
#define G_SMEM_U32 16640

__global__ __launch_bounds__(256, 2) void gemm3_bf16(
    const float* __restrict__ A,
    const float* __restrict__ W0, const float* __restrict__ W1, const float* __restrict__ W2,
    const float* __restrict__ b0, const float* __restrict__ b1, const float* __restrict__ b2,
    float* __restrict__ C0, float* __restrict__ C1, float* __restrict__ C2,
    int M)
{
    extern __shared__ uint32_t gsm[];
    uint32_t* AH = gsm + G_AH;
    uint32_t* AL = gsm + G_AL;
    uint32_t* BH = gsm + G_BH;
    uint32_t* BL = gsm + G_BL;

    const int sel = blockIdx.x / 12;
    const float* B    = (sel == 0) ? W0 : (sel == 1) ? W1 : W2;
    const float* bias = (sel == 0) ? b0 : (sel == 1) ? b1 : b2;
    float*       C    = (sel == 0) ? C0 : (sel == 1) ? C1 : C2;
    const int bn = (blockIdx.x - sel * 12) * 128;
    const int bm = blockIdx.y * 128;

    const int tid  = threadIdx.x;
    const int lane = tid & 31, wrp = tid >> 5;
    const int wm = wrp & 3, wn = wrp >> 2;
    const int g = lane >> 2, t4 = lane & 3;

    float acc[2][8][4];
    #pragma unroll
    for (int i = 0; i < 2; i++)
        #pragma unroll
        for (int j = 0; j < 8; j++)
            #pragma unroll
            for (int r = 0; r < 4; r++) acc[i][j][r] = 0.f;

    for (int k0 = 0; k0 < DIM; k0 += 64) {
        __syncthreads();
        #pragma unroll
        for (int it = 0; it < 8; it++) {
            int idx = tid + it * 256;
            int r = idx >> 4, c4 = idx & 15;
            int gr = bm + r;
            float4 v = (gr < M)
                ? *(const float4*)(A + (size_t)gr * DIM + k0 + c4 * 4)
                : make_float4(0.f, 0.f, 0.f, 0.f);
            int rl = r & 15, mtile = r >> 4;
            int ks = c4 >> 2, k8 = (c4 >> 1) & 1, t4a = (c4 & 1) * 2;
            int reg = (rl >> 3) + 2 * k8;
            int base = ks * 1024 + mtile * 128;
            int lane0 = (rl & 7) * 4 + t4a;
            float hx = bfr(v.x), hy = bfr(v.y), hz = bfr(v.z), hw = bfr(v.w);
            AH[base + lane0 * 4 + reg]       = pkbf2(hx, hy);
            AH[base + (lane0 + 1) * 4 + reg] = pkbf2(hz, hw);
            AL[base + lane0 * 4 + reg]       = pkbf2(v.x - hx, v.y - hy);
            AL[base + (lane0 + 1) * 4 + reg] = pkbf2(v.z - hz, v.w - hw);
        }
        #pragma unroll
        for (int it = 0; it < 4; it++) {
            int idx = tid + it * 256;
            int kp = idx >> 5, n4 = idx & 31;
            const float* bp = B + (size_t)(k0 + 2 * kp) * DIM + bn + n4 * 4;
            float4 u = *(const float4*)bp;
            float4 w = *(const float4*)(bp + DIM);
            int ks = kp >> 3, tb = kp & 3, reg = (kp >> 2) & 1;
            int base = ks * 1056;
            float uu[4] = {u.x, u.y, u.z, u.w};
            float ww[4] = {w.x, w.y, w.z, w.w};
            #pragma unroll
            for (int j = 0; j < 4; j++) {
                int n = n4 * 4 + j;
                int nt = n >> 3;
                int lb = (n & 7) * 4 + tb;
                float hu = bfr(uu[j]), hw2 = bfr(ww[j]);
                BH[base + nt * 66 + lb * 2 + reg] = pkbf2(hu, hw2);
                BL[base + nt * 66 + lb * 2 + reg] = pkbf2(uu[j] - hu, ww[j] - hw2);
            }
        }
        __syncthreads();

        #pragma unroll
        for (int ks = 0; ks < 4; ks++) {
            uint4 ah0 = *(const uint4*)&AH[ks * 1024 + (wm * 2 + 0) * 128 + lane * 4];
            uint4 ah1 = *(const uint4*)&AH[ks * 1024 + (wm * 2 + 1) * 128 + lane * 4];
            uint4 al0 = *(const uint4*)&AL[ks * 1024 + (wm * 2 + 0) * 128 + lane * 4];
            uint4 al1 = *(const uint4*)&AL[ks * 1024 + (wm * 2 + 1) * 128 + lane * 4];
            #pragma unroll
            for (int nf = 0; nf < 8; nf++) {
                int nt = wn * 8 + nf;
                uint2 bh = *(const uint2*)&BH[ks * 1056 + nt * 66 + lane * 2];
                uint2 bl = *(const uint2*)&BL[ks * 1056 + nt * 66 + lane * 2];
                mma_bf16(acc[0][nf], ah0, bh);
                mma_bf16(acc[1][nf], ah1, bh);
                mma_bf16(acc[0][nf], al0, bh);
                mma_bf16(acc[1][nf], al1, bh);
                mma_bf16(acc[0][nf], ah0, bl);
                mma_bf16(acc[1][nf], ah1, bl);
            }
        }
    }

    #pragma unroll
    for (int nf = 0; nf < 8; nf++) {
        int cn = bn + wn * 64 + nf * 8 + 2 * t4;
        float2 bv = *(const float2*)(bias + cn);
        #pragma unroll
        for (int mf = 0; mf < 2; mf++) {
            int r0 = bm + wm * 32 + mf * 16 + g;
            if (r0 < M) {
                float2 o = make_float2(acc[mf][nf][0] + bv.x, acc[mf][nf][1] + bv.y);
                *(float2*)(C + (size_t)r0 * DIM + cn) = o;
            }
            if (r0 + 8 < M) {
                float2 o = make_float2(acc[mf][nf][2] + bv.x, acc[mf][nf][3] + bv.y);
                *(float2*)(C + (size_t)(r0 + 8) * DIM + cn) = o;
            }
        }
    }
}

// ---------------- rmsnorm (+rope for q) ------------------------------------
__device__ __forceinline__ float block_rms_scale(const float* row, float* red)
{
    float ss = 0.f;
    for (int i = threadIdx.x; i < DIM; i += 256) { float v = row[i]; ss += v * v; }
    #pragma unroll
    for (int o = 16; o; o >>= 1) ss += __shfl_xor_sync(0xffffffffu, ss, o);
    if ((threadIdx.x & 31) == 0) red[threadIdx.x >> 5] = ss;
    __syncthreads();
    if (threadIdx.x == 0) {
        float tot = 0.f;
        #pragma unroll
        for (int i = 0; i < 8; i++) tot += red[i];
        red[0] = rsqrtf(tot / (float)DIM + EPS_F);
    }
    __syncthreads();
    return red[0];
}

__global__ __launch_bounds__(256) void rmsnorm_rope_q(
    float* __restrict__ q, const float* __restrict__ g,
    const float* __restrict__ fc, const float* __restrict__ fs)
{
    __shared__ float red[8];
    int t = blockIdx.x;
    float* row = q + (size_t)t * DIM;
    float scale = block_rms_scale(row, red);
    int h = t / WW, w = t % WW;
    for (int p = threadIdx.x; p < DIM / 2; p += 256) {
        int c = p & 63;
        int ridx = (c < FT) ? Q_FRAME : ((c < FT + FSZ) ? h : w);
        float cs = fc[ridx * 64 + c], sn = fs[ridx * 64 + c];
        float a = row[2*p]   * scale * g[2*p];
        float b = row[2*p+1] * scale * g[2*p+1];
        row[2*p]   = tf32r(a * cs - b * sn);
        row[2*p+1] = tf32r(a * sn + b * cs);
    }
}

__global__ __launch_bounds__(256) void rmsnorm_plain(
    float* __restrict__ k, const float* __restrict__ g)
{
    __shared__ float red[8];
    int t = blockIdx.x;
    float* row = k + (size_t)t * DIM;
    float scale = block_rms_scale(row, red);
    for (int i = threadIdx.x; i < DIM; i += 256)
        row[i] = row[i] * scale * g[i];
}

// ------ build combined KV directly in mma-fragment order (unchanged) -------
__device__ __forceinline__ const float* kv_src(
    int R, const float* __restrict__ cc, const float* __restrict__ nn,
    const float** s2)
{
    *s2 = nullptr;
    if (R < 1560) { *s2 = cc + (size_t)(9360 + R) * DIM; return cc + (size_t)R * DIM; }
    if (R < 7800) return cc + (size_t)(R + 3120) * DIM;
    return nn + (size_t)(R - 7800) * DIM;
}

__global__ __launch_bounds__(256) void build_kv_frag(
    const float* __restrict__ ck, const float* __restrict__ cv,
    const float* __restrict__ kn, const float* __restrict__ vn,
    float* __restrict__ kf, float* __restrict__ vf,
    const float* __restrict__ fc, const float* __restrict__ fs)
{
    const int tile = blockIdx.x, head = blockIdx.y;
    const int tid = threadIdx.x;
    float* dst = (blockIdx.z ? vf : kf) + ((size_t)head * NKT + tile) * 8192;

    if (blockIdx.z == 0) {
        #pragma unroll
        for (int it = 0; it < 4; it++) {
            int t = tid + it * 256;
            int ks = t >> 6;
            int rowT = ((t >> 3) & 7) * 8 + (t & 7);
            int k0 = ks * 8;
            int R = tile * 64 + rowT;
            float pr[8] = {0.f,0.f,0.f,0.f,0.f,0.f,0.f,0.f};
            if (R < KV_LEN) {
                const float* s2;
                const float* s1 = kv_src(R, ck, kn, &s2);
                float4 a = *(const float4*)(s1 + head * HDIM + k0);
                float4 b4 = *(const float4*)(s1 + head * HDIM + k0 + 4);
                if (s2) {
                    float4 a2 = *(const float4*)(s2 + head * HDIM + k0);
                    float4 b2 = *(const float4*)(s2 + head * HDIM + k0 + 4);
                    a.x = ALPHA_F*a.x + BETA_F*a2.x; a.y = ALPHA_F*a.y + BETA_F*a2.y;
                    a.z = ALPHA_F*a.z + BETA_F*a2.z; a.w = ALPHA_F*a.w + BETA_F*a2.w;
                    b4.x = ALPHA_F*b4.x + BETA_F*b2.x; b4.y = ALPHA_F*b4.y + BETA_F*b2.y;
                    b4.z = ALPHA_F*b4.z + BETA_F*b2.z; b4.w = ALPHA_F*b4.w + BETA_F*b2.w;
                }
                float raw[8] = {a.x, a.y, a.z, a.w, b4.x, b4.y, b4.z, b4.w};
                int fr = R / 1560, pp = R % 1560, hh = pp / WW, wc = pp % WW;
                #pragma unroll
                for (int j = 0; j < 4; j++) {
                    int c = ks * 4 + j;
                    int ridx = (c < FT) ? fr : ((c < FT + FSZ) ? hh : wc);
                    float cs = fc[ridx * 64 + c], sn = fs[ridx * 64 + c];
                    float x = raw[2*j], y = raw[2*j + 1];
                    pr[2*j]     = tf32r(x * cs - y * sn);
                    pr[2*j + 1] = tf32r(x * sn + y * cs);
                }
            }
            *(float4*)(dst + t * 8)     = make_float4(pr[0], pr[4], pr[1], pr[5]);
            *(float4*)(dst + t * 8 + 4) = make_float4(pr[2], pr[6], pr[3], pr[7]);
        }
    } else {
        #pragma unroll
        for (int it = 0; it < 8; it++) {
            int idx = (tid + it * 256) * 4;
            int ks = idx >> 10, rem = idx & 1023;
            int nt = rem >> 6, w = rem & 63;
            int dd = w >> 3, w2b = w & 7;
            int d = nt * 8 + dd;
            float out[4];
            #pragma unroll
            for (int j = 0; j < 4; j++) {
                int w2 = w2b + j;
                int r7 = (w2 >> 1) + ((w2 & 1) << 2);
                int R = tile * 64 + ks * 8 + r7;
                float v = 0.f;
                if (R < KV_LEN) {
                    const float* s2;
                    const float* s1 = kv_src(R, cv, vn, &s2);
                    v = s1[head * HDIM + d];
                    if (s2) v = ALPHA_F * v + BETA_F * s2[head * HDIM + d];
                }
                out[j] = tf32r(v);
            }
            *(float4*)(dst + idx) = make_float4(out[0], out[1], out[2], out[3]);
        }
    }
}

// ===== tf32 flash attention: Q in regs, K dbl-buffer pipeline, log2 softmax =
// smem: KB[2] (16384 w) | VB (8192 w) | PA (4128 w)  = 114816 B, 2 CTAs/SM.
// Q staged once through a region aliasing KB[1] (dead until K1 arrives).
#define KB_OFF 0
#define VB_OFF 16384
#define PA_OFF (VB_OFF + 8192)           /* 24576 */
#define PA_ST  516
#define QS_OFF 8192                       /* staging: aliases KB[1], 8256 w */
#define QS_ST  516
#define ATTN_SMEM_U32 (PA_OFF + 4128)     /* 28704 w = 114816 B */

__global__ __launch_bounds__(128, 2) void attn_tc(
    const float* __restrict__ Q, const float* __restrict__ Kf,
    const float* __restrict__ Vf, float* __restrict__ Oo)
{
    extern __shared__ uint32_t sm[];
    uint32_t* VB = sm + VB_OFF;
    uint32_t* PA = sm + PA_OFF;

    const int q0   = blockIdx.x * 64;
    const int head = blockIdx.y;
    const int tid  = threadIdx.x;
    const int lane = tid & 31;
    const int mt   = tid >> 5;
    const int g    = lane >> 2;
    const int t4   = lane & 3;

    // ---- stage Q into aliased smem region, then pull fragments to registers
    {
        uint32_t* QS = sm + QS_OFF;
        for (int idx = tid; idx < 64 * 32; idx += 128) {
            int r = idx >> 5, d4 = idx & 31;
            int k = d4 * 4;
            int gq = q0 + r;
            float4 v = (gq < S_LEN)
                ? *(const float4*)(Q + (size_t)gq * DIM + head * HDIM + k)
                : make_float4(0.f, 0.f, 0.f, 0.f);
            int ks = d4 >> 1;
            int khi = (d4 & 1) * 2;
            int rl = r & 15;
            int reg = ((rl >= 8) ? 1 : 0) + khi;
            int ln = (rl & 7) * 4;
            uint32_t* base = QS + ks * QS_ST + (r >> 4) * 128;
            base[(ln + 0) * 4 + reg] = __float_as_uint(v.x);
            base[(ln + 1) * 4 + reg] = __float_as_uint(v.y);
            base[(ln + 2) * 4 + reg] = __float_as_uint(v.z);
            base[(ln + 3) * 4 + reg] = __float_as_uint(v.w);
        }
    }
    __syncthreads();
    uint4 Qr[16];
    #pragma unroll
    for (int ks = 0; ks < 16; ks++)
        Qr[ks] = *(const uint4*)(sm + QS_OFF + ks * QS_ST + mt * 128 + lane * 4);
    __syncthreads();   // all reads done before K1 may overwrite QS region

    const float* kbase = Kf + (size_t)head * NKT * 8192;
    const float* vbase = Vf + (size_t)head * NKT * 8192;

    // ---- prologue: G0 = {K0, V0}; G1 = {K1} ----
    #pragma unroll
    for (int it = 0; it < 16; it++) {
        int idx = (tid + it * 128) * 4;
        cpa16(sm + KB_OFF + idx, kbase + idx);
    }
    #pragma unroll
    for (int it = 0; it < 16; it++) {
        int idx = (tid + it * 128) * 4;
        cpa16(VB + idx, vbase + idx);
    }
    asm volatile("cp.async.commit_group;");
    #pragma unroll
    for (int it = 0; it < 16; it++) {
        int idx = (tid + it * 128) * 4;
        cpa16(sm + KB_OFF + 8192 + idx, kbase + 8192 + idx);
    }
    asm volatile("cp.async.commit_group;");

    float m0 = -INFINITY, m1 = -INFINITY;
    float l0 = 0.f, l1 = 0.f;
    float O[16][4];
    #pragma unroll
    for (int i = 0; i < 16; i++)
        #pragma unroll
        for (int j = 0; j < 4; j++) O[i][j] = 0.f;

    for (int kt = 0; kt < NKT; kt++) {
        const int kt0 = kt * 64;
        const uint32_t* KBc = sm + KB_OFF + (kt & 1) * 8192;

        // K(kt) resident?
        if (kt == 0) asm volatile("cp.async.wait_group 1;");
        else         asm volatile("cp.async.wait_group 2;");
        __syncthreads();

        // ---- S = Q K^T  (warp tile 16 x 64, A from registers) ----
        float Sc[8][4];
        #pragma unroll
        for (int i = 0; i < 8; i++)
            #pragma unroll
            for (int j = 0; j < 4; j++) Sc[i][j] = 0.f;

        #pragma unroll
        for (int ks = 0; ks < 16; ks++) {
            uint4 a = Qr[ks];
            #pragma unroll
            for (int nt = 0; nt < 8; nt++) {
                uint2 b = *(const uint2*)(KBc + ks * 512 + nt * 64 + lane * 2);
                mma_tf32(Sc[nt][0], Sc[nt][1], Sc[nt][2], Sc[nt][3],
                         a.x, a.y, a.z, a.w, b.x, b.y);
            }
        }

        // ---- scale(log2 domain) + mask + warp-local row max ----
        float pm0 = -INFINITY, pm1 = -INFINITY;
        #pragma unroll
        for (int nt = 0; nt < 8; nt++) {
            int cbase = nt * 8 + 2 * t4;
            #pragma unroll
            for (int j = 0; j < 4; j++) {
                int c = cbase + (j & 1);
                bool valid = (kt0 + c) < KV_LEN;
                Sc[nt][j] = valid ? Sc[nt][j] * SCALE2 : -1e30f;
            }
            pm0 = fmaxf(pm0, fmaxf(Sc[nt][0], Sc[nt][1]));
            pm1 = fmaxf(pm1, fmaxf(Sc[nt][2], Sc[nt][3]));
        }
        pm0 = fmaxf(pm0, __shfl_xor_sync(0xffffffffu, pm0, 1));
        pm0 = fmaxf(pm0, __shfl_xor_sync(0xffffffffu, pm0, 2));
        pm1 = fmaxf(pm1, __shfl_xor_sync(0xffffffffu, pm1, 1));
        pm1 = fmaxf(pm1, __shfl_xor_sync(0xffffffffu, pm1, 2));

        float m0n = fmaxf(m0, pm0);
        float m1n = fmaxf(m1, pm1);

        // ---- exp2 + PA store (warp-private) + row sums ----
        float s0 = 0.f, s1 = 0.f;
        #pragma unroll
        for (int nt = 0; nt < 8; nt++) {
            uint32_t* base = PA + nt * PA_ST + mt * 128;
            #pragma unroll
            for (int j = 0; j < 4; j++) {
                float e = exp2f(Sc[nt][j] - ((j < 2) ? m0n : m1n));
                if (j < 2) s0 += e; else s1 += e;
                int c = 2 * t4 + (j & 1);
                int rl = (j < 2) ? g : (g + 8);
                int reg = ((rl >= 8) ? 1 : 0) + ((c >= 4) ? 2 : 0);
                base[((rl & 7) * 4 + (c & 3)) * 4 + reg] = f2tf32(e);
            }
        }
        s0 += __shfl_xor_sync(0xffffffffu, s0, 1);
        s0 += __shfl_xor_sync(0xffffffffu, s0, 2);
        s1 += __shfl_xor_sync(0xffffffffu, s1, 1);
        s1 += __shfl_xor_sync(0xffffffffu, s1, 2);

        float alpha0 = exp2f(m0 - m0n);
        float alpha1 = exp2f(m1 - m1n);
        l0 = l0 * alpha0 + s0;
        l1 = l1 * alpha1 + s1;
        m0 = m0n; m1 = m1n;

        #pragma unroll
        for (int nt = 0; nt < 16; nt++) {
            O[nt][0] *= alpha0; O[nt][1] *= alpha0;
            O[nt][2] *= alpha1; O[nt][3] *= alpha1;
        }

        // V(kt) resident?
        asm volatile("cp.async.wait_group 1;");
        __syncthreads();

        // ---- O += P V  (warp tile 16 x 128; PA warp-local) ----
        #pragma unroll
        for (int ks = 0; ks < 8; ks++) {
            uint4 a = *(const uint4*)(PA + ks * PA_ST + mt * 128 + lane * 4);
            #pragma unroll
            for (int nt = 0; nt < 16; nt++) {
                uint2 b = *(const uint2*)(VB + ks * 1024 + nt * 64 + lane * 2);
                mma_tf32(O[nt][0], O[nt][1], O[nt][2], O[nt][3],
                         a.x, a.y, a.z, a.w, b.x, b.y);
            }
        }
        __syncthreads();   // VB + KB[kt&1] reads done -> safe to refill

        // ---- issue next loads: V(kt+1) -> VB, K(kt+2) -> KB[kt&1] ----
        if (kt + 1 < NKT) {
            const float* vfp = vbase + (size_t)(kt + 1) * 8192;
            #pragma unroll
            for (int it = 0; it < 16; it++) {
                int idx = (tid + it * 128) * 4;
                cpa16(VB + idx, vfp + idx);
            }
        }
        asm volatile("cp.async.commit_group;");
        if (kt + 2 < NKT) {
            const float* kfp = kbase + (size_t)(kt + 2) * 8192;
            uint32_t* KBn = sm + KB_OFF + (kt & 1) * 8192;
            #pragma unroll
            for (int it = 0; it < 16; it++) {
                int idx = (tid + it * 128) * 4;
                cpa16(KBn + idx, kfp + idx);
            }
        }
        asm volatile("cp.async.commit_group;");
    }

    // ---- finalize ----
    float inv0 = 1.f / l0, inv1 = 1.f / l1;
    int gr0 = q0 + 16 * mt + g;
    int gr1 = gr0 + 8;
    #pragma unroll
    for (int nt = 0; nt < 16; nt++) {
        int c = nt * 8 + 2 * t4;
        if (gr0 < S_LEN) {
            float2 o0 = make_float2(O[nt][0] * inv0, O[nt][1] * inv0);
            *(float2*)(Oo + (size_t)gr0 * DIM + head * HDIM + c) = o0;
        }
        if (gr1 < S_LEN) {
            float2 o1 = make_float2(O[nt][2] * inv1, O[nt][3] * inv1);
            *(float2*)(Oo + (size_t)gr1 * DIM + head * HDIM + c) = o1;
        }
    }
}

// ---------------- launch -----------------------------------------------------
extern "C" void kernel_launch(void* const* d_in, const int* in_sizes, int n_in,
                              void* d_out, int out_size)
{
    const float* x  = (const float*)d_in[0];
    const float* Wq = (const float*)d_in[1];
    const float* bq = (const float*)d_in[2];
    const float* Wk = (const float*)d_in[3];
    const float* bk = (const float*)d_in[4];
    const float* Wv = (const float*)d_in[5];
    const float* bv = (const float*)d_in[6];
    const float* Wo = (const float*)d_in[7];
    const float* bo = (const float*)d_in[8];
    const float* gq = (const float*)d_in[9];
    const float* gk = (const float*)d_in[10];
    const float* ck = (const float*)d_in[11];
    const float* cv = (const float*)d_in[12];
    const float* fc = (const float*)d_in[13];
    const float* fs = (const float*)d_in[14];
    float* out = (float*)d_out;

    float *qb, *kb, *vb, *kf, *vf, *ob;
    cudaGetSymbolAddress((void**)&qb, d_qbuf);
    cudaGetSymbolAddress((void**)&kb, d_kbuf);
    cudaGetSymbolAddress((void**)&vb, d_vbuf);
    cudaGetSymbolAddress((void**)&kf, d_kfrag);
    cudaGetSymbolAddress((void**)&vf, d_vfrag);
    cudaGetSymbolAddress((void**)&ob, d_obuf);

    int gemm_smem = G_SMEM_U32 * (int)sizeof(uint32_t);
    cudaFuncSetAttribute(gemm3_bf16, cudaFuncAttributeMaxDynamicSharedMemorySize, gemm_smem);

    gemm3_bf16<<<dim3(36, 13), 256, gemm_smem>>>(
        x, Wq, Wk, Wv, bq, bk, bv, qb, kb, vb, S_LEN);

    rmsnorm_rope_q<<<S_LEN, 256>>>(qb, gq, fc, fs);
    rmsnorm_plain<<<S_LEN, 256>>>(kb, gk);

    build_kv_frag<<<dim3(NKT, NHEADS, 2), 256>>>(ck, cv, kb, vb, kf, vf, fc, fs);

    int attn_smem = ATTN_SMEM_U32 * (int)sizeof(uint32_t);
    cudaFuncSetAttribute(attn_tc, cudaFuncAttributeMaxDynamicSharedMemorySize, attn_smem);
    attn_tc<<<dim3((S_LEN + 63) / 64, NHEADS), 128, attn_smem>>>(qb, kf, vf, ob);

    gemm3_bf16<<<dim3(12, 13), 256, gemm_smem>>>(
        ob, Wo, Wo, Wo, bo, bo, bo, out, out, out, S_LEN);
}

// round 14
// speedup vs baseline: 5.7073x; 1.5918x over previous
#include <cuda_runtime.h>
#include <cuda_bf16.h>
#include <cuda_fp16.h>
#include <math.h>
#include <stdint.h>

#define DIM      1536
#define NHEADS   12
#define HDIM     128
#define S_LEN    1560
#define KV_LEN   9360
#define NKT      147            /* 64-row kv tiles */
#define FT       22
#define FSZ      21
#define WW       52
#define ALPHA_F  0.999f
#define BETA_F   0.001f
#define EPS_F    1e-6f
#define Q_FRAME  5
#define SCALE    0.08838834764831843f      /* 1/sqrt(128) */
#define SCALE2   0.12752476815166922f      /* SCALE * log2(e) */

// ---------------- scratch (device globals; no allocations allowed) ----------
__device__ float    d_qbuf[S_LEN * DIM];
__device__ float    d_kbuf[S_LEN * DIM];
__device__ float    d_vbuf[S_LEN * DIM];
__device__ uint32_t d_kfrag[(size_t)NHEADS * NKT * 4096];   /* half2 words */
__device__ uint32_t d_vfrag[(size_t)NHEADS * NKT * 4096];
__device__ float    d_obuf[S_LEN * DIM];

__device__ __forceinline__ float bfr(float v) {
    return __bfloat162float(__float2bfloat16_rn(v));
}
__device__ __forceinline__ uint32_t pkbf2(float lo, float hi) {
    __nv_bfloat162 t = __floats2bfloat162_rn(lo, hi);
    return *reinterpret_cast<uint32_t*>(&t);
}
__device__ __forceinline__ uint32_t pkh(float lo, float hi) {
    __half2 t = __floats2half2_rn(lo, hi);
    return *reinterpret_cast<uint32_t*>(&t);
}
__device__ __forceinline__ void cpa16(void* dst, const void* src) {
    uint32_t d = (uint32_t)__cvta_generic_to_shared(dst);
    asm volatile("cp.async.ca.shared.global [%0], [%1], 16;" :: "r"(d), "l"(src));
}

__device__ __forceinline__ void mma_f16(
    float* c, const uint4& a, const uint2& b)
{
    asm volatile(
        "mma.sync.aligned.m16n8k16.row.col.f32.f16.f16.f32 "
        "{%0,%1,%2,%3},{%4,%5,%6,%7},{%8,%9},{%0,%1,%2,%3};"
        : "+f"(c[0]), "+f"(c[1]), "+f"(c[2]), "+f"(c[3])
        : "r"(a.x), "r"(a.y), "r"(a.z), "r"(a.w), "r"(b.x), "r"(b.y));
}
__device__ __forceinline__ void mma_bf16(
    float* c, const uint4& a, const uint2& b)
{
    asm volatile(
        "mma.sync.aligned.m16n8k16.row.col.f32.bf16.bf16.f32 "
        "{%0,%1,%2,%3},{%4,%5,%6,%7},{%8,%9},{%0,%1,%2,%3};"
        : "+f"(c[0]), "+f"(c[1]), "+f"(c[2]), "+f"(c[3])
        : "r"(a.x), "r"(a.y), "r"(a.z), "r"(a.w), "r"(b.x), "r"(b.y));
}

// ============ bf16 3-term GEMM (unchanged) ==================================
#define G_AH 0
#define G_AL 4096
#define G_BH 8192
#define G_BL 12416
#define G_SMEM_U32 16640

__global__ __launch_bounds__(256, 2) void gemm3_bf16(
    const float* __restrict__ A,
    const float* __restrict__ W0, const float* __restrict__ W1, const float* __restrict__ W2,
    const float* __restrict__ b0, const float* __restrict__ b1, const float* __restrict__ b2,
    float* __restrict__ C0, float* __restrict__ C1, float* __restrict__ C2,
    int M)
{
    extern __shared__ uint32_t gsm[];
    uint32_t* AH = gsm + G_AH;
    uint32_t* AL = gsm + G_AL;
    uint32_t* BH = gsm + G_BH;
    uint32_t* BL = gsm + G_BL;

    const int sel = blockIdx.x / 12;
    const float* B    = (sel == 0) ? W0 : (sel == 1) ? W1 : W2;
    const float* bias = (sel == 0) ? b0 : (sel == 1) ? b1 : b2;
    float*       C    = (sel == 0) ? C0 : (sel == 1) ? C1 : C2;
    const int bn = (blockIdx.x - sel * 12) * 128;
    const int bm = blockIdx.y * 128;

    const int tid  = threadIdx.x;
    const int lane = tid & 31, wrp = tid >> 5;
    const int wm = wrp & 3, wn = wrp >> 2;
    const int g = lane >> 2, t4 = lane & 3;

    float acc[2][8][4];
    #pragma unroll
    for (int i = 0; i < 2; i++)
        #pragma unroll
        for (int j = 0; j < 8; j++)
            #pragma unroll
            for (int r = 0; r < 4; r++) acc[i][j][r] = 0.f;

    for (int k0 = 0; k0 < DIM; k0 += 64) {
        __syncthreads();
        #pragma unroll
        for (int it = 0; it < 8; it++) {
            int idx = tid + it * 256;
            int r = idx >> 4, c4 = idx & 15;
            int gr = bm + r;
            float4 v = (gr < M)
                ? *(const float4*)(A + (size_t)gr * DIM + k0 + c4 * 4)
                : make_float4(0.f, 0.f, 0.f, 0.f);
            int rl = r & 15, mtile = r >> 4;
            int ks = c4 >> 2, k8 = (c4 >> 1) & 1, t4a = (c4 & 1) * 2;
            int reg = (rl >> 3) + 2 * k8;
            int base = ks * 1024 + mtile * 128;
            int lane0 = (rl & 7) * 4 + t4a;
            float hx = bfr(v.x), hy = bfr(v.y), hz = bfr(v.z), hw = bfr(v.w);
            AH[base + lane0 * 4 + reg]       = pkbf2(hx, hy);
            AH[base + (lane0 + 1) * 4 + reg] = pkbf2(hz, hw);
            AL[base + lane0 * 4 + reg]       = pkbf2(v.x - hx, v.y - hy);
            AL[base + (lane0 + 1) * 4 + reg] = pkbf2(v.z - hz, v.w - hw);
        }
        #pragma unroll
        for (int it = 0; it < 4; it++) {
            int idx = tid + it * 256;
            int kp = idx >> 5, n4 = idx & 31;
            const float* bp = B + (size_t)(k0 + 2 * kp) * DIM + bn + n4 * 4;
            float4 u = *(const float4*)bp;
            float4 w = *(const float4*)(bp + DIM);
            int ks = kp >> 3, tb = kp & 3, reg = (kp >> 2) & 1;
            int base = ks * 1056;
            float uu[4] = {u.x, u.y, u.z, u.w};
            float ww[4] = {w.x, w.y, w.z, w.w};
            #pragma unroll
            for (int j = 0; j < 4; j++) {
                int n = n4 * 4 + j;
                int nt = n >> 3;
                int lb = (n & 7) * 4 + tb;
                float hu = bfr(uu[j]), hw2 = bfr(ww[j]);
                BH[base + nt * 66 + lb * 2 + reg] = pkbf2(hu, hw2);
                BL[base + nt * 66 + lb * 2 + reg] = pkbf2(uu[j] - hu, ww[j] - hw2);
            }
        }
        __syncthreads();

        #pragma unroll
        for (int ks = 0; ks < 4; ks++) {
            uint4 ah0 = *(const uint4*)&AH[ks * 1024 + (wm * 2 + 0) * 128 + lane * 4];
            uint4 ah1 = *(const uint4*)&AH[ks * 1024 + (wm * 2 + 1) * 128 + lane * 4];
            uint4 al0 = *(const uint4*)&AL[ks * 1024 + (wm * 2 + 0) * 128 + lane * 4];
            uint4 al1 = *(const uint4*)&AL[ks * 1024 + (wm * 2 + 1) * 128 + lane * 4];
            #pragma unroll
            for (int nf = 0; nf < 8; nf++) {
                int nt = wn * 8 + nf;
                uint2 bh = *(const uint2*)&BH[ks * 1056 + nt * 66 + lane * 2];
                uint2 bl = *(const uint2*)&BL[ks * 1056 + nt * 66 + lane * 2];
                mma_bf16(acc[0][nf], ah0, bh);
                mma_bf16(acc[1][nf], ah1, bh);
                mma_bf16(acc[0][nf], al0, bh);
                mma_bf16(acc[1][nf], al1, bh);
                mma_bf16(acc[0][nf], ah0, bl);
                mma_bf16(acc[1][nf], ah1, bl);
            }
        }
    }

    #pragma unroll
    for (int nf = 0; nf < 8; nf++) {
        int cn = bn + wn * 64 + nf * 8 + 2 * t4;
        float2 bv = *(const float2*)(bias + cn);
        #pragma unroll
        for (int mf = 0; mf < 2; mf++) {
            int r0 = bm + wm * 32 + mf * 16 + g;
            if (r0 < M) {
                float2 o = make_float2(acc[mf][nf][0] + bv.x, acc[mf][nf][1] + bv.y);
                *(float2*)(C + (size_t)r0 * DIM + cn) = o;
            }
            if (r0 + 8 < M) {
                float2 o = make_float2(acc[mf][nf][2] + bv.x, acc[mf][nf][3] + bv.y);
                *(float2*)(C + (size_t)(r0 + 8) * DIM + cn) = o;
            }
        }
    }
}

// ---------------- rmsnorm (+rope for q) ------------------------------------
__device__ __forceinline__ float block_rms_scale(const float* row, float* red)
{
    float ss = 0.f;
    for (int i = threadIdx.x; i < DIM; i += 256) { float v = row[i]; ss += v * v; }
    #pragma unroll
    for (int o = 16; o; o >>= 1) ss += __shfl_xor_sync(0xffffffffu, ss, o);
    if ((threadIdx.x & 31) == 0) red[threadIdx.x >> 5] = ss;
    __syncthreads();
    if (threadIdx.x == 0) {
        float tot = 0.f;
        #pragma unroll
        for (int i = 0; i < 8; i++) tot += red[i];
        red[0] = rsqrtf(tot / (float)DIM + EPS_F);
    }
    __syncthreads();
    return red[0];
}

__global__ __launch_bounds__(256) void rmsnorm_rope_q(
    float* __restrict__ q, const float* __restrict__ g,
    const float* __restrict__ fc, const float* __restrict__ fs)
{
    __shared__ float red[8];
    int t = blockIdx.x;
    float* row = q + (size_t)t * DIM;
    float scale = block_rms_scale(row, red);
    int h = t / WW, w = t % WW;
    for (int p = threadIdx.x; p < DIM / 2; p += 256) {
        int c = p & 63;
        int ridx = (c < FT) ? Q_FRAME : ((c < FT + FSZ) ? h : w);
        float cs = fc[ridx * 64 + c], sn = fs[ridx * 64 + c];
        float a = row[2*p]   * scale * g[2*p];
        float b = row[2*p+1] * scale * g[2*p+1];
        row[2*p]   = a * cs - b * sn;
        row[2*p+1] = a * sn + b * cs;
    }
}

__global__ __launch_bounds__(256) void rmsnorm_plain(
    float* __restrict__ k, const float* __restrict__ g)
{
    __shared__ float red[8];
    int t = blockIdx.x;
    float* row = k + (size_t)t * DIM;
    float scale = block_rms_scale(row, red);
    for (int i = threadIdx.x; i < DIM; i += 256)
        row[i] = row[i] * scale * g[i];
}

// ------ build combined KV in fp16 m16n8k16-fragment order (per head,tile) ---
// K blk(ks 0..7, nt 0..7): word = ks*512 + nt*64 + lane*2 + reg;
//   lane = (row&7)*4 + ((kl>>1)&3), reg = kl>>3; value = h2(K[row][k], K[row][k+1])
// V blk(ks 0..3, nt 0..15): word = ks*1024 + nt*64 + lane*2 + reg;
//   lane = (n&7)*4 + ((kl>>1)&3), reg = kl>>3; value = h2(V[k][n], V[k+1][n])
__device__ __forceinline__ const float* kv_src(
    int R, const float* __restrict__ cc, const float* __restrict__ nn,
    const float** s2)
{
    *s2 = nullptr;
    if (R < 1560) { *s2 = cc + (size_t)(9360 + R) * DIM; return cc + (size_t)R * DIM; }
    if (R < 7800) return cc + (size_t)(R + 3120) * DIM;
    return nn + (size_t)(R - 7800) * DIM;
}

__device__ __forceinline__ float kv_val(
    int R, int col, const float* __restrict__ cc, const float* __restrict__ nn)
{
    if (R >= KV_LEN) return 0.f;
    const float* s2;
    const float* s1 = kv_src(R, cc, nn, &s2);
    float v = s1[col];
    if (s2) v = ALPHA_F * v + BETA_F * s2[col];
    return v;
}

__global__ __launch_bounds__(256) void build_kv_frag(
    const float* __restrict__ ck, const float* __restrict__ cv,
    const float* __restrict__ kn, const float* __restrict__ vn,
    uint32_t* __restrict__ kf, uint32_t* __restrict__ vf,
    const float* __restrict__ fc, const float* __restrict__ fs)
{
    const int tile = blockIdx.x, head = blockIdx.y;
    const int tid = threadIdx.x;
    uint32_t* dst = (blockIdx.z ? vf : kf) + ((size_t)head * NKT + tile) * 4096;

    if (blockIdx.z == 0) {
        // ---- K: task t -> (rowT, ks); 16 contiguous k, rope, permuted store
        #pragma unroll
        for (int it = 0; it < 2; it++) {
            int t = tid + it * 256;               // 0..511
            int ks = t >> 6;                      // 0..7
            int rowT = ((t >> 3) & 7) * 8 + (t & 7);
            int k0 = ks * 16;
            int R = tile * 64 + rowT;
            uint32_t pr2[8];
            #pragma unroll
            for (int j = 0; j < 8; j++) pr2[j] = 0;
            if (R < KV_LEN) {
                const float* s2;
                const float* s1 = kv_src(R, ck, kn, &s2);
                float raw[16];
                #pragma unroll
                for (int q4 = 0; q4 < 4; q4++) {
                    float4 a = *(const float4*)(s1 + head * HDIM + k0 + q4 * 4);
                    if (s2) {
                        float4 b = *(const float4*)(s2 + head * HDIM + k0 + q4 * 4);
                        a.x = ALPHA_F*a.x + BETA_F*b.x; a.y = ALPHA_F*a.y + BETA_F*b.y;
                        a.z = ALPHA_F*a.z + BETA_F*b.z; a.w = ALPHA_F*a.w + BETA_F*b.w;
                    }
                    raw[q4*4+0] = a.x; raw[q4*4+1] = a.y; raw[q4*4+2] = a.z; raw[q4*4+3] = a.w;
                }
                int fr = R / 1560, pp = R % 1560, hh = pp / WW, wc = pp % WW;
                #pragma unroll
                for (int j = 0; j < 8; j++) {
                    int c = ks * 8 + j;           // rope pair index 0..63
                    int ridx = (c < FT) ? fr : ((c < FT + FSZ) ? hh : wc);
                    float cs = fc[ridx * 64 + c], sn = fs[ridx * 64 + c];
                    float x = raw[2*j], y = raw[2*j + 1];
                    pr2[j] = pkh(x * cs - y * sn, x * sn + y * cs);
                }
            }
            uint32_t* base = dst + ks * 512 + (rowT >> 3) * 64 + (rowT & 7) * 8;
            *(uint4*)(base)     = make_uint4(pr2[0], pr2[4], pr2[1], pr2[5]);
            *(uint4*)(base + 4) = make_uint4(pr2[2], pr2[6], pr2[3], pr2[7]);
        }
    } else {
        // ---- V: 4 words (one uint4) per task ----
        #pragma unroll
        for (int it = 0; it < 4; it++) {
            int wbase = (tid + it * 256) * 4;     // 4-aligned word index
            int blk = wbase >> 6;
            int ks = blk >> 4, nt = blk & 15;
            int lane0 = (wbase & 63) >> 1;        // even lane
            int n = nt * 8 + (lane0 >> 2);
            int k0a = ks * 16 + 2 * (lane0 & 3);
            int Rb = tile * 64 + k0a;
            int col = head * HDIM + n;
            float v0 = kv_val(Rb + 0,  col, cv, vn);
            float v1 = kv_val(Rb + 1,  col, cv, vn);
            float v8 = kv_val(Rb + 8,  col, cv, vn);
            float v9 = kv_val(Rb + 9,  col, cv, vn);
            float v2 = kv_val(Rb + 2,  col, cv, vn);
            float v3 = kv_val(Rb + 3,  col, cv, vn);
            float vA = kv_val(Rb + 10, col, cv, vn);
            float vB = kv_val(Rb + 11, col, cv, vn);
            *(uint4*)(dst + wbase) = make_uint4(
                pkh(v0, v1), pkh(v8, v9), pkh(v2, v3), pkh(vA, vB));
        }
    }
}

// ===== fp16 flash attention: Q+P in regs, K dbl-buffer pipeline =============
// smem: KB[2] (2 x 4096 w) | VB (4096 w) = 12288 w = 49152 B; 2 CTAs/SM.
#define KB_OFF 0
#define VB_OFF 8192
#define ATTN_SMEM_U32 12288

__global__ __launch_bounds__(128, 2) void attn_tc(
    const float* __restrict__ Q, const uint32_t* __restrict__ Kf,
    const uint32_t* __restrict__ Vf, float* __restrict__ Oo)
{
    extern __shared__ uint32_t sm[];
    uint32_t* VB = sm + VB_OFF;

    const int q0   = blockIdx.x * 64;
    const int head = blockIdx.y;
    const int tid  = threadIdx.x;
    const int lane = tid & 31;
    const int mt   = tid >> 5;
    const int g    = lane >> 2;
    const int t4   = lane & 3;

    // ---- Q A-fragments straight from gmem to registers (once) ----
    uint4 Qr[8];
    {
        int r0 = q0 + 16 * mt + g;
        int r1 = r0 + 8;
        const float* q0p = Q + (size_t)r0 * DIM + head * HDIM;
        const float* q1p = Q + (size_t)r1 * DIM + head * HDIM;
        bool ok0 = r0 < S_LEN, ok1 = r1 < S_LEN;
        #pragma unroll
        for (int ks = 0; ks < 8; ks++) {
            int k0 = ks * 16 + 2 * t4;
            float2 a0 = ok0 ? *(const float2*)(q0p + k0)     : make_float2(0.f, 0.f);
            float2 a1 = ok1 ? *(const float2*)(q1p + k0)     : make_float2(0.f, 0.f);
            float2 a2 = ok0 ? *(const float2*)(q0p + k0 + 8) : make_float2(0.f, 0.f);
            float2 a3 = ok1 ? *(const float2*)(q1p + k0 + 8) : make_float2(0.f, 0.f);
            Qr[ks] = make_uint4(pkh(a0.x, a0.y), pkh(a1.x, a1.y),
                                pkh(a2.x, a2.y), pkh(a3.x, a3.y));
        }
    }

    const uint32_t* kbase = Kf + (size_t)head * NKT * 4096;
    const uint32_t* vbase = Vf + (size_t)head * NKT * 4096;

    // ---- prologue: G0 = {K0, V0}; G1 = {K1} ----
    #pragma unroll
    for (int it = 0; it < 8; it++) {
        int idx = (tid + it * 128) * 4;
        cpa16(sm + KB_OFF + idx, kbase + idx);
    }
    #pragma unroll
    for (int it = 0; it < 8; it++) {
        int idx = (tid + it * 128) * 4;
        cpa16(VB + idx, vbase + idx);
    }
    asm volatile("cp.async.commit_group;");
    #pragma unroll
    for (int it = 0; it < 8; it++) {
        int idx = (tid + it * 128) * 4;
        cpa16(sm + KB_OFF + 4096 + idx, kbase + 4096 + idx);
    }
    asm volatile("cp.async.commit_group;");

    float m0 = -INFINITY, m1 = -INFINITY;
    float l0 = 0.f, l1 = 0.f;
    float O[16][4];
    #pragma unroll
    for (int i = 0; i < 16; i++)
        #pragma unroll
        for (int j = 0; j < 4; j++) O[i][j] = 0.f;

    for (int kt = 0; kt < NKT; kt++) {
        const int kt0 = kt * 64;
        const uint32_t* KBc = sm + KB_OFF + (kt & 1) * 4096;

        if (kt == 0) asm volatile("cp.async.wait_group 1;");
        else         asm volatile("cp.async.wait_group 2;");
        __syncthreads();

        // ---- S = Q K^T  (warp tile 16 x 64, fp16 k16) ----
        float Sc[8][4];
        #pragma unroll
        for (int i = 0; i < 8; i++)
            #pragma unroll
            for (int j = 0; j < 4; j++) Sc[i][j] = 0.f;

        #pragma unroll
        for (int ks = 0; ks < 8; ks++) {
            uint4 a = Qr[ks];
            #pragma unroll
            for (int nt = 0; nt < 8; nt++) {
                uint2 b = *(const uint2*)(KBc + ks * 512 + nt * 64 + lane * 2);
                mma_f16(Sc[nt], a, b);
            }
        }

        // ---- scale(log2) + mask + warp-local row max ----
        float pm0 = -INFINITY, pm1 = -INFINITY;
        #pragma unroll
        for (int nt = 0; nt < 8; nt++) {
            int cbase = nt * 8 + 2 * t4;
            #pragma unroll
            for (int j = 0; j < 4; j++) {
                int c = cbase + (j & 1);
                bool valid = (kt0 + c) < KV_LEN;
                Sc[nt][j] = valid ? Sc[nt][j] * SCALE2 : -1e30f;
            }
            pm0 = fmaxf(pm0, fmaxf(Sc[nt][0], Sc[nt][1]));
            pm1 = fmaxf(pm1, fmaxf(Sc[nt][2], Sc[nt][3]));
        }
        pm0 = fmaxf(pm0, __shfl_xor_sync(0xffffffffu, pm0, 1));
        pm0 = fmaxf(pm0, __shfl_xor_sync(0xffffffffu, pm0, 2));
        pm1 = fmaxf(pm1, __shfl_xor_sync(0xffffffffu, pm1, 1));
        pm1 = fmaxf(pm1, __shfl_xor_sync(0xffffffffu, pm1, 2));

        float m0n = fmaxf(m0, pm0);
        float m1n = fmaxf(m1, pm1);

        // ---- exp2 (register-resident P) + row sums ----
        float s0 = 0.f, s1 = 0.f;
        #pragma unroll
        for (int nt = 0; nt < 8; nt++) {
            Sc[nt][0] = exp2f(Sc[nt][0] - m0n);
            Sc[nt][1] = exp2f(Sc[nt][1] - m0n);
            Sc[nt][2] = exp2f(Sc[nt][2] - m1n);
            Sc[nt][3] = exp2f(Sc[nt][3] - m1n);
            s0 += Sc[nt][0] + Sc[nt][1];
            s1 += Sc[nt][2] + Sc[nt][3];
        }
        s0 += __shfl_xor_sync(0xffffffffu, s0, 1);
        s0 += __shfl_xor_sync(0xffffffffu, s0, 2);
        s1 += __shfl_xor_sync(0xffffffffu, s1, 1);
        s1 += __shfl_xor_sync(0xffffffffu, s1, 2);

        float alpha0 = exp2f(m0 - m0n);
        float alpha1 = exp2f(m1 - m1n);
        l0 = l0 * alpha0 + s0;
        l1 = l1 * alpha1 + s1;
        m0 = m0n; m1 = m1n;

        #pragma unroll
        for (int nt = 0; nt < 16; nt++) {
            O[nt][0] *= alpha0; O[nt][1] *= alpha0;
            O[nt][2] *= alpha1; O[nt][3] *= alpha1;
        }

        // ---- pack P to fp16 A-fragments (pure registers) ----
        uint4 Pr[4];
        #pragma unroll
        for (int ks = 0; ks < 4; ks++) {
            Pr[ks] = make_uint4(
                pkh(Sc[2*ks][0],     Sc[2*ks][1]),
                pkh(Sc[2*ks][2],     Sc[2*ks][3]),
                pkh(Sc[2*ks + 1][0], Sc[2*ks + 1][1]),
                pkh(Sc[2*ks + 1][2], Sc[2*ks + 1][3]));
        }

        asm volatile("cp.async.wait_group 1;");   // V resident
        __syncthreads();

        // ---- O += P V  (warp tile 16 x 128, fp16 k16) ----
        #pragma unroll
        for (int ks = 0; ks < 4; ks++) {
            uint4 a = Pr[ks];
            #pragma unroll
            for (int nt = 0; nt < 16; nt++) {
                uint2 b = *(const uint2*)(VB + ks * 1024 + nt * 64 + lane * 2);
                mma_f16(O[nt], a, b);
            }
        }
        __syncthreads();   // VB + KB[kt&1] reads done -> safe to refill

        // ---- issue next loads: V(kt+1) -> VB, K(kt+2) -> KB[kt&1] ----
        if (kt + 1 < NKT) {
            const uint32_t* vfp = vbase + (size_t)(kt + 1) * 4096;
            #pragma unroll
            for (int it = 0; it < 8; it++) {
                int idx = (tid + it * 128) * 4;
                cpa16(VB + idx, vfp + idx);
            }
        }
        asm volatile("cp.async.commit_group;");
        if (kt + 2 < NKT) {
            const uint32_t* kfp = kbase + (size_t)(kt + 2) * 4096;
            uint32_t* KBn = sm + KB_OFF + (kt & 1) * 4096;
            #pragma unroll
            for (int it = 0; it < 8; it++) {
                int idx = (tid + it * 128) * 4;
                cpa16(KBn + idx, kfp + idx);
            }
        }
        asm volatile("cp.async.commit_group;");
    }

    // ---- finalize ----
    float inv0 = 1.f / l0, inv1 = 1.f / l1;
    int gr0 = q0 + 16 * mt + g;
    int gr1 = gr0 + 8;
    #pragma unroll
    for (int nt = 0; nt < 16; nt++) {
        int c = nt * 8 + 2 * t4;
        if (gr0 < S_LEN) {
            float2 o0 = make_float2(O[nt][0] * inv0, O[nt][1] * inv0);
            *(float2*)(Oo + (size_t)gr0 * DIM + head * HDIM + c) = o0;
        }
        if (gr1 < S_LEN) {
            float2 o1 = make_float2(O[nt][2] * inv1, O[nt][3] * inv1);
            *(float2*)(Oo + (size_t)gr1 * DIM + head * HDIM + c) = o1;
        }
    }
}

// ---------------- launch -----------------------------------------------------
extern "C" void kernel_launch(void* const* d_in, const int* in_sizes, int n_in,
                              void* d_out, int out_size)
{
    const float* x  = (const float*)d_in[0];
    const float* Wq = (const float*)d_in[1];
    const float* bq = (const float*)d_in[2];
    const float* Wk = (const float*)d_in[3];
    const float* bk = (const float*)d_in[4];
    const float* Wv = (const float*)d_in[5];
    const float* bv = (const float*)d_in[6];
    const float* Wo = (const float*)d_in[7];
    const float* bo = (const float*)d_in[8];
    const float* gq = (const float*)d_in[9];
    const float* gk = (const float*)d_in[10];
    const float* ck = (const float*)d_in[11];
    const float* cv = (const float*)d_in[12];
    const float* fc = (const float*)d_in[13];
    const float* fs = (const float*)d_in[14];
    float* out = (float*)d_out;

    float *qb, *kb, *vb, *ob;
    uint32_t *kf, *vf;
    cudaGetSymbolAddress((void**)&qb, d_qbuf);
    cudaGetSymbolAddress((void**)&kb, d_kbuf);
    cudaGetSymbolAddress((void**)&vb, d_vbuf);
    cudaGetSymbolAddress((void**)&kf, d_kfrag);
    cudaGetSymbolAddress((void**)&vf, d_vfrag);
    cudaGetSymbolAddress((void**)&ob, d_obuf);

    int gemm_smem = G_SMEM_U32 * (int)sizeof(uint32_t);
    cudaFuncSetAttribute(gemm3_bf16, cudaFuncAttributeMaxDynamicSharedMemorySize, gemm_smem);

    gemm3_bf16<<<dim3(36, 13), 256, gemm_smem>>>(
        x, Wq, Wk, Wv, bq, bk, bv, qb, kb, vb, S_LEN);

    rmsnorm_rope_q<<<S_LEN, 256>>>(qb, gq, fc, fs);
    rmsnorm_plain<<<S_LEN, 256>>>(kb, gk);

    build_kv_frag<<<dim3(NKT, NHEADS, 2), 256>>>(ck, cv, kb, vb, kf, vf, fc, fs);

    int attn_smem = ATTN_SMEM_U32 * (int)sizeof(uint32_t);
    cudaFuncSetAttribute(attn_tc, cudaFuncAttributeMaxDynamicSharedMemorySize, attn_smem);
    attn_tc<<<dim3((S_LEN + 63) / 64, NHEADS), 128, attn_smem>>>(qb, kf, vf, ob);

    gemm3_bf16<<<dim3(12, 13), 256, gemm_smem>>>(
        ob, Wo, Wo, Wo, bo, bo, bo, out, out, out, S_LEN);
}

// round 16
// speedup vs baseline: 5.8070x; 1.0175x over previous
#include <cuda_runtime.h>
#include <cuda_fp16.h>
#include <math.h>
#include <stdint.h>

#define DIM      1536
#define NHEADS   12
#define HDIM     128
#define S_LEN    1560
#define KV_LEN   9360
#define NKT      147            /* 64-row kv tiles */
#define FT       22
#define FSZ      21
#define WW       52
#define ALPHA_F  0.999f
#define BETA_F   0.001f
#define EPS_F    1e-6f
#define Q_FRAME  5
#define SCALE2   0.12752476815166922f      /* (1/sqrt(128)) * log2(e) */

// ---------------- scratch (device globals; no allocations allowed) ----------
__device__ float    d_qbuf[S_LEN * DIM];
__device__ float    d_kbuf[S_LEN * DIM];
__device__ float    d_vbuf[S_LEN * DIM];
__device__ uint32_t d_kfrag[(size_t)NHEADS * NKT * 4096];   /* half2 words */
__device__ uint32_t d_vfrag[(size_t)NHEADS * NKT * 4096];
__device__ float    d_obuf[S_LEN * DIM];

__device__ __forceinline__ float hr(float v) {
    return __half2float(__float2half_rn(v));
}
__device__ __forceinline__ uint32_t pkh(float lo, float hi) {
    __half2 t = __floats2half2_rn(lo, hi);
    return *reinterpret_cast<uint32_t*>(&t);
}
__device__ __forceinline__ void cpa16(void* dst, const void* src) {
    uint32_t d = (uint32_t)__cvta_generic_to_shared(dst);
    asm volatile("cp.async.ca.shared.global [%0], [%1], 16;" :: "r"(d), "l"(src));
}

__device__ __forceinline__ void mma_f16(
    float* c, const uint4& a, const uint2& b)
{
    asm volatile(
        "mma.sync.aligned.m16n8k16.row.col.f32.f16.f16.f32 "
        "{%0,%1,%2,%3},{%4,%5,%6,%7},{%8,%9},{%0,%1,%2,%3};"
        : "+f"(c[0]), "+f"(c[1]), "+f"(c[2]), "+f"(c[3])
        : "r"(a.x), "r"(a.y), "r"(a.z), "r"(a.w), "r"(b.x), "r"(b.y));
}

// ============ fp16 2-term GEMM: C = Ah@(Bh+Bl) + bias ======================
// A single fp16 (drop Al term ~2^-13); weights hi/lo fp16.
#define G_AH 0
#define G_BH 4096
#define G_BL 8320
#define G_SMEM_U32 12544   /* 50176 B */

__global__ __launch_bounds__(256, 2) void gemm3_f16(
    const float* __restrict__ A,
    const float* __restrict__ W0, const float* __restrict__ W1, const float* __restrict__ W2,
    const float* __restrict__ b0, const float* __restrict__ b1, const float* __restrict__ b2,
    float* __restrict__ C0, float* __restrict__ C1, float* __restrict__ C2,
    int M)
{
    extern __shared__ uint32_t gsm[];
    uint32_t* AH = gsm + G_AH;
    uint32_t* BH = gsm + G_BH;
    uint32_t* BL = gsm + G_BL;

    const int sel = blockIdx.x / 12;
    const float* B    = (sel == 0) ? W0 : (sel == 1) ? W1 : W2;
    const float* bias = (sel == 0) ? b0 : (sel == 1) ? b1 : b2;
    float*       C    = (sel == 0) ? C0 : (sel == 1) ? C1 : C2;
    const int bn = (blockIdx.x - sel * 12) * 128;
    const int bm = blockIdx.y * 128;

    const int tid  = threadIdx.x;
    const int lane = tid & 31, wrp = tid >> 5;
    const int wm = wrp & 3, wn = wrp >> 2;
    const int g = lane >> 2, t4 = lane & 3;

    float acc[2][8][4];
    #pragma unroll
    for (int i = 0; i < 2; i++)
        #pragma unroll
        for (int j = 0; j < 8; j++)
            #pragma unroll
            for (int r = 0; r < 4; r++) acc[i][j][r] = 0.f;

    for (int k0 = 0; k0 < DIM; k0 += 64) {
        __syncthreads();
        // ---- A tile 128x64 -> fp16 fragment-order ----
        #pragma unroll
        for (int it = 0; it < 8; it++) {
            int idx = tid + it * 256;
            int r = idx >> 4, c4 = idx & 15;
            int gr = bm + r;
            float4 v = (gr < M)
                ? *(const float4*)(A + (size_t)gr * DIM + k0 + c4 * 4)
                : make_float4(0.f, 0.f, 0.f, 0.f);
            int rl = r & 15, mtile = r >> 4;
            int ks = c4 >> 2, k8 = (c4 >> 1) & 1, t4a = (c4 & 1) * 2;
            int reg = (rl >> 3) + 2 * k8;
            int base = ks * 1024 + mtile * 128;
            int lane0 = (rl & 7) * 4 + t4a;
            AH[base + lane0 * 4 + reg]       = pkh(v.x, v.y);
            AH[base + (lane0 + 1) * 4 + reg] = pkh(v.z, v.w);
        }
        // ---- B tile 64x128 -> hi/lo fp16 fragment-order ----
        #pragma unroll
        for (int it = 0; it < 4; it++) {
            int idx = tid + it * 256;
            int kp = idx >> 5, n4 = idx & 31;
            const float* bp = B + (size_t)(k0 + 2 * kp) * DIM + bn + n4 * 4;
            float4 u = *(const float4*)bp;
            float4 w = *(const float4*)(bp + DIM);
            int ks = kp >> 3, tb = kp & 3, reg = (kp >> 2) & 1;
            int base = ks * 1056;
            float uu[4] = {u.x, u.y, u.z, u.w};
            float ww[4] = {w.x, w.y, w.z, w.w};
            #pragma unroll
            for (int j = 0; j < 4; j++) {
                int n = n4 * 4 + j;
                int nt = n >> 3;
                int lb = (n & 7) * 4 + tb;
                float hu = hr(uu[j]), hw2 = hr(ww[j]);
                BH[base + nt * 66 + lb * 2 + reg] = pkh(hu, hw2);
                BL[base + nt * 66 + lb * 2 + reg] = pkh(uu[j] - hu, ww[j] - hw2);
            }
        }
        __syncthreads();

        #pragma unroll
        for (int ks = 0; ks < 4; ks++) {
            uint4 ah0 = *(const uint4*)&AH[ks * 1024 + (wm * 2 + 0) * 128 + lane * 4];
            uint4 ah1 = *(const uint4*)&AH[ks * 1024 + (wm * 2 + 1) * 128 + lane * 4];
            #pragma unroll
            for (int nf = 0; nf < 8; nf++) {
                int nt = wn * 8 + nf;
                uint2 bh = *(const uint2*)&BH[ks * 1056 + nt * 66 + lane * 2];
                uint2 bl = *(const uint2*)&BL[ks * 1056 + nt * 66 + lane * 2];
                mma_f16(acc[0][nf], ah0, bh);
                mma_f16(acc[1][nf], ah1, bh);
                mma_f16(acc[0][nf], ah0, bl);
                mma_f16(acc[1][nf], ah1, bl);
            }
        }
    }

    #pragma unroll
    for (int nf = 0; nf < 8; nf++) {
        int cn = bn + wn * 64 + nf * 8 + 2 * t4;
        float2 bv = *(const float2*)(bias + cn);
        #pragma unroll
        for (int mf = 0; mf < 2; mf++) {
            int r0 = bm + wm * 32 + mf * 16 + g;
            if (r0 < M) {
                float2 o = make_float2(acc[mf][nf][0] + bv.x, acc[mf][nf][1] + bv.y);
                *(float2*)(C + (size_t)r0 * DIM + cn) = o;
            }
            if (r0 + 8 < M) {
                float2 o = make_float2(acc[mf][nf][2] + bv.x, acc[mf][nf][3] + bv.y);
                *(float2*)(C + (size_t)(r0 + 8) * DIM + cn) = o;
            }
        }
    }
}

// ---------------- rmsnorm (+rope for q; SCALE2 folded in) -------------------
__device__ __forceinline__ float block_rms_scale(const float* row, float* red)
{
    float ss = 0.f;
    for (int i = threadIdx.x; i < DIM; i += 256) { float v = row[i]; ss += v * v; }
    #pragma unroll
    for (int o = 16; o; o >>= 1) ss += __shfl_xor_sync(0xffffffffu, ss, o);
    if ((threadIdx.x & 31) == 0) red[threadIdx.x >> 5] = ss;
    __syncthreads();
    if (threadIdx.x == 0) {
        float tot = 0.f;
        #pragma unroll
        for (int i = 0; i < 8; i++) tot += red[i];
        red[0] = rsqrtf(tot / (float)DIM + EPS_F);
    }
    __syncthreads();
    return red[0];
}

__global__ __launch_bounds__(256) void rmsnorm_rope_q(
    float* __restrict__ q, const float* __restrict__ g,
    const float* __restrict__ fc, const float* __restrict__ fs)
{
    __shared__ float red[8];
    int t = blockIdx.x;
    float* row = q + (size_t)t * DIM;
    float scale = block_rms_scale(row, red);
    int h = t / WW, w = t % WW;
    for (int p = threadIdx.x; p < DIM / 2; p += 256) {
        int c = p & 63;
        int ridx = (c < FT) ? Q_FRAME : ((c < FT + FSZ) ? h : w);
        float cs = fc[ridx * 64 + c], sn = fs[ridx * 64 + c];
        float a = row[2*p]   * scale * g[2*p];
        float b = row[2*p+1] * scale * g[2*p+1];
        row[2*p]   = (a * cs - b * sn) * SCALE2;
        row[2*p+1] = (a * sn + b * cs) * SCALE2;
    }
}

__global__ __launch_bounds__(256) void rmsnorm_plain(
    float* __restrict__ k, const float* __restrict__ g)
{
    __shared__ float red[8];
    int t = blockIdx.x;
    float* row = k + (size_t)t * DIM;
    float scale = block_rms_scale(row, red);
    for (int i = threadIdx.x; i < DIM; i += 256)
        row[i] = row[i] * scale * g[i];
}

// ------ build combined KV in fp16 m16n8k16-fragment order (unchanged) -------
__device__ __forceinline__ const float* kv_src(
    int R, const float* __restrict__ cc, const float* __restrict__ nn,
    const float** s2)
{
    *s2 = nullptr;
    if (R < 1560) { *s2 = cc + (size_t)(9360 + R) * DIM; return cc + (size_t)R * DIM; }
    if (R < 7800) return cc + (size_t)(R + 3120) * DIM;
    return nn + (size_t)(R - 7800) * DIM;
}

__device__ __forceinline__ float kv_val(
    int R, int col, const float* __restrict__ cc, const float* __restrict__ nn)
{
    if (R >= KV_LEN) return 0.f;
    const float* s2;
    const float* s1 = kv_src(R, cc, nn, &s2);
    float v = s1[col];
    if (s2) v = ALPHA_F * v + BETA_F * s2[col];
    return v;
}

__global__ __launch_bounds__(256) void build_kv_frag(
    const float* __restrict__ ck, const float* __restrict__ cv,
    const float* __restrict__ kn, const float* __restrict__ vn,
    uint32_t* __restrict__ kf, uint32_t* __restrict__ vf,
    const float* __restrict__ fc, const float* __restrict__ fs)
{
    const int tile = blockIdx.x, head = blockIdx.y;
    const int tid = threadIdx.x;
    uint32_t* dst = (blockIdx.z ? vf : kf) + ((size_t)head * NKT + tile) * 4096;

    if (blockIdx.z == 0) {
        #pragma unroll
        for (int it = 0; it < 2; it++) {
            int t = tid + it * 256;
            int ks = t >> 6;
            int rowT = ((t >> 3) & 7) * 8 + (t & 7);
            int k0 = ks * 16;
            int R = tile * 64 + rowT;
            uint32_t pr2[8];
            #pragma unroll
            for (int j = 0; j < 8; j++) pr2[j] = 0;
            if (R < KV_LEN) {
                const float* s2;
                const float* s1 = kv_src(R, ck, kn, &s2);
                float raw[16];
                #pragma unroll
                for (int q4 = 0; q4 < 4; q4++) {
                    float4 a = *(const float4*)(s1 + head * HDIM + k0 + q4 * 4);
                    if (s2) {
                        float4 b = *(const float4*)(s2 + head * HDIM + k0 + q4 * 4);
                        a.x = ALPHA_F*a.x + BETA_F*b.x; a.y = ALPHA_F*a.y + BETA_F*b.y;
                        a.z = ALPHA_F*a.z + BETA_F*b.z; a.w = ALPHA_F*a.w + BETA_F*b.w;
                    }
                    raw[q4*4+0] = a.x; raw[q4*4+1] = a.y; raw[q4*4+2] = a.z; raw[q4*4+3] = a.w;
                }
                int fr = R / 1560, pp = R % 1560, hh = pp / WW, wc = pp % WW;
                #pragma unroll
                for (int j = 0; j < 8; j++) {
                    int c = ks * 8 + j;
                    int ridx = (c < FT) ? fr : ((c < FT + FSZ) ? hh : wc);
                    float cs = fc[ridx * 64 + c], sn = fs[ridx * 64 + c];
                    float x = raw[2*j], y = raw[2*j + 1];
                    pr2[j] = pkh(x * cs - y * sn, x * sn + y * cs);
                }
            }
            uint32_t* base = dst + ks * 512 + (rowT >> 3) * 64 + (rowT & 7) * 8;
            *(uint4*)(base)     = make_uint4(pr2[0], pr2[4], pr2[1], pr2[5]);
            *(uint4*)(base + 4) = make_uint4(pr2[2], pr2[6], pr2[3], pr2[7]);
        }
    } else {
        #pragma unroll
        for (int it = 0; it < 4; it++) {
            int wbase = (tid + it * 256) * 4;
            int blk = wbase >> 6;
            int ks = blk >> 4, nt = blk & 15;
            int lane0 = (wbase & 63) >> 1;
            int n = nt * 8 + (lane0 >> 2);
            int k0a = ks * 16 + 2 * (lane0 & 3);
            int Rb = tile * 64 + k0a;
            int col = head * HDIM + n;
            float v0 = kv_val(Rb + 0,  col, cv, vn);
            float v1 = kv_val(Rb + 1,  col, cv, vn);
            float v8 = kv_val(Rb + 8,  col, cv, vn);
            float v9 = kv_val(Rb + 9,  col, cv, vn);
            float v2 = kv_val(Rb + 2,  col, cv, vn);
            float v3 = kv_val(Rb + 3,  col, cv, vn);
            float vA = kv_val(Rb + 10, col, cv, vn);
            float vB = kv_val(Rb + 11, col, cv, vn);
            *(uint4*)(dst + wbase) = make_uint4(
                pkh(v0, v1), pkh(v8, v9), pkh(v2, v3), pkh(vA, vB));
        }
    }
}

// ===== fp16 flash attention: Q+P in regs, K dbl-buffer pipeline =============
#define KB_OFF 0
#define VB_OFF 8192
#define ATTN_SMEM_U32 12288

__global__ __launch_bounds__(128, 2) void attn_tc(
    const float* __restrict__ Q, const uint32_t* __restrict__ Kf,
    const uint32_t* __restrict__ Vf, float* __restrict__ Oo)
{
    extern __shared__ uint32_t sm[];
    uint32_t* VB = sm + VB_OFF;

    const int q0   = blockIdx.x * 64;
    const int head = blockIdx.y;
    const int tid  = threadIdx.x;
    const int lane = tid & 31;
    const int mt   = tid >> 5;
    const int g    = lane >> 2;
    const int t4   = lane & 3;

    // ---- Q A-fragments straight from gmem to registers (pre-scaled) ----
    uint4 Qr[8];
    {
        int r0 = q0 + 16 * mt + g;
        int r1 = r0 + 8;
        const float* q0p = Q + (size_t)r0 * DIM + head * HDIM;
        const float* q1p = Q + (size_t)r1 * DIM + head * HDIM;
        bool ok0 = r0 < S_LEN, ok1 = r1 < S_LEN;
        #pragma unroll
        for (int ks = 0; ks < 8; ks++) {
            int k0 = ks * 16 + 2 * t4;
            float2 a0 = ok0 ? *(const float2*)(q0p + k0)     : make_float2(0.f, 0.f);
            float2 a1 = ok1 ? *(const float2*)(q1p + k0)     : make_float2(0.f, 0.f);
            float2 a2 = ok0 ? *(const float2*)(q0p + k0 + 8) : make_float2(0.f, 0.f);
            float2 a3 = ok1 ? *(const float2*)(q1p + k0 + 8) : make_float2(0.f, 0.f);
            Qr[ks] = make_uint4(pkh(a0.x, a0.y), pkh(a1.x, a1.y),
                                pkh(a2.x, a2.y), pkh(a3.x, a3.y));
        }
    }

    const uint32_t* kbase = Kf + (size_t)head * NKT * 4096;
    const uint32_t* vbase = Vf + (size_t)head * NKT * 4096;

    // ---- prologue: G0 = {K0, V0}; G1 = {K1} ----
    #pragma unroll
    for (int it = 0; it < 8; it++) {
        int idx = (tid + it * 128) * 4;
        cpa16(sm + KB_OFF + idx, kbase + idx);
    }
    #pragma unroll
    for (int it = 0; it < 8; it++) {
        int idx = (tid + it * 128) * 4;
        cpa16(VB + idx, vbase + idx);
    }
    asm volatile("cp.async.commit_group;");
    #pragma unroll
    for (int it = 0; it < 8; it++) {
        int idx = (tid + it * 128) * 4;
        cpa16(sm + KB_OFF + 4096 + idx, kbase + 4096 + idx);
    }
    asm volatile("cp.async.commit_group;");

    float m0 = -INFINITY, m1 = -INFINITY;
    float l0 = 0.f, l1 = 0.f;
    float O[16][4];
    #pragma unroll
    for (int i = 0; i < 16; i++)
        #pragma unroll
        for (int j = 0; j < 4; j++) O[i][j] = 0.f;

    for (int kt = 0; kt < NKT; kt++) {
        const uint32_t* KBc = sm + KB_OFF + (kt & 1) * 4096;

        if (kt == 0) asm volatile("cp.async.wait_group 1;");
        else         asm volatile("cp.async.wait_group 2;");
        __syncthreads();

        // ---- S = Q K^T  (already in log2-scaled domain via Q) ----
        float Sc[8][4];
        #pragma unroll
        for (int i = 0; i < 8; i++)
            #pragma unroll
            for (int j = 0; j < 4; j++) Sc[i][j] = 0.f;

        #pragma unroll
        for (int ks = 0; ks < 8; ks++) {
            uint4 a = Qr[ks];
            #pragma unroll
            for (int nt = 0; nt < 8; nt++) {
                uint2 b = *(const uint2*)(KBc + ks * 512 + nt * 64 + lane * 2);
                mma_f16(Sc[nt], a, b);
            }
        }

        // ---- mask (last tile only) + warp-local row max ----
        if (kt == NKT - 1) {
            int kt0 = kt * 64;
            #pragma unroll
            for (int nt = 0; nt < 8; nt++) {
                int cbase = nt * 8 + 2 * t4;
                #pragma unroll
                for (int j = 0; j < 4; j++) {
                    if (kt0 + cbase + (j & 1) >= KV_LEN) Sc[nt][j] = -1e30f;
                }
            }
        }
        float pm0 = -INFINITY, pm1 = -INFINITY;
        #pragma unroll
        for (int nt = 0; nt < 8; nt++) {
            pm0 = fmaxf(pm0, fmaxf(Sc[nt][0], Sc[nt][1]));
            pm1 = fmaxf(pm1, fmaxf(Sc[nt][2], Sc[nt][3]));
        }
        pm0 = fmaxf(pm0, __shfl_xor_sync(0xffffffffu, pm0, 1));
        pm0 = fmaxf(pm0, __shfl_xor_sync(0xffffffffu, pm0, 2));
        pm1 = fmaxf(pm1, __shfl_xor_sync(0xffffffffu, pm1, 1));
        pm1 = fmaxf(pm1, __shfl_xor_sync(0xffffffffu, pm1, 2));

        float m0n = fmaxf(m0, pm0);
        float m1n = fmaxf(m1, pm1);

        // ---- exp2 (register-resident P) + row sums ----
        float s0 = 0.f, s1 = 0.f;
        #pragma unroll
        for (int nt = 0; nt < 8; nt++) {
            Sc[nt][0] = exp2f(Sc[nt][0] - m0n);
            Sc[nt][1] = exp2f(Sc[nt][1] - m0n);
            Sc[nt][2] = exp2f(Sc[nt][2] - m1n);
            Sc[nt][3] = exp2f(Sc[nt][3] - m1n);
            s0 += Sc[nt][0] + Sc[nt][1];
            s1 += Sc[nt][2] + Sc[nt][3];
        }
        s0 += __shfl_xor_sync(0xffffffffu, s0, 1);
        s0 += __shfl_xor_sync(0xffffffffu, s0, 2);
        s1 += __shfl_xor_sync(0xffffffffu, s1, 1);
        s1 += __shfl_xor_sync(0xffffffffu, s1, 2);

        float alpha0 = exp2f(m0 - m0n);
        float alpha1 = exp2f(m1 - m1n);
        l0 = l0 * alpha0 + s0;
        l1 = l1 * alpha1 + s1;
        m0 = m0n; m1 = m1n;

        #pragma unroll
        for (int nt = 0; nt < 16; nt++) {
            O[nt][0] *= alpha0; O[nt][1] *= alpha0;
            O[nt][2] *= alpha1; O[nt][3] *= alpha1;
        }

        // ---- pack P to fp16 A-fragments (registers) ----
        uint4 Pr[4];
        #pragma unroll
        for (int ks = 0; ks < 4; ks++) {
            Pr[ks] = make_uint4(
                pkh(Sc[2*ks][0],     Sc[2*ks][1]),
                pkh(Sc[2*ks][2],     Sc[2*ks][3]),
                pkh(Sc[2*ks + 1][0], Sc[2*ks + 1][1]),
                pkh(Sc[2*ks + 1][2], Sc[2*ks + 1][3]));
        }

        asm volatile("cp.async.wait_group 1;");   // V resident
        __syncthreads();

        // ---- O += P V ----
        #pragma unroll
        for (int ks = 0; ks < 4; ks++) {
            uint4 a = Pr[ks];
            #pragma unroll
            for (int nt = 0; nt < 16; nt++) {
                uint2 b = *(const uint2*)(VB + ks * 1024 + nt * 64 + lane * 2);
                mma_f16(O[nt], a, b);
            }
        }
        __syncthreads();   // VB + KB[kt&1] reads done -> safe to refill

        // ---- issue next loads: V(kt+1) -> VB, K(kt+2) -> KB[kt&1] ----
        if (kt + 1 < NKT) {
            const uint32_t* vfp = vbase + (size_t)(kt + 1) * 4096;
            #pragma unroll
            for (int it = 0; it < 8; it++) {
                int idx = (tid + it * 128) * 4;
                cpa16(VB + idx, vfp + idx);
            }
        }
        asm volatile("cp.async.commit_group;");
        if (kt + 2 < NKT) {
            const uint32_t* kfp = kbase + (size_t)(kt + 2) * 4096;
            uint32_t* KBn = sm + KB_OFF + (kt & 1) * 4096;
            #pragma unroll
            for (int it = 0; it < 8; it++) {
                int idx = (tid + it * 128) * 4;
                cpa16(KBn + idx, kfp + idx);
            }
        }
        asm volatile("cp.async.commit_group;");
    }

    // ---- finalize ----
    float inv0 = 1.f / l0, inv1 = 1.f / l1;
    int gr0 = q0 + 16 * mt + g;
    int gr1 = gr0 + 8;
    #pragma unroll
    for (int nt = 0; nt < 16; nt++) {
        int c = nt * 8 + 2 * t4;
        if (gr0 < S_LEN) {
            float2 o0 = make_float2(O[nt][0] * inv0, O[nt][1] * inv0);
            *(float2*)(Oo + (size_t)gr0 * DIM + head * HDIM + c) = o0;
        }
        if (gr1 < S_LEN) {
            float2 o1 = make_float2(O[nt][2] * inv1, O[nt][3] * inv1);
            *(float2*)(Oo + (size_t)gr1 * DIM + head * HDIM + c) = o1;
        }
    }
}

// ---------------- launch -----------------------------------------------------
extern "C" void kernel_launch(void* const* d_in, const int* in_sizes, int n_in,
                              void* d_out, int out_size)
{
    const float* x  = (const float*)d_in[0];
    const float* Wq = (const float*)d_in[1];
    const float* bq = (const float*)d_in[2];
    const float* Wk = (const float*)d_in[3];
    const float* bk = (const float*)d_in[4];
    const float* Wv = (const float*)d_in[5];
    const float* bv = (const float*)d_in[6];
    const float* Wo = (const float*)d_in[7];
    const float* bo = (const float*)d_in[8];
    const float* gq = (const float*)d_in[9];
    const float* gk = (const float*)d_in[10];
    const float* ck = (const float*)d_in[11];
    const float* cv = (const float*)d_in[12];
    const float* fc = (const float*)d_in[13];
    const float* fs = (const float*)d_in[14];
    float* out = (float*)d_out;

    float *qb, *kb, *vb, *ob;
    uint32_t *kf, *vf;
    cudaGetSymbolAddress((void**)&qb, d_qbuf);
    cudaGetSymbolAddress((void**)&kb, d_kbuf);
    cudaGetSymbolAddress((void**)&vb, d_vbuf);
    cudaGetSymbolAddress((void**)&kf, d_kfrag);
    cudaGetSymbolAddress((void**)&vf, d_vfrag);
    cudaGetSymbolAddress((void**)&ob, d_obuf);

    int gemm_smem = G_SMEM_U32 * (int)sizeof(uint32_t);
    cudaFuncSetAttribute(gemm3_f16, cudaFuncAttributeMaxDynamicSharedMemorySize, gemm_smem);

    gemm3_f16<<<dim3(36, 13), 256, gemm_smem>>>(
        x, Wq, Wk, Wv, bq, bk, bv, qb, kb, vb, S_LEN);

    rmsnorm_rope_q<<<S_LEN, 256>>>(qb, gq, fc, fs);
    rmsnorm_plain<<<S_LEN, 256>>>(kb, gk);

    build_kv_frag<<<dim3(NKT, NHEADS, 2), 256>>>(ck, cv, kb, vb, kf, vf, fc, fs);

    int attn_smem = ATTN_SMEM_U32 * (int)sizeof(uint32_t);
    cudaFuncSetAttribute(attn_tc, cudaFuncAttributeMaxDynamicSharedMemorySize, attn_smem);
    attn_tc<<<dim3((S_LEN + 63) / 64, NHEADS), 128, attn_smem>>>(qb, kf, vf, ob);

    gemm3_f16<<<dim3(12, 13), 256, gemm_smem>>>(
        ob, Wo, Wo, Wo, bo, bo, bo, out, out, out, S_LEN);
}